// round 1
// baseline (speedup 1.0000x reference)
#include <cuda_runtime.h>

#define L   128
#define BZ  32
#define TT  512
#define DD  4096
#define MT  (TT*BZ)   // 16384 rows into the decoder

// ---------------- scratch (device globals; no allocation) ----------------
__device__ float g_h1[BZ * L];
__device__ float g_h2[BZ * L];
__device__ float g_z0[BZ * L];
__device__ float g_Kpow[9 * L * L];   // K^2, K^4, ..., K^512
__device__ float g_Z [MT * L];
__device__ float g_T1[MT * L];
__device__ float g_T2[MT * L];

// ---------------- encoder layer 0: [32,4096] @ [4096,128] + b, relu ----------------
__global__ void enc0_kernel(const float* __restrict__ x0,
                            const float* __restrict__ W,
                            const float* __restrict__ b) {
    __shared__ float xs[DD];
    int row = blockIdx.x;
    const float4* x4 = (const float4*)(x0 + (size_t)row * DD);
    for (int i = threadIdx.x; i < DD / 4; i += 128)
        ((float4*)xs)[i] = x4[i];
    __syncthreads();
    int n = threadIdx.x;
    float acc = 0.f;
#pragma unroll 8
    for (int k = 0; k < DD; k++)
        acc += xs[k] * W[(size_t)k * L + n];
    acc += b[n];
    g_h1[row * L + n] = fmaxf(acc, 0.f);
}

// ---------------- generic [M,128] @ [128,128] + b (opt relu); 32 rows/block ----------------
__global__ void dense128_kernel(const float* __restrict__ X,
                                const float* __restrict__ W,
                                const float* __restrict__ bias,
                                float* __restrict__ out,
                                int relu) {
    extern __shared__ float sm[];
    float* Ws = sm;            // 128*128
    float* Xs = sm + L * L;    // 32*128
    int tid = threadIdx.x;

    const float4* W4 = (const float4*)W;
    float4* Ws4 = (float4*)Ws;
#pragma unroll
    for (int i = tid; i < L * L / 4; i += 256) Ws4[i] = W4[i];

    const float4* X4 = (const float4*)(X + (size_t)blockIdx.x * 32 * L);
    float4* Xs4 = (float4*)Xs;
#pragma unroll
    for (int i = tid; i < 32 * L / 4; i += 256) Xs4[i] = X4[i];
    __syncthreads();

    int n    = tid & 127;
    int half = tid >> 7;           // 0/1 -> rows [0,16) or [16,32)
    float bn = bias[n];

#pragma unroll
    for (int rc = 0; rc < 4; rc++) {
        int r0 = half * 16 + rc * 4;
        float a0 = 0.f, a1 = 0.f, a2 = 0.f, a3 = 0.f;
#pragma unroll 8
        for (int k = 0; k < L; k++) {
            float w = Ws[k * L + n];
            a0 += Xs[(r0 + 0) * L + k] * w;
            a1 += Xs[(r0 + 1) * L + k] * w;
            a2 += Xs[(r0 + 2) * L + k] * w;
            a3 += Xs[(r0 + 3) * L + k] * w;
        }
        a0 += bn; a1 += bn; a2 += bn; a3 += bn;
        if (relu) {
            a0 = fmaxf(a0, 0.f); a1 = fmaxf(a1, 0.f);
            a2 = fmaxf(a2, 0.f); a3 = fmaxf(a3, 0.f);
        }
        size_t ob = ((size_t)blockIdx.x * 32 + r0) * L + n;
        out[ob + 0 * L] = a0;
        out[ob + 1 * L] = a1;
        out[ob + 2 * L] = a2;
        out[ob + 3 * L] = a3;
    }
}

// ---------------- K squaring: C = A @ A, 128x128 ----------------
__global__ void kpow_kernel(const float* __restrict__ A, float* __restrict__ C) {
    __shared__ float rowA[L];
    int i = blockIdx.x;
    rowA[threadIdx.x] = A[i * L + threadIdx.x];
    __syncthreads();
    int n = threadIdx.x;
    float acc = 0.f;
#pragma unroll 8
    for (int k = 0; k < L; k++)
        acc += rowA[k] * A[k * L + n];
    C[i * L + n] = acc;
}

// ---------------- per-t: Z_t = K^exps[t] @ z0^T  (binary powers) ----------------
__global__ void zprop_kernel(const float* __restrict__ K1,
                             const int* __restrict__ idxw) {
    extern __shared__ float sm[];
    float* Ks    = sm;                // 128*128
    float* Zbuf0 = sm + L * L;        // 128*32
    float* Zbuf1 = Zbuf0 + L * BZ;    // 128*32
    int t   = blockIdx.x;
    int tid = threadIdx.x;

    // Detect int64-layout idx buffer (values < 2^31 -> odd words zero).
    bool is64 = ((idxw[1] | idxw[3] | idxw[5] | idxw[7] | idxw[9] | idxw[11]) == 0);
    int e = is64 ? (idxw[2 * t] - idxw[0]) : (idxw[t] - idxw[0]);

    // state[l][b] = z0[b][l]
    for (int i = tid; i < L * BZ; i += 256) {
        int l = i >> 5, b = i & 31;
        Zbuf0[i] = g_z0[b * L + l];
    }
    __syncthreads();

    float* Zin  = Zbuf0;
    float* Zout = Zbuf1;
    int b  = tid & 31;
    int ig = tid >> 5;   // 0..7, rows ig*16 .. ig*16+15

    for (int bit = 0; bit < 10; bit++) {
        if ((e >> bit) & 1) {
            const float* Kp = (bit == 0) ? K1 : (g_Kpow + (size_t)(bit - 1) * L * L);
#pragma unroll
            for (int i = tid; i < L * L / 4; i += 256)
                ((float4*)Ks)[i] = ((const float4*)Kp)[i];
            __syncthreads();

            float acc[16];
#pragma unroll
            for (int i = 0; i < 16; i++) acc[i] = 0.f;

            for (int k4 = 0; k4 < 32; k4++) {
                float z0v = Zin[(4 * k4 + 0) * 32 + b];
                float z1v = Zin[(4 * k4 + 1) * 32 + b];
                float z2v = Zin[(4 * k4 + 2) * 32 + b];
                float z3v = Zin[(4 * k4 + 3) * 32 + b];
#pragma unroll
                for (int i = 0; i < 16; i++) {
                    float4 kr = ((const float4*)Ks)[(ig * 16 + i) * 32 + k4];
                    acc[i] += kr.x * z0v + kr.y * z1v + kr.z * z2v + kr.w * z3v;
                }
            }
#pragma unroll
            for (int i = 0; i < 16; i++)
                Zout[(ig * 16 + i) * 32 + b] = acc[i];
            __syncthreads();
            float* tp = Zin; Zin = Zout; Zout = tp;
        }
    }

    // g_Z[(t*32+b)][l] = state[l][b]   (coalesced global write)
    for (int i = tid; i < L * BZ; i += 256) {
        int bb = i >> 7, l = i & 127;
        g_Z[((size_t)t * BZ + bb) * L + l] = Zin[l * 32 + bb];
    }
}

// ---------------- final: [16384,128] @ [128,4096] + b  (BM=128, BN=64, full K) ----------------
#define BM 128
#define BN 64
__global__ void final_gemm_kernel(const float* __restrict__ A,
                                  const float* __restrict__ W,
                                  const float* __restrict__ bias,
                                  float* __restrict__ out) {
    extern __shared__ float sm[];
    float* As = sm;             // 128*128 floats, layout [m][k]
    float* Bs = sm + BM * L;    // 128*64  floats, layout [k][n]
    int tid = threadIdx.x;
    int bm0 = blockIdx.y * BM;
    int bn0 = blockIdx.x * BN;

    const float4* A4  = (const float4*)(A + (size_t)bm0 * L);
    float4* As4 = (float4*)As;
#pragma unroll
    for (int i = tid; i < BM * L / 4; i += 256) As4[i] = A4[i];

    float4* Bs4 = (float4*)Bs;
#pragma unroll
    for (int i = tid; i < L * BN / 4; i += 256) {
        int k  = i >> 4;    // BN/4 = 16 float4 per k-row
        int nq = i & 15;
        Bs4[i] = ((const float4*)(W + (size_t)k * DD + bn0))[nq];
    }
    __syncthreads();

    int tx = tid & 15;      // 4 output cols
    int ty = tid >> 4;      // 8 output rows
    int m0 = ty * 8;
    int n0 = tx * 4;

    float acc[8][4];
#pragma unroll
    for (int i = 0; i < 8; i++)
#pragma unroll
        for (int j = 0; j < 4; j++) acc[i][j] = 0.f;

#pragma unroll 4
    for (int k4 = 0; k4 < 32; k4++) {
        float4 b0 = Bs4[(4 * k4 + 0) * 16 + tx];
        float4 b1 = Bs4[(4 * k4 + 1) * 16 + tx];
        float4 b2 = Bs4[(4 * k4 + 2) * 16 + tx];
        float4 b3 = Bs4[(4 * k4 + 3) * 16 + tx];
#pragma unroll
        for (int i = 0; i < 8; i++) {
            float4 a = As4[(m0 + i) * 32 + k4];
            acc[i][0] += a.x * b0.x + a.y * b1.x + a.z * b2.x + a.w * b3.x;
            acc[i][1] += a.x * b0.y + a.y * b1.y + a.z * b2.y + a.w * b3.y;
            acc[i][2] += a.x * b0.z + a.y * b1.z + a.z * b2.z + a.w * b3.z;
            acc[i][3] += a.x * b0.w + a.y * b1.w + a.z * b2.w + a.w * b3.w;
        }
    }

    float4 bb = *(const float4*)(bias + bn0 + n0);
#pragma unroll
    for (int i = 0; i < 8; i++) {
        float4 v;
        v.x = acc[i][0] + bb.x;
        v.y = acc[i][1] + bb.y;
        v.z = acc[i][2] + bb.z;
        v.w = acc[i][3] + bb.w;
        *(float4*)(out + ((size_t)(bm0 + m0 + i)) * DD + bn0 + n0) = v;
    }
}

// ---------------- launch ----------------
extern "C" void kernel_launch(void* const* d_in, const int* in_sizes, int n_in,
                              void* d_out, int out_size) {
    const float* x0  = (const float*)d_in[0];
    const int*   idx = (const int*)  d_in[1];
    const float* K   = (const float*)d_in[2];
    const float* We0 = (const float*)d_in[3];
    const float* be0 = (const float*)d_in[4];
    const float* We1 = (const float*)d_in[5];
    const float* be1 = (const float*)d_in[6];
    const float* We2 = (const float*)d_in[7];
    const float* be2 = (const float*)d_in[8];
    const float* We3 = (const float*)d_in[9];
    const float* be3 = (const float*)d_in[10];
    const float* Wd0 = (const float*)d_in[11];
    const float* bd0 = (const float*)d_in[12];
    const float* Wd1 = (const float*)d_in[13];
    const float* bd1 = (const float*)d_in[14];
    const float* Wd2 = (const float*)d_in[15];
    const float* bd2 = (const float*)d_in[16];
    const float* Wd3 = (const float*)d_in[17];
    const float* bd3 = (const float*)d_in[18];
    float* out = (float*)d_out;

    // smem opt-ins (host-side attribute sets; capture-safe, idempotent)
    const int smem_dense = (L * L + 32 * L) * 4;          // 80 KB
    const int smem_zprop = (L * L + 2 * L * BZ) * 4;      // 96 KB
    const int smem_final = (BM * L + L * BN) * 4;         // 96 KB
    cudaFuncSetAttribute(dense128_kernel,  cudaFuncAttributeMaxDynamicSharedMemorySize, smem_dense);
    cudaFuncSetAttribute(zprop_kernel,     cudaFuncAttributeMaxDynamicSharedMemorySize, smem_zprop);
    cudaFuncSetAttribute(final_gemm_kernel, cudaFuncAttributeMaxDynamicSharedMemorySize, smem_final);

    float *pH1, *pH2, *pZ0, *pKp, *pZ, *pT1, *pT2;
    cudaGetSymbolAddress((void**)&pH1, g_h1);
    cudaGetSymbolAddress((void**)&pH2, g_h2);
    cudaGetSymbolAddress((void**)&pZ0, g_z0);
    cudaGetSymbolAddress((void**)&pKp, g_Kpow);
    cudaGetSymbolAddress((void**)&pZ,  g_Z);
    cudaGetSymbolAddress((void**)&pT1, g_T1);
    cudaGetSymbolAddress((void**)&pT2, g_T2);

    // Encoder
    enc0_kernel<<<BZ, 128>>>(x0, We0, be0);                                    // -> g_h1
    dense128_kernel<<<1, 256, smem_dense>>>(pH1, We1, be1, pH2, 1);
    dense128_kernel<<<1, 256, smem_dense>>>(pH2, We2, be2, pH1, 1);
    dense128_kernel<<<1, 256, smem_dense>>>(pH1, We3, be3, pZ0, 0);            // z0

    // Binary powers of K: g_Kpow[p] = K^(2^(p+1)), p = 0..8
    kpow_kernel<<<L, L>>>(K, pKp);
    for (int p = 1; p < 9; p++)
        kpow_kernel<<<L, L>>>(pKp + (size_t)(p - 1) * L * L, pKp + (size_t)p * L * L);

    // Z[t] = K^exps[t] @ z0^T
    zprop_kernel<<<TT, 256, smem_zprop>>>(K, idx);

    // Decoder hidden layers
    dense128_kernel<<<MT / 32, 256, smem_dense>>>(pZ,  Wd0, bd0, pT1, 1);
    dense128_kernel<<<MT / 32, 256, smem_dense>>>(pT1, Wd1, bd1, pT2, 1);
    dense128_kernel<<<MT / 32, 256, smem_dense>>>(pT2, Wd2, bd2, pT1, 1);

    // Final projection to D=4096
    dim3 fgrid(DD / BN, MT / BM);   // (64, 128)
    final_gemm_kernel<<<fgrid, 256, smem_final>>>(pT1, Wd3, bd3, out);
}

// round 3
// speedup vs baseline: 1.2803x; 1.2803x over previous
#include <cuda_runtime.h>
#include <cuda_bf16.h>
#include <stdint.h>

#define L   128
#define BZ  32
#define TT  512
#define DD  4096
#define MT  (TT*BZ)   // 16384 decoder rows

// ---------------- scratch (device globals; no allocation) ----------------
__device__ float g_h1[BZ * L];
__device__ float g_z0[BZ * L];
__device__ float g_Kpow[9 * L * L];          // K^2 .. K^512
__device__ float g_Z [MT * L];
__device__ float g_T1[MT * L];
__device__ float g_T2[MT * L];
__device__ __nv_bfloat16 g_Ahi[MT * L];      // last hidden activations, bf16 hi
__device__ __nv_bfloat16 g_Alo[MT * L];      // residual lo
__device__ __nv_bfloat16 g_Whi[DD * L];      // Wd3 transposed [n][k], hi
__device__ __nv_bfloat16 g_Wlo[DD * L];      // residual lo

// ---------------- encoder layer 0: [32,4096] @ [4096,128] + b, relu ----------------
__global__ void enc0_kernel(const float* __restrict__ x0,
                            const float* __restrict__ W,
                            const float* __restrict__ b) {
    __shared__ float xs[DD];
    int row = blockIdx.x;
    const float4* x4 = (const float4*)(x0 + (size_t)row * DD);
    for (int i = threadIdx.x; i < DD / 4; i += 128)
        ((float4*)xs)[i] = x4[i];
    __syncthreads();
    int n = threadIdx.x;
    float acc = 0.f;
#pragma unroll 8
    for (int k = 0; k < DD; k++)
        acc += xs[k] * W[(size_t)k * L + n];
    acc += b[n];
    g_h1[row * L + n] = fmaxf(acc, 0.f);
}

// ---------------- fused encoder tail: 3x (32x128 @ 128x128) ----------------
__device__ __forceinline__ void enc_layer(const float* Xin, const float* __restrict__ W,
                                          const float* __restrict__ b,
                                          float* Xout, float* gout, int relu, int tid) {
    int n = tid & 127;
    int r0 = (tid >> 7) * 16;
    float acc[16];
#pragma unroll
    for (int i = 0; i < 16; i++) acc[i] = 0.f;
#pragma unroll 4
    for (int k = 0; k < L; k++) {
        float w = W[k * L + n];
#pragma unroll
        for (int i = 0; i < 16; i++) acc[i] += Xin[(r0 + i) * L + k] * w;
    }
    float bn = b[n];
#pragma unroll
    for (int i = 0; i < 16; i++) {
        float v = acc[i] + bn;
        if (relu) v = fmaxf(v, 0.f);
        if (Xout) Xout[(r0 + i) * L + n] = v;
        else      gout[(r0 + i) * L + n] = v;
    }
}

__global__ void enc_tail_kernel(const float* W1, const float* b1,
                                const float* W2, const float* b2,
                                const float* W3, const float* b3) {
    __shared__ float Xa[BZ * L];
    __shared__ float Xb[BZ * L];
    int tid = threadIdx.x;
    for (int i = tid; i < BZ * L; i += 256) Xa[i] = g_h1[i];
    __syncthreads();
    enc_layer(Xa, W1, b1, Xb, nullptr, 1, tid); __syncthreads();
    enc_layer(Xb, W2, b2, Xa, nullptr, 1, tid); __syncthreads();
    enc_layer(Xa, W3, b3, nullptr, g_z0, 0, tid);
}

// ---------------- K squaring: C = A @ A, 128x128 ----------------
__global__ void kpow_kernel(const float* __restrict__ A, float* __restrict__ C) {
    __shared__ float rowA[L];
    int i = blockIdx.x;
    rowA[threadIdx.x] = A[i * L + threadIdx.x];
    __syncthreads();
    int n = threadIdx.x;
    float acc = 0.f;
#pragma unroll 8
    for (int k = 0; k < L; k++)
        acc += rowA[k] * A[k * L + n];
    C[i * L + n] = acc;
}

// ---------------- per-t: Z_t = K^exps[t] @ z0^T  (binary powers) ----------------
__global__ void zprop_kernel(const float* __restrict__ K1,
                             const int* __restrict__ idxw) {
    extern __shared__ float sm[];
    float* Ks    = sm;
    float* Zbuf0 = sm + L * L;
    float* Zbuf1 = Zbuf0 + L * BZ;
    int t   = blockIdx.x;
    int tid = threadIdx.x;

    bool is64 = ((idxw[1] | idxw[3] | idxw[5] | idxw[7] | idxw[9] | idxw[11]) == 0);
    int e = is64 ? (idxw[2 * t] - idxw[0]) : (idxw[t] - idxw[0]);

    for (int i = tid; i < L * BZ; i += 256) {
        int l = i >> 5, b = i & 31;
        Zbuf0[i] = g_z0[b * L + l];
    }
    __syncthreads();

    float* Zin  = Zbuf0;
    float* Zout = Zbuf1;
    int b  = tid & 31;
    int ig = tid >> 5;

    for (int bit = 0; bit < 10; bit++) {
        if ((e >> bit) & 1) {
            const float* Kp = (bit == 0) ? K1 : (g_Kpow + (size_t)(bit - 1) * L * L);
#pragma unroll
            for (int i = tid; i < L * L / 4; i += 256)
                ((float4*)Ks)[i] = ((const float4*)Kp)[i];
            __syncthreads();

            float acc[16];
#pragma unroll
            for (int i = 0; i < 16; i++) acc[i] = 0.f;

            for (int k4 = 0; k4 < 32; k4++) {
                float z0v = Zin[(4 * k4 + 0) * 32 + b];
                float z1v = Zin[(4 * k4 + 1) * 32 + b];
                float z2v = Zin[(4 * k4 + 2) * 32 + b];
                float z3v = Zin[(4 * k4 + 3) * 32 + b];
#pragma unroll
                for (int i = 0; i < 16; i++) {
                    float4 kr = ((const float4*)Ks)[(ig * 16 + i) * 32 + k4];
                    acc[i] += kr.x * z0v + kr.y * z1v + kr.z * z2v + kr.w * z3v;
                }
            }
#pragma unroll
            for (int i = 0; i < 16; i++)
                Zout[(ig * 16 + i) * 32 + b] = acc[i];
            __syncthreads();
            float* tp = Zin; Zin = Zout; Zout = tp;
        }
    }

    for (int i = tid; i < L * BZ; i += 256) {
        int bb = i >> 7, l = i & 127;
        g_Z[((size_t)t * BZ + bb) * L + l] = Zin[l * 32 + bb];
    }
}

// ---------------- W split/transpose: Wd3 [128,4096] f32 -> g_Whi/g_Wlo [4096,128] bf16 ----------------
__global__ void splitW_kernel(const float* __restrict__ W) {
    int n = blockIdx.x;     // 0..4095
    int k = threadIdx.x;    // 0..127
    float w = W[(size_t)k * DD + n];
    __nv_bfloat16 hi = __float2bfloat16(w);
    float rem = w - __bfloat162float(hi);
    g_Whi[n * L + k] = hi;
    g_Wlo[n * L + k] = __float2bfloat16(rem);
}

// ---------------- hidden dense: [16384,128] @ [128,128] + b ----------------
__global__ __launch_bounds__(256, 1)
void dense_wide_kernel(const float* __restrict__ X, const float* __restrict__ W,
                       const float* __restrict__ bias, float* __restrict__ outf,
                       int mode) {
    extern __shared__ float sm[];
    float* Xs = sm;            // 128*128
    float* Ws = sm + L * L;    // 128*128
    int tid = threadIdx.x;
    int bm0 = blockIdx.x * 128;

    const float4* X4 = (const float4*)X + (size_t)bm0 * 32;
    float4* Xs4 = (float4*)Xs;
    float4* Ws4 = (float4*)Ws;
    const float4* W4 = (const float4*)W;
#pragma unroll
    for (int i = tid; i < L * L / 4; i += 256) { Xs4[i] = X4[i]; Ws4[i] = W4[i]; }
    __syncthreads();

    int tx = tid & 31;    // float4 n-col
    int ty = tid >> 5;    // row group (warp-uniform)
    int r0 = ty * 16;

    float acc[16][4];
#pragma unroll
    for (int i = 0; i < 16; i++)
#pragma unroll
        for (int j = 0; j < 4; j++) acc[i][j] = 0.f;

    for (int k4 = 0; k4 < 32; k4++) {
        float4 b0 = Ws4[(4 * k4 + 0) * 32 + tx];
        float4 b1 = Ws4[(4 * k4 + 1) * 32 + tx];
        float4 b2 = Ws4[(4 * k4 + 2) * 32 + tx];
        float4 b3 = Ws4[(4 * k4 + 3) * 32 + tx];
#pragma unroll
        for (int i = 0; i < 16; i++) {
            float4 a = Xs4[(r0 + i) * 32 + k4];   // warp-uniform broadcast
            acc[i][0] += a.x * b0.x + a.y * b1.x + a.z * b2.x + a.w * b3.x;
            acc[i][1] += a.x * b0.y + a.y * b1.y + a.z * b2.y + a.w * b3.y;
            acc[i][2] += a.x * b0.z + a.y * b1.z + a.z * b2.z + a.w * b3.z;
            acc[i][3] += a.x * b0.w + a.y * b1.w + a.z * b2.w + a.w * b3.w;
        }
    }

    float4 bb = ((const float4*)bias)[tx];
#pragma unroll
    for (int i = 0; i < 16; i++) {
        float4 v;
        v.x = fmaxf(acc[i][0] + bb.x, 0.f);
        v.y = fmaxf(acc[i][1] + bb.y, 0.f);
        v.z = fmaxf(acc[i][2] + bb.z, 0.f);
        v.w = fmaxf(acc[i][3] + bb.w, 0.f);
        size_t row = (size_t)(bm0 + r0 + i);
        if (mode == 0) {
            ((float4*)outf)[row * 32 + tx] = v;
        } else {
            __nv_bfloat16 h0 = __float2bfloat16(v.x), h1 = __float2bfloat16(v.y);
            __nv_bfloat16 h2 = __float2bfloat16(v.z), h3 = __float2bfloat16(v.w);
            __nv_bfloat16 l0 = __float2bfloat16(v.x - __bfloat162float(h0));
            __nv_bfloat16 l1 = __float2bfloat16(v.y - __bfloat162float(h1));
            __nv_bfloat16 l2 = __float2bfloat16(v.z - __bfloat162float(h2));
            __nv_bfloat16 l3 = __float2bfloat16(v.w - __bfloat162float(h3));
            __nv_bfloat162* dh = (__nv_bfloat162*)(g_Ahi + row * L + tx * 4);
            __nv_bfloat162* dl = (__nv_bfloat162*)(g_Alo + row * L + tx * 4);
            dh[0] = __halves2bfloat162(h0, h1);
            dh[1] = __halves2bfloat162(h2, h3);
            dl[0] = __halves2bfloat162(l0, l1);
            dl[1] = __halves2bfloat162(l2, l3);
        }
    }
}

// ================= final GEMM: mma.sync bf16 hi/lo (baseline-PTX tensor path) =================
// [16384,128] @ [128,4096] + b. Tile BM=128 x BN=128, full K=128 in smem.
// Rows padded to 272B so ldmatrix 8-row reads rotate across 16B bank groups.

#define SPE 136          // padded row stride, bf16 elems (272 B)
#define FSM_BYTES (4 * 128 * SPE * 2)   // 4 tiles -> 139264 B

__device__ __forceinline__ uint32_t smem_u32(const void* p) {
    uint32_t a;
    asm("{ .reg .u64 t; cvta.to.shared.u64 t, %1; cvt.u32.u64 %0, t; }" : "=r"(a) : "l"(p));
    return a;
}

__device__ __forceinline__ void ldmx4(uint32_t* r, uint32_t addr) {
    asm volatile("ldmatrix.sync.aligned.m8n8.x4.shared.b16 {%0,%1,%2,%3}, [%4];"
                 : "=r"(r[0]), "=r"(r[1]), "=r"(r[2]), "=r"(r[3]) : "r"(addr));
}
__device__ __forceinline__ void ldmx2(uint32_t* r, uint32_t addr) {
    asm volatile("ldmatrix.sync.aligned.m8n8.x2.shared.b16 {%0,%1}, [%2];"
                 : "=r"(r[0]), "=r"(r[1]) : "r"(addr));
}
__device__ __forceinline__ void mma16816(float* c, const uint32_t* a, const uint32_t* b) {
    asm volatile(
        "mma.sync.aligned.m16n8k16.row.col.f32.bf16.bf16.f32 "
        "{%0,%1,%2,%3}, {%4,%5,%6,%7}, {%8,%9}, {%0,%1,%2,%3};"
        : "+f"(c[0]), "+f"(c[1]), "+f"(c[2]), "+f"(c[3])
        : "r"(a[0]), "r"(a[1]), "r"(a[2]), "r"(a[3]), "r"(b[0]), "r"(b[1]));
}

__global__ __launch_bounds__(256, 1)
void final_mma_kernel(const float* __restrict__ bias, float* __restrict__ out) {
    extern __shared__ __align__(16) __nv_bfloat16 smb[];
    __nv_bfloat16* Ahi = smb;
    __nv_bfloat16* Alo = smb + 128 * SPE;
    __nv_bfloat16* Bhi = smb + 2 * 128 * SPE;
    __nv_bfloat16* Blo = smb + 3 * 128 * SPE;

    int tid  = threadIdx.x;
    int wid  = tid >> 5, lane = tid & 31;
    int bn0  = blockIdx.x * 128;
    int bm0  = blockIdx.y * 128;

    // ---- load tiles: 2048 uint4 per tile (128 rows x 16 chunks of 8 bf16) ----
    const uint4* GAh = (const uint4*)g_Ahi;
    const uint4* GAl = (const uint4*)g_Alo;
    const uint4* GBh = (const uint4*)g_Whi;
    const uint4* GBl = (const uint4*)g_Wlo;
#pragma unroll
    for (int i = tid; i < 2048; i += 256) {
        int r = i >> 4, q = i & 15;
        int so = r * SPE + q * 8;                       // bf16 elems
        *(uint4*)(Ahi + so) = GAh[(size_t)(bm0 + r) * 16 + q];
        *(uint4*)(Alo + so) = GAl[(size_t)(bm0 + r) * 16 + q];
        *(uint4*)(Bhi + so) = GBh[(size_t)(bn0 + r) * 16 + q];
        *(uint4*)(Blo + so) = GBl[(size_t)(bn0 + r) * 16 + q];
    }
    __syncthreads();

    // warp tile: 64 rows x 32 cols; wm in {0,1}, wn in {0..3}
    int wm = wid >> 2, wn = wid & 3;

    float c[4][4][4];
#pragma unroll
    for (int mi = 0; mi < 4; mi++)
#pragma unroll
        for (int ni = 0; ni < 4; ni++)
#pragma unroll
            for (int j = 0; j < 4; j++) c[mi][ni][j] = 0.f;

    // precompute smem byte offsets (within a tile) for ldmatrix
    uint32_t a_off[4], b_off[4];
#pragma unroll
    for (int mi = 0; mi < 4; mi++) {
        int row = wm * 64 + mi * 16 + (lane & 15);
        a_off[mi] = (uint32_t)(row * SPE * 2) + ((lane >> 4) << 4);
    }
#pragma unroll
    for (int ni = 0; ni < 4; ni++) {
        int row = wn * 32 + ni * 8 + (lane & 7);
        b_off[ni] = (uint32_t)(row * SPE * 2) + (((lane >> 3) & 1) << 4);
    }

    uint32_t sAhi = smem_u32(Ahi), sAlo = smem_u32(Alo);
    uint32_t sBhi = smem_u32(Bhi), sBlo = smem_u32(Blo);

#pragma unroll 1
    for (int pass = 0; pass < 3; pass++) {
        uint32_t sA = (pass == 2) ? sAlo : sAhi;
        uint32_t sB = (pass == 1) ? sBlo : sBhi;
#pragma unroll
        for (int k0 = 0; k0 < 8; k0++) {               // K step 16
            uint32_t koff = (uint32_t)(k0 * 32);       // 16 bf16 = 32 B
            uint32_t a[4][4], b[4][2];
#pragma unroll
            for (int mi = 0; mi < 4; mi++) ldmx4(a[mi], sA + a_off[mi] + koff);
#pragma unroll
            for (int ni = 0; ni < 4; ni++) ldmx2(b[ni], sB + b_off[ni] + koff);
#pragma unroll
            for (int mi = 0; mi < 4; mi++)
#pragma unroll
                for (int ni = 0; ni < 4; ni++)
                    mma16816(c[mi][ni], a[mi], b[ni]);
        }
    }

    // ---- epilogue: c layout g=lane>>2, col pair (lane&3)*2, rows +8 for c[2],c[3] ----
    int g  = lane >> 2;
    int cc = (lane & 3) * 2;
#pragma unroll
    for (int ni = 0; ni < 4; ni++) {
        int col = bn0 + wn * 32 + ni * 8 + cc;
        float bx = bias[col], by = bias[col + 1];
#pragma unroll
        for (int mi = 0; mi < 4; mi++) {
            size_t row = (size_t)(bm0 + wm * 64 + mi * 16 + g);
            float2 v0 = make_float2(c[mi][ni][0] + bx, c[mi][ni][1] + by);
            float2 v1 = make_float2(c[mi][ni][2] + bx, c[mi][ni][3] + by);
            *(float2*)(out + row * DD + col)       = v0;
            *(float2*)(out + (row + 8) * DD + col) = v1;
        }
    }
}

// ---------------- launch ----------------
extern "C" void kernel_launch(void* const* d_in, const int* in_sizes, int n_in,
                              void* d_out, int out_size) {
    const float* x0  = (const float*)d_in[0];
    const int*   idx = (const int*)  d_in[1];
    const float* K   = (const float*)d_in[2];
    const float* We0 = (const float*)d_in[3];
    const float* be0 = (const float*)d_in[4];
    const float* We1 = (const float*)d_in[5];
    const float* be1 = (const float*)d_in[6];
    const float* We2 = (const float*)d_in[7];
    const float* be2 = (const float*)d_in[8];
    const float* We3 = (const float*)d_in[9];
    const float* be3 = (const float*)d_in[10];
    const float* Wd0 = (const float*)d_in[11];
    const float* bd0 = (const float*)d_in[12];
    const float* Wd1 = (const float*)d_in[13];
    const float* bd1 = (const float*)d_in[14];
    const float* Wd2 = (const float*)d_in[15];
    const float* bd2 = (const float*)d_in[16];
    const float* Wd3 = (const float*)d_in[17];
    const float* bd3 = (const float*)d_in[18];
    float* out = (float*)d_out;

    const int smem_zprop = (L * L + 2 * L * BZ) * 4;   // 96 KB
    const int smem_dense = 2 * L * L * 4;              // 128 KB
    const int smem_final = FSM_BYTES;                  // ~136 KB
    cudaFuncSetAttribute(zprop_kernel,      cudaFuncAttributeMaxDynamicSharedMemorySize, smem_zprop);
    cudaFuncSetAttribute(dense_wide_kernel, cudaFuncAttributeMaxDynamicSharedMemorySize, smem_dense);
    cudaFuncSetAttribute(final_mma_kernel,  cudaFuncAttributeMaxDynamicSharedMemorySize, smem_final);

    float *pKp, *pZ, *pT1, *pT2;
    cudaGetSymbolAddress((void**)&pKp, g_Kpow);
    cudaGetSymbolAddress((void**)&pZ,  g_Z);
    cudaGetSymbolAddress((void**)&pT1, g_T1);
    cudaGetSymbolAddress((void**)&pT2, g_T2);

    // Encoder
    enc0_kernel<<<BZ, 128>>>(x0, We0, be0);                         // -> g_h1
    enc_tail_kernel<<<1, 256>>>(We1, be1, We2, be2, We3, be3);      // -> g_z0

    // Binary powers of K
    kpow_kernel<<<L, L>>>(K, pKp);
    for (int p = 1; p < 9; p++)
        kpow_kernel<<<L, L>>>(pKp + (size_t)(p - 1) * L * L, pKp + (size_t)p * L * L);

    // Z[t] = K^exps[t] @ z0^T
    zprop_kernel<<<TT, 256, smem_zprop>>>(K, idx);

    // Wd3 transpose + bf16 hi/lo split (independent of Z chain)
    splitW_kernel<<<DD, 128>>>(Wd3);

    // Decoder hidden layers (last one emits bf16 hi/lo activations)
    dense_wide_kernel<<<MT / 128, 256, smem_dense>>>(pZ,  Wd0, bd0, pT1, 0);
    dense_wide_kernel<<<MT / 128, 256, smem_dense>>>(pT1, Wd1, bd1, pT2, 0);
    dense_wide_kernel<<<MT / 128, 256, smem_dense>>>(pT2, Wd2, bd2, nullptr, 2);

    // Final projection via mma.sync tensor cores
    dim3 fgrid(DD / 128, MT / 128);   // (32, 128)
    final_mma_kernel<<<fgrid, 256, smem_final>>>(bd3, out);
}

// round 4
// speedup vs baseline: 1.3261x; 1.0357x over previous
#include <cuda_runtime.h>
#include <cuda_bf16.h>
#include <stdint.h>

#define L   128
#define BZ  32
#define TT  512
#define DD  4096
#define MT  (TT*BZ)   // 16384 decoder rows

// ---------------- scratch (device globals; no allocation) ----------------
__device__ float g_h1[BZ * L];
__device__ float g_z0[BZ * L];
__device__ float g_Kpow[9 * L * L];          // K^2 .. K^512
__device__ float g_Z [MT * L];
__device__ float g_T1[MT * L];
__device__ float g_T2[MT * L];
__device__ __nv_bfloat16 g_Ahi[MT * L];      // last hidden activations, bf16 hi
__device__ __nv_bfloat16 g_Alo[MT * L];      // residual lo
__device__ __nv_bfloat16 g_Whi[DD * L];      // Wd3 transposed [n][k], hi
__device__ __nv_bfloat16 g_Wlo[DD * L];      // residual lo
__device__ int g_bar[16];                    // kpow grid barrier (zeroed by enc_tail)

// ---------------- encoder layer 0: [32,4096] @ [4096,128] + b, relu ----------------
__global__ void enc0_kernel(const float* __restrict__ x0,
                            const float* __restrict__ W,
                            const float* __restrict__ b) {
    __shared__ float xs[DD];
    int row = blockIdx.x;
    const float4* x4 = (const float4*)(x0 + (size_t)row * DD);
    for (int i = threadIdx.x; i < DD / 4; i += 128)
        ((float4*)xs)[i] = x4[i];
    __syncthreads();
    int n = threadIdx.x;
    float a0 = 0.f, a1 = 0.f, a2 = 0.f, a3 = 0.f;
#pragma unroll 4
    for (int k = 0; k < DD; k += 4) {
        a0 += xs[k + 0] * W[(size_t)(k + 0) * L + n];
        a1 += xs[k + 1] * W[(size_t)(k + 1) * L + n];
        a2 += xs[k + 2] * W[(size_t)(k + 2) * L + n];
        a3 += xs[k + 3] * W[(size_t)(k + 3) * L + n];
    }
    float acc = (a0 + a1) + (a2 + a3) + b[n];
    g_h1[row * L + n] = fmaxf(acc, 0.f);
}

// ---------------- fused encoder tail: 3x (32x128 @ 128x128); also zeroes g_bar ----------------
__device__ __forceinline__ void enc_layer(const float* Xin, const float* __restrict__ W,
                                          const float* __restrict__ b,
                                          float* Xout, float* gout, int relu, int tid) {
    int n = tid & 127;
    int r0 = (tid >> 7) * 16;
    float acc[16];
#pragma unroll
    for (int i = 0; i < 16; i++) acc[i] = 0.f;
#pragma unroll 4
    for (int k = 0; k < L; k++) {
        float w = W[k * L + n];
#pragma unroll
        for (int i = 0; i < 16; i++) acc[i] += Xin[(r0 + i) * L + k] * w;
    }
    float bn = b[n];
#pragma unroll
    for (int i = 0; i < 16; i++) {
        float v = acc[i] + bn;
        if (relu) v = fmaxf(v, 0.f);
        if (Xout) Xout[(r0 + i) * L + n] = v;
        else      gout[(r0 + i) * L + n] = v;
    }
}

__global__ void enc_tail_kernel(const float* W1, const float* b1,
                                const float* W2, const float* b2,
                                const float* W3, const float* b3) {
    __shared__ float Xa[BZ * L];
    __shared__ float Xb[BZ * L];
    int tid = threadIdx.x;
    if (tid < 16) g_bar[tid] = 0;          // reset kpow barrier for this execution
    for (int i = tid; i < BZ * L; i += 256) Xa[i] = g_h1[i];
    __syncthreads();
    enc_layer(Xa, W1, b1, Xb, nullptr, 1, tid); __syncthreads();
    enc_layer(Xb, W2, b2, Xa, nullptr, 1, tid); __syncthreads();
    enc_layer(Xa, W3, b3, nullptr, g_z0, 0, tid);
    __threadfence();
}

// ---------------- all 9 K squarings in ONE kernel with a software grid barrier ----------------
// grid = 128 CTAs (1/SM guaranteed resident), block = 128.
__global__ void kpow_fused_kernel(const float* __restrict__ K1) {
    __shared__ float rowA[L];
    int i = blockIdx.x;      // output row
    int n = threadIdx.x;     // output col
    const float* A = K1;
    for (int p = 0; p < 9; p++) {
        float* C = g_Kpow + (size_t)p * L * L;
        rowA[n] = A[i * L + n];
        __syncthreads();
        float a0 = 0.f, a1 = 0.f, a2 = 0.f, a3 = 0.f;
#pragma unroll 8
        for (int k = 0; k < L; k += 4) {
            a0 += rowA[k + 0] * A[(k + 0) * L + n];
            a1 += rowA[k + 1] * A[(k + 1) * L + n];
            a2 += rowA[k + 2] * A[(k + 2) * L + n];
            a3 += rowA[k + 3] * A[(k + 3) * L + n];
        }
        C[i * L + n] = (a0 + a1) + (a2 + a3);
        __threadfence();
        __syncthreads();                 // all stores + rowA reads done
        if (threadIdx.x == 0) {
            atomicAdd(&g_bar[p], 1);
            while (atomicAdd(&g_bar[p], 0) < (int)gridDim.x) {}
            __threadfence();
        }
        __syncthreads();
        A = C;
    }
}

// ---------------- per-t: Z_t = K^exps[t] @ z0^T  (binary powers) ----------------
__global__ void zprop_kernel(const float* __restrict__ K1,
                             const int* __restrict__ idxw) {
    extern __shared__ float sm[];
    float* Ks    = sm;
    float* Zbuf0 = sm + L * L;
    float* Zbuf1 = Zbuf0 + L * BZ;
    int t   = blockIdx.x;
    int tid = threadIdx.x;

    bool is64 = ((idxw[1] | idxw[3] | idxw[5] | idxw[7] | idxw[9] | idxw[11]) == 0);
    int e = is64 ? (idxw[2 * t] - idxw[0]) : (idxw[t] - idxw[0]);

    for (int i = tid; i < L * BZ; i += 256) {
        int l = i >> 5, b = i & 31;
        Zbuf0[i] = g_z0[b * L + l];
    }
    __syncthreads();

    float* Zin  = Zbuf0;
    float* Zout = Zbuf1;
    int b  = tid & 31;
    int ig = tid >> 5;

    for (int bit = 0; bit < 10; bit++) {
        if ((e >> bit) & 1) {
            const float* Kp = (bit == 0) ? K1 : (g_Kpow + (size_t)(bit - 1) * L * L);
#pragma unroll
            for (int i = tid; i < L * L / 4; i += 256)
                ((float4*)Ks)[i] = ((const float4*)Kp)[i];
            __syncthreads();

            float acc[16];
#pragma unroll
            for (int i = 0; i < 16; i++) acc[i] = 0.f;

            for (int k4 = 0; k4 < 32; k4++) {
                float z0v = Zin[(4 * k4 + 0) * 32 + b];
                float z1v = Zin[(4 * k4 + 1) * 32 + b];
                float z2v = Zin[(4 * k4 + 2) * 32 + b];
                float z3v = Zin[(4 * k4 + 3) * 32 + b];
#pragma unroll
                for (int i = 0; i < 16; i++) {
                    float4 kr = ((const float4*)Ks)[(ig * 16 + i) * 32 + k4];
                    acc[i] += kr.x * z0v + kr.y * z1v + kr.z * z2v + kr.w * z3v;
                }
            }
#pragma unroll
            for (int i = 0; i < 16; i++)
                Zout[(ig * 16 + i) * 32 + b] = acc[i];
            __syncthreads();
            float* tp = Zin; Zin = Zout; Zout = tp;
        }
    }

    for (int i = tid; i < L * BZ; i += 256) {
        int bb = i >> 7, l = i & 127;
        g_Z[((size_t)t * BZ + bb) * L + l] = Zin[l * 32 + bb];
    }
}

// ---------------- W split/transpose (coalesced reads via smem tile) ----------------
__global__ void splitW_kernel(const float* __restrict__ W) {
    __shared__ float tile[128][33];
    int n0 = blockIdx.x * 32;
    int tx = threadIdx.x & 31, ty = threadIdx.x >> 5;
    for (int k = ty; k < 128; k += 8)
        tile[k][tx] = W[(size_t)k * DD + n0 + tx];
    __syncthreads();
    int n  = n0 + (threadIdx.x >> 3);
    int k0 = (threadIdx.x & 7) * 16;
    int c  = n - n0;
    __nv_bfloat162 hi[8], lo[8];
#pragma unroll
    for (int j = 0; j < 8; j++) {
        float w0 = tile[k0 + 2 * j][c];
        float w1 = tile[k0 + 2 * j + 1][c];
        __nv_bfloat16 h0 = __float2bfloat16(w0);
        __nv_bfloat16 h1 = __float2bfloat16(w1);
        hi[j] = __halves2bfloat162(h0, h1);
        lo[j] = __halves2bfloat162(__float2bfloat16(w0 - __bfloat162float(h0)),
                                   __float2bfloat16(w1 - __bfloat162float(h1)));
    }
    uint4* dh = (uint4*)(g_Whi + (size_t)n * L + k0);
    uint4* dl = (uint4*)(g_Wlo + (size_t)n * L + k0);
    dh[0] = ((uint4*)hi)[0]; dh[1] = ((uint4*)hi)[1];
    dl[0] = ((uint4*)lo)[0]; dl[1] = ((uint4*)lo)[1];
}

// ---------------- hidden dense: [16384,128] @ [128,128] + b ----------------
__global__ __launch_bounds__(256, 1)
void dense_wide_kernel(const float* __restrict__ X, const float* __restrict__ W,
                       const float* __restrict__ bias, float* __restrict__ outf,
                       int mode) {
    extern __shared__ float sm[];
    float* Xs = sm;            // 128*128
    float* Ws = sm + L * L;    // 128*128
    int tid = threadIdx.x;
    int bm0 = blockIdx.x * 128;

    const float4* X4 = (const float4*)X + (size_t)bm0 * 32;
    float4* Xs4 = (float4*)Xs;
    float4* Ws4 = (float4*)Ws;
    const float4* W4 = (const float4*)W;
#pragma unroll
    for (int i = tid; i < L * L / 4; i += 256) { Xs4[i] = X4[i]; Ws4[i] = W4[i]; }
    __syncthreads();

    int tx = tid & 31;
    int ty = tid >> 5;
    int r0 = ty * 16;

    float acc[16][4];
#pragma unroll
    for (int i = 0; i < 16; i++)
#pragma unroll
        for (int j = 0; j < 4; j++) acc[i][j] = 0.f;

    for (int k4 = 0; k4 < 32; k4++) {
        float4 b0 = Ws4[(4 * k4 + 0) * 32 + tx];
        float4 b1 = Ws4[(4 * k4 + 1) * 32 + tx];
        float4 b2 = Ws4[(4 * k4 + 2) * 32 + tx];
        float4 b3 = Ws4[(4 * k4 + 3) * 32 + tx];
#pragma unroll
        for (int i = 0; i < 16; i++) {
            float4 a = Xs4[(r0 + i) * 32 + k4];
            acc[i][0] += a.x * b0.x + a.y * b1.x + a.z * b2.x + a.w * b3.x;
            acc[i][1] += a.x * b0.y + a.y * b1.y + a.z * b2.y + a.w * b3.y;
            acc[i][2] += a.x * b0.z + a.y * b1.z + a.z * b2.z + a.w * b3.z;
            acc[i][3] += a.x * b0.w + a.y * b1.w + a.z * b2.w + a.w * b3.w;
        }
    }

    float4 bb = ((const float4*)bias)[tx];
#pragma unroll
    for (int i = 0; i < 16; i++) {
        float4 v;
        v.x = fmaxf(acc[i][0] + bb.x, 0.f);
        v.y = fmaxf(acc[i][1] + bb.y, 0.f);
        v.z = fmaxf(acc[i][2] + bb.z, 0.f);
        v.w = fmaxf(acc[i][3] + bb.w, 0.f);
        size_t row = (size_t)(bm0 + r0 + i);
        if (mode == 0) {
            ((float4*)outf)[row * 32 + tx] = v;
        } else {
            __nv_bfloat16 h0 = __float2bfloat16(v.x), h1 = __float2bfloat16(v.y);
            __nv_bfloat16 h2 = __float2bfloat16(v.z), h3 = __float2bfloat16(v.w);
            __nv_bfloat16 l0 = __float2bfloat16(v.x - __bfloat162float(h0));
            __nv_bfloat16 l1 = __float2bfloat16(v.y - __bfloat162float(h1));
            __nv_bfloat16 l2 = __float2bfloat16(v.z - __bfloat162float(h2));
            __nv_bfloat16 l3 = __float2bfloat16(v.w - __bfloat162float(h3));
            __nv_bfloat162* dh = (__nv_bfloat162*)(g_Ahi + row * L + tx * 4);
            __nv_bfloat162* dl = (__nv_bfloat162*)(g_Alo + row * L + tx * 4);
            dh[0] = __halves2bfloat162(h0, h1);
            dh[1] = __halves2bfloat162(h2, h3);
            dl[0] = __halves2bfloat162(l0, l1);
            dl[1] = __halves2bfloat162(l2, l3);
        }
    }
}

// ================= persistent final GEMM: mma.sync bf16 hi/lo + cp.async pipeline =================
// [16384,128] @ [128,4096] + b. grid (32 n-blocks, 4 m-groups); each CTA: B resident,
// 32 m-tiles of A double-buffered with cp.async.

#define SPE 136                         // padded row stride in bf16 (272 B; odd*16B -> ldmatrix conflict-free)
#define TILE_BYTES (128 * SPE * 2)      // 34816 B per bf16 tile
#define OFF_BHI  0
#define OFF_BLO  TILE_BYTES
#define OFF_A0   (2 * TILE_BYTES)
#define OFF_A1   (4 * TILE_BYTES)
#define FSM_BYTES (6 * TILE_BYTES)      // 208896 B

__device__ __forceinline__ uint32_t smem_u32(const void* p) {
    uint32_t a;
    asm("{ .reg .u64 t; cvta.to.shared.u64 t, %1; cvt.u32.u64 %0, t; }" : "=r"(a) : "l"(p));
    return a;
}
__device__ __forceinline__ void cpasync16(uint32_t dst, const void* src) {
    asm volatile("cp.async.cg.shared.global [%0], [%1], 16;" :: "r"(dst), "l"(src));
}
__device__ __forceinline__ void cp_commit() {
    asm volatile("cp.async.commit_group;" ::: "memory");
}
__device__ __forceinline__ void cp_wait1() {
    asm volatile("cp.async.wait_group 1;" ::: "memory");
}
__device__ __forceinline__ void cp_wait0() {
    asm volatile("cp.async.wait_group 0;" ::: "memory");
}
__device__ __forceinline__ void ldmx4(uint32_t* r, uint32_t addr) {
    asm volatile("ldmatrix.sync.aligned.m8n8.x4.shared.b16 {%0,%1,%2,%3}, [%4];"
                 : "=r"(r[0]), "=r"(r[1]), "=r"(r[2]), "=r"(r[3]) : "r"(addr));
}
__device__ __forceinline__ void ldmx2(uint32_t* r, uint32_t addr) {
    asm volatile("ldmatrix.sync.aligned.m8n8.x2.shared.b16 {%0,%1}, [%2];"
                 : "=r"(r[0]), "=r"(r[1]) : "r"(addr));
}
__device__ __forceinline__ void mma16816(float* c, const uint32_t* a, const uint32_t* b) {
    asm volatile(
        "mma.sync.aligned.m16n8k16.row.col.f32.bf16.bf16.f32 "
        "{%0,%1,%2,%3}, {%4,%5,%6,%7}, {%8,%9}, {%0,%1,%2,%3};"
        : "+f"(c[0]), "+f"(c[1]), "+f"(c[2]), "+f"(c[3])
        : "r"(a[0]), "r"(a[1]), "r"(a[2]), "r"(a[3]), "r"(b[0]), "r"(b[1]));
}

__device__ __forceinline__ void issue_A(uint32_t sbase, int bm0, int tid) {
    const uint4* GAh = (const uint4*)g_Ahi;
    const uint4* GAl = (const uint4*)g_Alo;
#pragma unroll
    for (int t = tid; t < 2048; t += 256) {
        int r = t >> 4, q = t & 15;
        uint32_t dst = sbase + (uint32_t)(r * (SPE * 2) + q * 16);
        cpasync16(dst,                        GAh + (size_t)(bm0 + r) * 16 + q);
        cpasync16(dst + (uint32_t)TILE_BYTES, GAl + (size_t)(bm0 + r) * 16 + q);
    }
}

__global__ __launch_bounds__(256, 1)
void final_mma_kernel(const float* __restrict__ bias, float* __restrict__ out) {
    extern __shared__ __align__(16) char smf[];
    uint32_t sbase = smem_u32(smf);
    int tid  = threadIdx.x;
    int wid  = tid >> 5, lane = tid & 31;
    int bn0  = blockIdx.x * 128;

    // ---- B tiles via cp.async (group 0) ----
    const uint4* GBh = (const uint4*)g_Whi;
    const uint4* GBl = (const uint4*)g_Wlo;
#pragma unroll
    for (int t = tid; t < 2048; t += 256) {
        int r = t >> 4, q = t & 15;
        uint32_t dst = sbase + (uint32_t)(r * (SPE * 2) + q * 16);
        cpasync16(dst + OFF_BHI, GBh + (size_t)(bn0 + r) * 16 + q);
        cpasync16(dst + OFF_BLO, GBl + (size_t)(bn0 + r) * 16 + q);
    }
    cp_commit();

    // ---- A stage 0 (group 1) ----
    issue_A(sbase + OFF_A0, blockIdx.y * 128, tid);
    cp_commit();

    // warp tile: 64 rows x 32 cols
    int wm = wid >> 2, wn = wid & 3;

    // ldmatrix offsets (byte offsets within a tile)
    uint32_t a_off[4], b_off[4];
#pragma unroll
    for (int mi = 0; mi < 4; mi++) {
        int row = wm * 64 + mi * 16 + (lane & 15);
        a_off[mi] = (uint32_t)(row * SPE * 2) + ((lane >> 4) << 4);
    }
#pragma unroll
    for (int ni = 0; ni < 4; ni++) {
        int row = wn * 32 + ni * 8 + (lane & 7);
        b_off[ni] = (uint32_t)(row * SPE * 2) + (((lane >> 3) & 1) << 4);
    }
    uint32_t sBhi = sbase + OFF_BHI, sBlo = sbase + OFF_BLO;

    // bias registers (n-range fixed for this CTA)
    int g  = lane >> 2;
    int cc = (lane & 3) * 2;
    float2 br[4];
#pragma unroll
    for (int ni = 0; ni < 4; ni++) {
        int col = bn0 + wn * 32 + ni * 8 + cc;
        br[ni] = make_float2(bias[col], bias[col + 1]);
    }

    const int NT = 32;   // m-tiles per CTA
    for (int it = 0; it < NT; it++) {
        int bm0 = (blockIdx.y + 4 * it) * 128;
        if (it + 1 < NT) {
            issue_A(sbase + ((it + 1) & 1 ? OFF_A1 : OFF_A0),
                    (blockIdx.y + 4 * (it + 1)) * 128, tid);
            cp_commit();
            cp_wait1();
        } else {
            cp_wait0();
        }
        __syncthreads();

        uint32_t sA = sbase + ((it & 1) ? OFF_A1 : OFF_A0);
        float c[4][4][4];
#pragma unroll
        for (int mi = 0; mi < 4; mi++)
#pragma unroll
            for (int ni = 0; ni < 4; ni++)
#pragma unroll
                for (int j = 0; j < 4; j++) c[mi][ni][j] = 0.f;

#pragma unroll
        for (int k0 = 0; k0 < 8; k0++) {
            uint32_t koff = (uint32_t)(k0 * 32);
            uint32_t ah[4][4], al[4][4], bh[4][2], bl[4][2];
#pragma unroll
            for (int mi = 0; mi < 4; mi++) {
                ldmx4(ah[mi], sA + a_off[mi] + koff);
                ldmx4(al[mi], sA + (uint32_t)TILE_BYTES + a_off[mi] + koff);
            }
#pragma unroll
            for (int ni = 0; ni < 4; ni++) {
                ldmx2(bh[ni], sBhi + b_off[ni] + koff);
                ldmx2(bl[ni], sBlo + b_off[ni] + koff);
            }
#pragma unroll
            for (int mi = 0; mi < 4; mi++)
#pragma unroll
                for (int ni = 0; ni < 4; ni++) {
                    mma16816(c[mi][ni], ah[mi], bh[ni]);
                    mma16816(c[mi][ni], ah[mi], bl[ni]);
                    mma16816(c[mi][ni], al[mi], bh[ni]);
                }
        }

        // epilogue for this m-tile
#pragma unroll
        for (int ni = 0; ni < 4; ni++) {
            int col = bn0 + wn * 32 + ni * 8 + cc;
#pragma unroll
            for (int mi = 0; mi < 4; mi++) {
                size_t row = (size_t)(bm0 + wm * 64 + mi * 16 + g);
                float2 v0 = make_float2(c[mi][ni][0] + br[ni].x, c[mi][ni][1] + br[ni].y);
                float2 v1 = make_float2(c[mi][ni][2] + br[ni].x, c[mi][ni][3] + br[ni].y);
                *(float2*)(out + row * DD + col)       = v0;
                *(float2*)(out + (row + 8) * DD + col) = v1;
            }
        }
        __syncthreads();   // all ldmatrix reads done before next-stage cp.async overwrite
    }
}

// ---------------- launch ----------------
extern "C" void kernel_launch(void* const* d_in, const int* in_sizes, int n_in,
                              void* d_out, int out_size) {
    const float* x0  = (const float*)d_in[0];
    const int*   idx = (const int*)  d_in[1];
    const float* K   = (const float*)d_in[2];
    const float* We0 = (const float*)d_in[3];
    const float* be0 = (const float*)d_in[4];
    const float* We1 = (const float*)d_in[5];
    const float* be1 = (const float*)d_in[6];
    const float* We2 = (const float*)d_in[7];
    const float* be2 = (const float*)d_in[8];
    const float* We3 = (const float*)d_in[9];
    const float* be3 = (const float*)d_in[10];
    const float* Wd0 = (const float*)d_in[11];
    const float* bd0 = (const float*)d_in[12];
    const float* Wd1 = (const float*)d_in[13];
    const float* bd1 = (const float*)d_in[14];
    const float* Wd2 = (const float*)d_in[15];
    const float* bd2 = (const float*)d_in[16];
    const float* Wd3 = (const float*)d_in[17];
    const float* bd3 = (const float*)d_in[18];
    float* out = (float*)d_out;

    const int smem_zprop = (L * L + 2 * L * BZ) * 4;   // 96 KB
    const int smem_dense = 2 * L * L * 4;              // 128 KB
    const int smem_final = FSM_BYTES;                  // ~204 KB
    cudaFuncSetAttribute(zprop_kernel,      cudaFuncAttributeMaxDynamicSharedMemorySize, smem_zprop);
    cudaFuncSetAttribute(dense_wide_kernel, cudaFuncAttributeMaxDynamicSharedMemorySize, smem_dense);
    cudaFuncSetAttribute(final_mma_kernel,  cudaFuncAttributeMaxDynamicSharedMemorySize, smem_final);

    float *pZ, *pT1, *pT2;
    cudaGetSymbolAddress((void**)&pZ,  g_Z);
    cudaGetSymbolAddress((void**)&pT1, g_T1);
    cudaGetSymbolAddress((void**)&pT2, g_T2);

    // Encoder (enc_tail also resets the kpow grid barrier)
    enc0_kernel<<<BZ, 128>>>(x0, We0, be0);
    enc_tail_kernel<<<1, 256>>>(We1, be1, We2, be2, We3, be3);

    // All 9 binary powers of K in one kernel
    kpow_fused_kernel<<<128, 128>>>(K);

    // Z[t] = K^exps[t] @ z0^T
    zprop_kernel<<<TT, 256, smem_zprop>>>(K, idx);

    // Wd3 transpose + bf16 hi/lo split
    splitW_kernel<<<DD / 32, 256>>>(Wd3);

    // Decoder hidden layers (last one emits bf16 hi/lo activations)
    dense_wide_kernel<<<MT / 128, 256, smem_dense>>>(pZ,  Wd0, bd0, pT1, 0);
    dense_wide_kernel<<<MT / 128, 256, smem_dense>>>(pT1, Wd1, bd1, pT2, 0);
    dense_wide_kernel<<<MT / 128, 256, smem_dense>>>(pT2, Wd2, bd2, nullptr, 2);

    // Final projection: persistent tensor-core GEMM
    dim3 fgrid(DD / 128, 4);   // (32 n-blocks, 4 m-groups)
    final_mma_kernel<<<fgrid, 256, smem_final>>>(bd3, out);
}

// round 5
// speedup vs baseline: 1.4139x; 1.0662x over previous
#include <cuda_runtime.h>
#include <cuda_bf16.h>
#include <stdint.h>

#define L   128
#define BZ  32
#define TT  512
#define DD  4096
#define MT  (TT*BZ)   // 16384 decoder rows

// ---------------- scratch (device globals; no allocation) ----------------
__device__ float g_h1[BZ * L];
__device__ float g_z0[BZ * L];
__device__ float g_Kpow[9 * L * L];          // K^2, K^4, ..., K^512
__device__ float g_Klo[16 * L * L];          // K^lo, lo in [0,16) (0,1 unused)
__device__ float g_Phi[64 * L * BZ];         // Phi[hi] = (K^16)^hi @ z0^T, layout [hi][l][b]
__device__ float g_Z [MT * L];
__device__ float g_T1[MT * L];
__device__ float g_T2[MT * L];
__device__ __nv_bfloat16 g_Ahi[MT * L];      // last hidden activations, bf16 hi
__device__ __nv_bfloat16 g_Alo[MT * L];      // residual lo
__device__ __nv_bfloat16 g_Whi[DD * L];      // Wd3 transposed [n][k], hi
__device__ __nv_bfloat16 g_Wlo[DD * L];      // residual lo
__device__ int g_bar[16];                    // kpow grid barrier (zeroed by enc_tail)

// ---------------- encoder layer 0 ----------------
__global__ void enc0_kernel(const float* __restrict__ x0,
                            const float* __restrict__ W,
                            const float* __restrict__ b) {
    __shared__ float xs[DD];
    int row = blockIdx.x;
    const float4* x4 = (const float4*)(x0 + (size_t)row * DD);
    for (int i = threadIdx.x; i < DD / 4; i += 128)
        ((float4*)xs)[i] = x4[i];
    __syncthreads();
    int n = threadIdx.x;
    float a0 = 0.f, a1 = 0.f, a2 = 0.f, a3 = 0.f;
#pragma unroll 4
    for (int k = 0; k < DD; k += 4) {
        a0 += xs[k + 0] * W[(size_t)(k + 0) * L + n];
        a1 += xs[k + 1] * W[(size_t)(k + 1) * L + n];
        a2 += xs[k + 2] * W[(size_t)(k + 2) * L + n];
        a3 += xs[k + 3] * W[(size_t)(k + 3) * L + n];
    }
    float acc = (a0 + a1) + (a2 + a3) + b[n];
    g_h1[row * L + n] = fmaxf(acc, 0.f);
}

// ---------------- fused encoder tail; also zeroes g_bar ----------------
__device__ __forceinline__ void enc_layer(const float* Xin, const float* __restrict__ W,
                                          const float* __restrict__ b,
                                          float* Xout, float* gout, int relu, int tid) {
    int n = tid & 127;
    int r0 = (tid >> 7) * 16;
    float acc[16];
#pragma unroll
    for (int i = 0; i < 16; i++) acc[i] = 0.f;
#pragma unroll 4
    for (int k = 0; k < L; k++) {
        float w = W[k * L + n];
#pragma unroll
        for (int i = 0; i < 16; i++) acc[i] += Xin[(r0 + i) * L + k] * w;
    }
    float bn = b[n];
#pragma unroll
    for (int i = 0; i < 16; i++) {
        float v = acc[i] + bn;
        if (relu) v = fmaxf(v, 0.f);
        if (Xout) Xout[(r0 + i) * L + n] = v;
        else      gout[(r0 + i) * L + n] = v;
    }
}

__global__ void enc_tail_kernel(const float* W1, const float* b1,
                                const float* W2, const float* b2,
                                const float* W3, const float* b3) {
    __shared__ float Xa[BZ * L];
    __shared__ float Xb[BZ * L];
    int tid = threadIdx.x;
    if (tid < 16) g_bar[tid] = 0;
    for (int i = tid; i < BZ * L; i += 256) Xa[i] = g_h1[i];
    __syncthreads();
    enc_layer(Xa, W1, b1, Xb, nullptr, 1, tid); __syncthreads();
    enc_layer(Xb, W2, b2, Xa, nullptr, 1, tid); __syncthreads();
    enc_layer(Xa, W3, b3, nullptr, g_z0, 0, tid);
    __threadfence();
}

// ---------------- all 9 K squarings in one kernel, software grid barrier ----------------
__global__ void kpow_fused_kernel(const float* __restrict__ K1) {
    __shared__ float rowA[L];
    int i = blockIdx.x;
    int n = threadIdx.x;
    const float* A = K1;
    for (int p = 0; p < 9; p++) {
        float* C = g_Kpow + (size_t)p * L * L;
        rowA[n] = A[i * L + n];
        __syncthreads();
        float a0 = 0.f, a1 = 0.f, a2 = 0.f, a3 = 0.f;
#pragma unroll 8
        for (int k = 0; k < L; k += 4) {
            a0 += rowA[k + 0] * A[(k + 0) * L + n];
            a1 += rowA[k + 1] * A[(k + 1) * L + n];
            a2 += rowA[k + 2] * A[(k + 2) * L + n];
            a3 += rowA[k + 3] * A[(k + 3) * L + n];
        }
        C[i * L + n] = (a0 + a1) + (a2 + a3);
        __threadfence();
        __syncthreads();
        if (threadIdx.x == 0) {
            atomicAdd(&g_bar[p], 1);
            while (atomicAdd(&g_bar[p], 0) < (int)gridDim.x) {}
            __threadfence();
        }
        __syncthreads();
        A = C;
    }
}

// ---------------- K^lo table: lo in [2,16), product of bits over {K, K2, K4, K8} ----------------
// grid (14, 4): x -> lo-2, y -> 32-row band. smem: F 64KB + two 16KB band buffers.
__global__ __launch_bounds__(256)
void klo_kernel(const float* __restrict__ K1) {
    extern __shared__ float sm[];
    float* Fs = sm;              // 128*128
    float* S  = sm + L * L;      // 32*128
    float* T  = S + 32 * L;      // 32*128
    int l    = blockIdx.x + 2;
    int band = blockIdx.y;
    int tid  = threadIdx.x;

    const float* fac[4]; int nf = 0;
    if (l & 1) fac[nf++] = K1;
    if (l & 2) fac[nf++] = g_Kpow + 0 * L * L;   // K^2
    if (l & 4) fac[nf++] = g_Kpow + 1 * L * L;   // K^4
    if (l & 8) fac[nf++] = g_Kpow + 2 * L * L;   // K^8

    // S = rows [band*32, band*32+32) of fac[0]
    const float4* f0 = (const float4*)(fac[0] + (size_t)band * 32 * L);
#pragma unroll
    for (int i = tid; i < 32 * L / 4; i += 256) ((float4*)S)[i] = f0[i];
    __syncthreads();

    float* in = S; float* out = T;
    for (int f = 1; f < nf; f++) {
        const float4* F4 = (const float4*)fac[f];
#pragma unroll
        for (int i = tid; i < L * L / 4; i += 256) ((float4*)Fs)[i] = F4[i];
        __syncthreads();
        int n  = tid & 127;
        int r0 = (tid >> 7) * 16;
        float acc[16];
#pragma unroll
        for (int i = 0; i < 16; i++) acc[i] = 0.f;
#pragma unroll 4
        for (int k = 0; k < L; k++) {
            float w = Fs[k * L + n];
#pragma unroll
            for (int i = 0; i < 16; i++) acc[i] += in[(r0 + i) * L + k] * w;
        }
        __syncthreads();
#pragma unroll
        for (int i = 0; i < 16; i++) out[(r0 + i) * L + n] = acc[i];
        __syncthreads();
        float* tp = in; in = out; out = tp;
    }

    float* dst = g_Klo + (size_t)l * L * L + (size_t)band * 32 * L;
#pragma unroll
    for (int i = tid; i < 32 * L / 4; i += 256) ((float4*)dst)[i] = ((float4*)in)[i];
}

// ---------------- Phi[hi] = (K^16)^hi @ z0^T, binary bits of hi ----------------
// 64 CTAs; state [l][b] = [128][32]; matrices K^(16*2^j) = g_Kpow[3+j].
__global__ __launch_bounds__(256)
void phi_kernel() {
    extern __shared__ float sm[];
    float* Ks    = sm;
    float* Zbuf0 = sm + L * L;
    float* Zbuf1 = Zbuf0 + L * BZ;
    int hi  = blockIdx.x;
    int tid = threadIdx.x;

    for (int i = tid; i < L * BZ; i += 256) {
        int l = i >> 5, b = i & 31;
        Zbuf0[i] = g_z0[b * L + l];
    }
    __syncthreads();

    float* Zin = Zbuf0; float* Zout = Zbuf1;
    int b  = tid & 31;
    int ig = tid >> 5;

    for (int j = 0; j < 6; j++) {
        if ((hi >> j) & 1) {
            const float* Kp = g_Kpow + (size_t)(3 + j) * L * L;
#pragma unroll
            for (int i = tid; i < L * L / 4; i += 256)
                ((float4*)Ks)[i] = ((const float4*)Kp)[i];
            __syncthreads();

            float acc[16];
#pragma unroll
            for (int i = 0; i < 16; i++) acc[i] = 0.f;
            for (int k4 = 0; k4 < 32; k4++) {
                float z0v = Zin[(4 * k4 + 0) * 32 + b];
                float z1v = Zin[(4 * k4 + 1) * 32 + b];
                float z2v = Zin[(4 * k4 + 2) * 32 + b];
                float z3v = Zin[(4 * k4 + 3) * 32 + b];
#pragma unroll
                for (int i = 0; i < 16; i++) {
                    float4 kr = ((const float4*)Ks)[(ig * 16 + i) * 32 + k4];
                    acc[i] += kr.x * z0v + kr.y * z1v + kr.z * z2v + kr.w * z3v;
                }
            }
#pragma unroll
            for (int i = 0; i < 16; i++)
                Zout[(ig * 16 + i) * 32 + b] = acc[i];
            __syncthreads();
            float* tp = Zin; Zin = Zout; Zout = tp;
        }
    }

    float4* dst = (float4*)(g_Phi + (size_t)hi * L * BZ);
#pragma unroll
    for (int i = tid; i < L * BZ / 4; i += 256) dst[i] = ((float4*)Zin)[i];
}

// ---------------- apply: Z_t = K^lo(t) @ Phi[hi(t)], ONE matrix apply per t ----------------
__global__ __launch_bounds__(256)
void apply_kernel(const float* __restrict__ K1, const int* __restrict__ idxw) {
    extern __shared__ float sm[];
    float* Ks    = sm;
    float* Zbuf0 = sm + L * L;
    float* Zbuf1 = Zbuf0 + L * BZ;
    int t   = blockIdx.x;
    int tid = threadIdx.x;

    bool is64 = ((idxw[1] | idxw[3] | idxw[5] | idxw[7] | idxw[9] | idxw[11]) == 0);
    int e = is64 ? (idxw[2 * t] - idxw[0]) : (idxw[t] - idxw[0]);
    int lo = e & 15, hi = e >> 4;

    // state <- Phi[hi]  ([128][32])
    const float4* src = (const float4*)(g_Phi + (size_t)hi * L * BZ);
#pragma unroll
    for (int i = tid; i < L * BZ / 4; i += 256) ((float4*)Zbuf0)[i] = src[i];

    float* Zres = Zbuf0;
    if (lo != 0) {
        const float* Kp = (lo == 1) ? K1 : (g_Klo + (size_t)lo * L * L);
#pragma unroll
        for (int i = tid; i < L * L / 4; i += 256)
            ((float4*)Ks)[i] = ((const float4*)Kp)[i];
        __syncthreads();

        int b  = tid & 31;
        int ig = tid >> 5;
        float acc[16];
#pragma unroll
        for (int i = 0; i < 16; i++) acc[i] = 0.f;
        for (int k4 = 0; k4 < 32; k4++) {
            float z0v = Zbuf0[(4 * k4 + 0) * 32 + b];
            float z1v = Zbuf0[(4 * k4 + 1) * 32 + b];
            float z2v = Zbuf0[(4 * k4 + 2) * 32 + b];
            float z3v = Zbuf0[(4 * k4 + 3) * 32 + b];
#pragma unroll
            for (int i = 0; i < 16; i++) {
                float4 kr = ((const float4*)Ks)[(ig * 16 + i) * 32 + k4];
                acc[i] += kr.x * z0v + kr.y * z1v + kr.z * z2v + kr.w * z3v;
            }
        }
#pragma unroll
        for (int i = 0; i < 16; i++)
            Zbuf1[(ig * 16 + i) * 32 + b] = acc[i];
        Zres = Zbuf1;
    }
    __syncthreads();

    // g_Z[(t*32+bb)][l] = state[l][bb]
    for (int i = tid; i < L * BZ; i += 256) {
        int bb = i >> 7, l = i & 127;
        g_Z[((size_t)t * BZ + bb) * L + l] = Zres[l * 32 + bb];
    }
}

// ---------------- W split/transpose ----------------
__global__ void splitW_kernel(const float* __restrict__ W) {
    __shared__ float tile[128][33];
    int n0 = blockIdx.x * 32;
    int tx = threadIdx.x & 31, ty = threadIdx.x >> 5;
    for (int k = ty; k < 128; k += 8)
        tile[k][tx] = W[(size_t)k * DD + n0 + tx];
    __syncthreads();
    int n  = n0 + (threadIdx.x >> 3);
    int k0 = (threadIdx.x & 7) * 16;
    int c  = n - n0;
    __nv_bfloat162 hi[8], lo[8];
#pragma unroll
    for (int j = 0; j < 8; j++) {
        float w0 = tile[k0 + 2 * j][c];
        float w1 = tile[k0 + 2 * j + 1][c];
        __nv_bfloat16 h0 = __float2bfloat16(w0);
        __nv_bfloat16 h1 = __float2bfloat16(w1);
        hi[j] = __halves2bfloat162(h0, h1);
        lo[j] = __halves2bfloat162(__float2bfloat16(w0 - __bfloat162float(h0)),
                                   __float2bfloat16(w1 - __bfloat162float(h1)));
    }
    uint4* dh = (uint4*)(g_Whi + (size_t)n * L + k0);
    uint4* dl = (uint4*)(g_Wlo + (size_t)n * L + k0);
    dh[0] = ((uint4*)hi)[0]; dh[1] = ((uint4*)hi)[1];
    dl[0] = ((uint4*)lo)[0]; dl[1] = ((uint4*)lo)[1];
}

// ---------------- hidden dense: 64-row tiles, 2 CTAs/SM ----------------
__global__ __launch_bounds__(256)
void dense64_kernel(const float* __restrict__ X, const float* __restrict__ W,
                    const float* __restrict__ bias, float* __restrict__ outf,
                    int mode) {
    extern __shared__ float sm[];
    float* Xs = sm;            // 64*128
    float* Ws = sm + 64 * L;   // 128*128
    int tid = threadIdx.x;
    int bm0 = blockIdx.x * 64;

    const float4* X4 = (const float4*)X + (size_t)bm0 * 32;
    float4* Xs4 = (float4*)Xs;
    float4* Ws4 = (float4*)Ws;
    const float4* W4 = (const float4*)W;
#pragma unroll
    for (int i = tid; i < 64 * L / 4; i += 256) Xs4[i] = X4[i];
#pragma unroll
    for (int i = tid; i < L * L / 4; i += 256) Ws4[i] = W4[i];
    __syncthreads();

    int tx = tid & 31;    // float4 n-col
    int ty = tid >> 5;    // warp id -> rows (warp-uniform)
    int r0 = ty * 8;

    float acc[8][4];
#pragma unroll
    for (int i = 0; i < 8; i++)
#pragma unroll
        for (int j = 0; j < 4; j++) acc[i][j] = 0.f;

    for (int k4 = 0; k4 < 32; k4++) {
        float4 b0 = Ws4[(4 * k4 + 0) * 32 + tx];
        float4 b1 = Ws4[(4 * k4 + 1) * 32 + tx];
        float4 b2 = Ws4[(4 * k4 + 2) * 32 + tx];
        float4 b3 = Ws4[(4 * k4 + 3) * 32 + tx];
#pragma unroll
        for (int i = 0; i < 8; i++) {
            float4 a = Xs4[(r0 + i) * 32 + k4];
            acc[i][0] += a.x * b0.x + a.y * b1.x + a.z * b2.x + a.w * b3.x;
            acc[i][1] += a.x * b0.y + a.y * b1.y + a.z * b2.y + a.w * b3.y;
            acc[i][2] += a.x * b0.z + a.y * b1.z + a.z * b2.z + a.w * b3.z;
            acc[i][3] += a.x * b0.w + a.y * b1.w + a.z * b2.w + a.w * b3.w;
        }
    }

    float4 bb = ((const float4*)bias)[tx];
#pragma unroll
    for (int i = 0; i < 8; i++) {
        float4 v;
        v.x = fmaxf(acc[i][0] + bb.x, 0.f);
        v.y = fmaxf(acc[i][1] + bb.y, 0.f);
        v.z = fmaxf(acc[i][2] + bb.z, 0.f);
        v.w = fmaxf(acc[i][3] + bb.w, 0.f);
        size_t row = (size_t)(bm0 + r0 + i);
        if (mode == 0) {
            ((float4*)outf)[row * 32 + tx] = v;
        } else {
            __nv_bfloat16 h0 = __float2bfloat16(v.x), h1 = __float2bfloat16(v.y);
            __nv_bfloat16 h2 = __float2bfloat16(v.z), h3 = __float2bfloat16(v.w);
            __nv_bfloat16 l0 = __float2bfloat16(v.x - __bfloat162float(h0));
            __nv_bfloat16 l1 = __float2bfloat16(v.y - __bfloat162float(h1));
            __nv_bfloat16 l2 = __float2bfloat16(v.z - __bfloat162float(h2));
            __nv_bfloat16 l3 = __float2bfloat16(v.w - __bfloat162float(h3));
            __nv_bfloat162* dh = (__nv_bfloat162*)(g_Ahi + row * L + tx * 4);
            __nv_bfloat162* dl = (__nv_bfloat162*)(g_Alo + row * L + tx * 4);
            dh[0] = __halves2bfloat162(h0, h1);
            dh[1] = __halves2bfloat162(h2, h3);
            dl[0] = __halves2bfloat162(l0, l1);
            dl[1] = __halves2bfloat162(l2, l3);
        }
    }
}

// ================= persistent final GEMM: mma.sync bf16 hi/lo + cp.async pipeline =================
#define SPE 136
#define TILE_BYTES (128 * SPE * 2)
#define OFF_BHI  0
#define OFF_BLO  TILE_BYTES
#define OFF_A0   (2 * TILE_BYTES)
#define OFF_A1   (4 * TILE_BYTES)
#define FSM_BYTES (6 * TILE_BYTES)

__device__ __forceinline__ uint32_t smem_u32(const void* p) {
    uint32_t a;
    asm("{ .reg .u64 t; cvta.to.shared.u64 t, %1; cvt.u32.u64 %0, t; }" : "=r"(a) : "l"(p));
    return a;
}
__device__ __forceinline__ void cpasync16(uint32_t dst, const void* src) {
    asm volatile("cp.async.cg.shared.global [%0], [%1], 16;" :: "r"(dst), "l"(src));
}
__device__ __forceinline__ void cp_commit() {
    asm volatile("cp.async.commit_group;" ::: "memory");
}
__device__ __forceinline__ void cp_wait1() {
    asm volatile("cp.async.wait_group 1;" ::: "memory");
}
__device__ __forceinline__ void cp_wait0() {
    asm volatile("cp.async.wait_group 0;" ::: "memory");
}
__device__ __forceinline__ void ldmx4(uint32_t* r, uint32_t addr) {
    asm volatile("ldmatrix.sync.aligned.m8n8.x4.shared.b16 {%0,%1,%2,%3}, [%4];"
                 : "=r"(r[0]), "=r"(r[1]), "=r"(r[2]), "=r"(r[3]) : "r"(addr));
}
__device__ __forceinline__ void ldmx2(uint32_t* r, uint32_t addr) {
    asm volatile("ldmatrix.sync.aligned.m8n8.x2.shared.b16 {%0,%1}, [%2];"
                 : "=r"(r[0]), "=r"(r[1]) : "r"(addr));
}
__device__ __forceinline__ void mma16816(float* c, const uint32_t* a, const uint32_t* b) {
    asm volatile(
        "mma.sync.aligned.m16n8k16.row.col.f32.bf16.bf16.f32 "
        "{%0,%1,%2,%3}, {%4,%5,%6,%7}, {%8,%9}, {%0,%1,%2,%3};"
        : "+f"(c[0]), "+f"(c[1]), "+f"(c[2]), "+f"(c[3])
        : "r"(a[0]), "r"(a[1]), "r"(a[2]), "r"(a[3]), "r"(b[0]), "r"(b[1]));
}

__device__ __forceinline__ void issue_A(uint32_t sbase, int bm0, int tid) {
    const uint4* GAh = (const uint4*)g_Ahi;
    const uint4* GAl = (const uint4*)g_Alo;
#pragma unroll
    for (int t = tid; t < 2048; t += 256) {
        int r = t >> 4, q = t & 15;
        uint32_t dst = sbase + (uint32_t)(r * (SPE * 2) + q * 16);
        cpasync16(dst,                        GAh + (size_t)(bm0 + r) * 16 + q);
        cpasync16(dst + (uint32_t)TILE_BYTES, GAl + (size_t)(bm0 + r) * 16 + q);
    }
}

__global__ __launch_bounds__(256, 1)
void final_mma_kernel(const float* __restrict__ bias, float* __restrict__ out) {
    extern __shared__ __align__(16) char smf[];
    uint32_t sbase = smem_u32(smf);
    int tid  = threadIdx.x;
    int wid  = tid >> 5, lane = tid & 31;
    int bn0  = blockIdx.x * 128;

    const uint4* GBh = (const uint4*)g_Whi;
    const uint4* GBl = (const uint4*)g_Wlo;
#pragma unroll
    for (int t = tid; t < 2048; t += 256) {
        int r = t >> 4, q = t & 15;
        uint32_t dst = sbase + (uint32_t)(r * (SPE * 2) + q * 16);
        cpasync16(dst + OFF_BHI, GBh + (size_t)(bn0 + r) * 16 + q);
        cpasync16(dst + OFF_BLO, GBl + (size_t)(bn0 + r) * 16 + q);
    }
    cp_commit();

    issue_A(sbase + OFF_A0, blockIdx.y * 128, tid);
    cp_commit();

    int wm = wid >> 2, wn = wid & 3;

    uint32_t a_off[4], b_off[4];
#pragma unroll
    for (int mi = 0; mi < 4; mi++) {
        int row = wm * 64 + mi * 16 + (lane & 15);
        a_off[mi] = (uint32_t)(row * SPE * 2) + ((lane >> 4) << 4);
    }
#pragma unroll
    for (int ni = 0; ni < 4; ni++) {
        int row = wn * 32 + ni * 8 + (lane & 7);
        b_off[ni] = (uint32_t)(row * SPE * 2) + (((lane >> 3) & 1) << 4);
    }
    uint32_t sBhi = sbase + OFF_BHI, sBlo = sbase + OFF_BLO;

    int g  = lane >> 2;
    int cc = (lane & 3) * 2;
    float2 br[4];
#pragma unroll
    for (int ni = 0; ni < 4; ni++) {
        int col = bn0 + wn * 32 + ni * 8 + cc;
        br[ni] = make_float2(bias[col], bias[col + 1]);
    }

    const int NT = 32;
    for (int it = 0; it < NT; it++) {
        int bm0 = (blockIdx.y + 4 * it) * 128;
        if (it + 1 < NT) {
            issue_A(sbase + ((it + 1) & 1 ? OFF_A1 : OFF_A0),
                    (blockIdx.y + 4 * (it + 1)) * 128, tid);
            cp_commit();
            cp_wait1();
        } else {
            cp_wait0();
        }
        __syncthreads();

        uint32_t sA = sbase + ((it & 1) ? OFF_A1 : OFF_A0);
        float c[4][4][4];
#pragma unroll
        for (int mi = 0; mi < 4; mi++)
#pragma unroll
            for (int ni = 0; ni < 4; ni++)
#pragma unroll
                for (int j = 0; j < 4; j++) c[mi][ni][j] = 0.f;

#pragma unroll
        for (int k0 = 0; k0 < 8; k0++) {
            uint32_t koff = (uint32_t)(k0 * 32);
            uint32_t ah[4][4], al[4][4], bh[4][2], bl[4][2];
#pragma unroll
            for (int mi = 0; mi < 4; mi++) {
                ldmx4(ah[mi], sA + a_off[mi] + koff);
                ldmx4(al[mi], sA + (uint32_t)TILE_BYTES + a_off[mi] + koff);
            }
#pragma unroll
            for (int ni = 0; ni < 4; ni++) {
                ldmx2(bh[ni], sBhi + b_off[ni] + koff);
                ldmx2(bl[ni], sBlo + b_off[ni] + koff);
            }
#pragma unroll
            for (int mi = 0; mi < 4; mi++)
#pragma unroll
                for (int ni = 0; ni < 4; ni++) {
                    mma16816(c[mi][ni], ah[mi], bh[ni]);
                    mma16816(c[mi][ni], ah[mi], bl[ni]);
                    mma16816(c[mi][ni], al[mi], bh[ni]);
                }
        }

#pragma unroll
        for (int ni = 0; ni < 4; ni++) {
            int col = bn0 + wn * 32 + ni * 8 + cc;
#pragma unroll
            for (int mi = 0; mi < 4; mi++) {
                size_t row = (size_t)(bm0 + wm * 64 + mi * 16 + g);
                float2 v0 = make_float2(c[mi][ni][0] + br[ni].x, c[mi][ni][1] + br[ni].y);
                float2 v1 = make_float2(c[mi][ni][2] + br[ni].x, c[mi][ni][3] + br[ni].y);
                *(float2*)(out + row * DD + col)       = v0;
                *(float2*)(out + (row + 8) * DD + col) = v1;
            }
        }
        __syncthreads();
    }
}

// ---------------- launch ----------------
extern "C" void kernel_launch(void* const* d_in, const int* in_sizes, int n_in,
                              void* d_out, int out_size) {
    const float* x0  = (const float*)d_in[0];
    const int*   idx = (const int*)  d_in[1];
    const float* K   = (const float*)d_in[2];
    const float* We0 = (const float*)d_in[3];
    const float* be0 = (const float*)d_in[4];
    const float* We1 = (const float*)d_in[5];
    const float* be1 = (const float*)d_in[6];
    const float* We2 = (const float*)d_in[7];
    const float* be2 = (const float*)d_in[8];
    const float* We3 = (const float*)d_in[9];
    const float* be3 = (const float*)d_in[10];
    const float* Wd0 = (const float*)d_in[11];
    const float* bd0 = (const float*)d_in[12];
    const float* Wd1 = (const float*)d_in[13];
    const float* bd1 = (const float*)d_in[14];
    const float* Wd2 = (const float*)d_in[15];
    const float* bd2 = (const float*)d_in[16];
    const float* Wd3 = (const float*)d_in[17];
    const float* bd3 = (const float*)d_in[18];
    float* out = (float*)d_out;

    const int smem_koop  = (L * L + 2 * L * BZ) * 4;   // 96 KB (phi/apply)
    const int smem_klo   = (L * L + 2 * 32 * L) * 4;   // 96 KB
    const int smem_dense = (64 * L + L * L) * 4;       // 96 KB
    const int smem_final = FSM_BYTES;                  // ~204 KB
    cudaFuncSetAttribute(klo_kernel,      cudaFuncAttributeMaxDynamicSharedMemorySize, smem_klo);
    cudaFuncSetAttribute(phi_kernel,      cudaFuncAttributeMaxDynamicSharedMemorySize, smem_koop);
    cudaFuncSetAttribute(apply_kernel,    cudaFuncAttributeMaxDynamicSharedMemorySize, smem_koop);
    cudaFuncSetAttribute(dense64_kernel,  cudaFuncAttributeMaxDynamicSharedMemorySize, smem_dense);
    cudaFuncSetAttribute(final_mma_kernel, cudaFuncAttributeMaxDynamicSharedMemorySize, smem_final);

    float *pZ, *pT1, *pT2;
    cudaGetSymbolAddress((void**)&pZ,  g_Z);
    cudaGetSymbolAddress((void**)&pT1, g_T1);
    cudaGetSymbolAddress((void**)&pT2, g_T2);

    // Encoder (enc_tail also resets the kpow grid barrier)
    enc0_kernel<<<BZ, 128>>>(x0, We0, be0);
    enc_tail_kernel<<<1, 256>>>(We1, be1, We2, be2, We3, be3);

    // K^2..K^512 (one kernel, 9 grid-barrier steps)
    kpow_fused_kernel<<<128, 128>>>(K);

    // K^lo table (lo = 2..15)
    klo_kernel<<<dim3(14, 4), 256, smem_klo>>>(K);

    // Phi[hi] = (K^16)^hi @ z0^T
    phi_kernel<<<64, 256, smem_koop>>>();

    // Z_t = K^lo(t) @ Phi[hi(t)]  (one apply per t)
    apply_kernel<<<TT, 256, smem_koop>>>(K, idx);

    // Wd3 transpose + bf16 hi/lo split
    splitW_kernel<<<DD / 32, 256>>>(Wd3);

    // Decoder hidden layers (last emits bf16 hi/lo activations)
    dense64_kernel<<<MT / 64, 256, smem_dense>>>(pZ,  Wd0, bd0, pT1, 0);
    dense64_kernel<<<MT / 64, 256, smem_dense>>>(pT1, Wd1, bd1, pT2, 0);
    dense64_kernel<<<MT / 64, 256, smem_dense>>>(pT2, Wd2, bd2, nullptr, 2);

    // Final projection: persistent tensor-core GEMM
    dim3 fgrid(DD / 128, 4);
    final_mma_kernel<<<fgrid, 256, smem_final>>>(bd3, out);
}

// round 6
// speedup vs baseline: 1.6806x; 1.1886x over previous
#include <cuda_runtime.h>
#include <cuda_fp16.h>
#include <stdint.h>

#define L   128
#define BZ  32
#define TT  512
#define DD  4096
#define MT  (TT*BZ)   // 16384 decoder rows

// ---------------- scratch (device globals; no allocation) ----------------
__device__ float g_h1[BZ * L];
__device__ float g_z0[BZ * L];
__device__ float g_Kpow[9 * L * L];          // K^2, K^4, ..., K^512
__device__ float g_Klo[16 * L * L];          // K^lo, lo in [0,16) (0,1 unused)
__device__ float g_Phi[64 * L * BZ];         // Phi[hi] = (K^16)^hi @ z0^T, [hi][l][b]
__device__ float g_Z [MT * L];
__device__ float g_T1[MT * L];
__device__ float g_T2[MT * L];
__device__ __half g_Ah[MT * L];              // last hidden activations, fp16
__device__ __half g_Wh[DD * L];              // Wd3 transposed [n][k], fp16
__device__ int g_bar[16];                    // kpow grid barrier (zeroed by enc_tail)

// ---------------- encoder layer 0 ----------------
__global__ void enc0_kernel(const float* __restrict__ x0,
                            const float* __restrict__ W,
                            const float* __restrict__ b) {
    __shared__ float xs[DD];
    int row = blockIdx.x;
    const float4* x4 = (const float4*)(x0 + (size_t)row * DD);
    for (int i = threadIdx.x; i < DD / 4; i += 128)
        ((float4*)xs)[i] = x4[i];
    __syncthreads();
    int n = threadIdx.x;
    float a0 = 0.f, a1 = 0.f, a2 = 0.f, a3 = 0.f;
#pragma unroll 4
    for (int k = 0; k < DD; k += 4) {
        a0 += xs[k + 0] * W[(size_t)(k + 0) * L + n];
        a1 += xs[k + 1] * W[(size_t)(k + 1) * L + n];
        a2 += xs[k + 2] * W[(size_t)(k + 2) * L + n];
        a3 += xs[k + 3] * W[(size_t)(k + 3) * L + n];
    }
    float acc = (a0 + a1) + (a2 + a3) + b[n];
    g_h1[row * L + n] = fmaxf(acc, 0.f);
}

// ---------------- fused encoder tail; also zeroes g_bar ----------------
__device__ __forceinline__ void enc_layer(const float* Xin, const float* __restrict__ W,
                                          const float* __restrict__ b,
                                          float* Xout, float* gout, int relu, int tid) {
    int n = tid & 127;
    int r0 = (tid >> 7) * 16;
    float acc[16];
#pragma unroll
    for (int i = 0; i < 16; i++) acc[i] = 0.f;
#pragma unroll 4
    for (int k = 0; k < L; k++) {
        float w = W[k * L + n];
#pragma unroll
        for (int i = 0; i < 16; i++) acc[i] += Xin[(r0 + i) * L + k] * w;
    }
    float bn = b[n];
#pragma unroll
    for (int i = 0; i < 16; i++) {
        float v = acc[i] + bn;
        if (relu) v = fmaxf(v, 0.f);
        if (Xout) Xout[(r0 + i) * L + n] = v;
        else      gout[(r0 + i) * L + n] = v;
    }
}

__global__ void enc_tail_kernel(const float* W1, const float* b1,
                                const float* W2, const float* b2,
                                const float* W3, const float* b3) {
    __shared__ float Xa[BZ * L];
    __shared__ float Xb[BZ * L];
    int tid = threadIdx.x;
    if (tid < 16) g_bar[tid] = 0;
    for (int i = tid; i < BZ * L; i += 256) Xa[i] = g_h1[i];
    __syncthreads();
    enc_layer(Xa, W1, b1, Xb, nullptr, 1, tid); __syncthreads();
    enc_layer(Xb, W2, b2, Xa, nullptr, 1, tid); __syncthreads();
    enc_layer(Xa, W3, b3, nullptr, g_z0, 0, tid);
    __threadfence();
}

// ---------------- all 9 K squarings, one kernel, software grid barrier ----------------
__global__ void kpow_fused_kernel(const float* __restrict__ K1) {
    __shared__ float rowA[L];
    int i = blockIdx.x;
    int n = threadIdx.x;
    const float* A = K1;
    for (int p = 0; p < 9; p++) {
        float* C = g_Kpow + (size_t)p * L * L;
        rowA[n] = A[i * L + n];
        __syncthreads();
        float a0 = 0.f, a1 = 0.f, a2 = 0.f, a3 = 0.f;
#pragma unroll 8
        for (int k = 0; k < L; k += 4) {
            a0 += rowA[k + 0] * A[(k + 0) * L + n];
            a1 += rowA[k + 1] * A[(k + 1) * L + n];
            a2 += rowA[k + 2] * A[(k + 2) * L + n];
            a3 += rowA[k + 3] * A[(k + 3) * L + n];
        }
        C[i * L + n] = (a0 + a1) + (a2 + a3);
        __threadfence();
        __syncthreads();
        if (threadIdx.x == 0) {
            atomicAdd(&g_bar[p], 1);
            while (atomicAdd(&g_bar[p], 0) < (int)gridDim.x) {}
            __threadfence();
        }
        __syncthreads();
        A = C;
    }
}

// ---------------- K^lo table: grid (14, 8), 16-row bands ----------------
__global__ __launch_bounds__(256)
void klo_kernel(const float* __restrict__ K1) {
    extern __shared__ float sm[];
    float* Fs = sm;              // 128*128
    float* S  = sm + L * L;      // 16*128
    float* T  = S + 16 * L;      // 16*128
    int l    = blockIdx.x + 2;
    int band = blockIdx.y;       // 0..7
    int tid  = threadIdx.x;

    const float* fac[4]; int nf = 0;
    if (l & 1) fac[nf++] = K1;
    if (l & 2) fac[nf++] = g_Kpow + 0 * L * L;   // K^2
    if (l & 4) fac[nf++] = g_Kpow + 1 * L * L;   // K^4
    if (l & 8) fac[nf++] = g_Kpow + 2 * L * L;   // K^8

    const float4* f0 = (const float4*)(fac[0] + (size_t)band * 16 * L);
#pragma unroll
    for (int i = tid; i < 16 * L / 4; i += 256) ((float4*)S)[i] = f0[i];
    __syncthreads();

    float* in = S; float* out = T;
    for (int f = 1; f < nf; f++) {
        const float4* F4 = (const float4*)fac[f];
#pragma unroll
        for (int i = tid; i < L * L / 4; i += 256) ((float4*)Fs)[i] = F4[i];
        __syncthreads();
        int n  = tid & 127;
        int r0 = (tid >> 7) * 8;
        float acc[8];
#pragma unroll
        for (int i = 0; i < 8; i++) acc[i] = 0.f;
#pragma unroll 4
        for (int k = 0; k < L; k++) {
            float w = Fs[k * L + n];
#pragma unroll
            for (int i = 0; i < 8; i++) acc[i] += in[(r0 + i) * L + k] * w;
        }
        __syncthreads();
#pragma unroll
        for (int i = 0; i < 8; i++) out[(r0 + i) * L + n] = acc[i];
        __syncthreads();
        float* tp = in; in = out; out = tp;
    }

    float* dst = g_Klo + (size_t)l * L * L + (size_t)band * 16 * L;
#pragma unroll
    for (int i = tid; i < 16 * L / 4; i += 256) ((float4*)dst)[i] = ((float4*)in)[i];
}

// ---------------- Phi[hi] = (K^16)^hi @ z0^T ----------------
__global__ __launch_bounds__(256)
void phi_kernel() {
    extern __shared__ float sm[];
    float* Ks    = sm;
    float* Zbuf0 = sm + L * L;
    float* Zbuf1 = Zbuf0 + L * BZ;
    int hi  = blockIdx.x;
    int tid = threadIdx.x;

    for (int i = tid; i < L * BZ; i += 256) {
        int l = i >> 5, b = i & 31;
        Zbuf0[i] = g_z0[b * L + l];
    }
    __syncthreads();

    float* Zin = Zbuf0; float* Zout = Zbuf1;
    int b  = tid & 31;
    int ig = tid >> 5;

    for (int j = 0; j < 6; j++) {
        if ((hi >> j) & 1) {
            const float* Kp = g_Kpow + (size_t)(3 + j) * L * L;
#pragma unroll
            for (int i = tid; i < L * L / 4; i += 256)
                ((float4*)Ks)[i] = ((const float4*)Kp)[i];
            __syncthreads();

            float acc[16];
#pragma unroll
            for (int i = 0; i < 16; i++) acc[i] = 0.f;
            for (int k4 = 0; k4 < 32; k4++) {
                float z0v = Zin[(4 * k4 + 0) * 32 + b];
                float z1v = Zin[(4 * k4 + 1) * 32 + b];
                float z2v = Zin[(4 * k4 + 2) * 32 + b];
                float z3v = Zin[(4 * k4 + 3) * 32 + b];
#pragma unroll
                for (int i = 0; i < 16; i++) {
                    float4 kr = ((const float4*)Ks)[(ig * 16 + i) * 32 + k4];
                    acc[i] += kr.x * z0v + kr.y * z1v + kr.z * z2v + kr.w * z3v;
                }
            }
#pragma unroll
            for (int i = 0; i < 16; i++)
                Zout[(ig * 16 + i) * 32 + b] = acc[i];
            __syncthreads();
            float* tp = Zin; Zin = Zout; Zout = tp;
        }
    }

    float4* dst = (float4*)(g_Phi + (size_t)hi * L * BZ);
#pragma unroll
    for (int i = tid; i < L * BZ / 4; i += 256) dst[i] = ((float4*)Zin)[i];
}

// ---------------- apply: Z_t = K^lo(t) @ Phi[hi(t)] ----------------
__global__ __launch_bounds__(256)
void apply_kernel(const float* __restrict__ K1, const int* __restrict__ idxw) {
    extern __shared__ float sm[];
    float* Ks    = sm;
    float* Zbuf0 = sm + L * L;
    float* Zbuf1 = Zbuf0 + L * BZ;
    int t   = blockIdx.x;
    int tid = threadIdx.x;

    bool is64 = ((idxw[1] | idxw[3] | idxw[5] | idxw[7] | idxw[9] | idxw[11]) == 0);
    int e = is64 ? (idxw[2 * t] - idxw[0]) : (idxw[t] - idxw[0]);
    int lo = e & 15, hi = e >> 4;

    const float4* src = (const float4*)(g_Phi + (size_t)hi * L * BZ);
#pragma unroll
    for (int i = tid; i < L * BZ / 4; i += 256) ((float4*)Zbuf0)[i] = src[i];

    float* Zres = Zbuf0;
    if (lo != 0) {
        const float* Kp = (lo == 1) ? K1 : (g_Klo + (size_t)lo * L * L);
#pragma unroll
        for (int i = tid; i < L * L / 4; i += 256)
            ((float4*)Ks)[i] = ((const float4*)Kp)[i];
        __syncthreads();

        int b  = tid & 31;
        int ig = tid >> 5;
        float acc[16];
#pragma unroll
        for (int i = 0; i < 16; i++) acc[i] = 0.f;
        for (int k4 = 0; k4 < 32; k4++) {
            float z0v = Zbuf0[(4 * k4 + 0) * 32 + b];
            float z1v = Zbuf0[(4 * k4 + 1) * 32 + b];
            float z2v = Zbuf0[(4 * k4 + 2) * 32 + b];
            float z3v = Zbuf0[(4 * k4 + 3) * 32 + b];
#pragma unroll
            for (int i = 0; i < 16; i++) {
                float4 kr = ((const float4*)Ks)[(ig * 16 + i) * 32 + k4];
                acc[i] += kr.x * z0v + kr.y * z1v + kr.z * z2v + kr.w * z3v;
            }
        }
#pragma unroll
        for (int i = 0; i < 16; i++)
            Zbuf1[(ig * 16 + i) * 32 + b] = acc[i];
        Zres = Zbuf1;
    }
    __syncthreads();

    for (int i = tid; i < L * BZ; i += 256) {
        int bb = i >> 7, l = i & 127;
        g_Z[((size_t)t * BZ + bb) * L + l] = Zres[l * 32 + bb];
    }
}

// ---------------- W transpose + fp16 convert: Wd3 [128,4096] -> g_Wh [4096,128] ----------------
__global__ void cvtW_kernel(const float* __restrict__ W) {
    __shared__ float tile[128][33];
    int n0 = blockIdx.x * 32;
    int tx = threadIdx.x & 31, ty = threadIdx.x >> 5;
    for (int k = ty; k < 128; k += 8)
        tile[k][tx] = W[(size_t)k * DD + n0 + tx];
    __syncthreads();
    int n  = n0 + (threadIdx.x >> 3);
    int k0 = (threadIdx.x & 7) * 16;
    int c  = n - n0;
    __half2 h[8];
#pragma unroll
    for (int j = 0; j < 8; j++)
        h[j] = __floats2half2_rn(tile[k0 + 2 * j][c], tile[k0 + 2 * j + 1][c]);
    uint4* dh = (uint4*)(g_Wh + (size_t)n * L + k0);
    dh[0] = ((uint4*)h)[0];
    dh[1] = ((uint4*)h)[1];
}

// ---------------- hidden dense: 64-row tiles ----------------
__global__ __launch_bounds__(256)
void dense64_kernel(const float* __restrict__ X, const float* __restrict__ W,
                    const float* __restrict__ bias, float* __restrict__ outf,
                    int mode) {
    extern __shared__ float sm[];
    float* Xs = sm;            // 64*128
    float* Ws = sm + 64 * L;   // 128*128
    int tid = threadIdx.x;
    int bm0 = blockIdx.x * 64;

    const float4* X4 = (const float4*)X + (size_t)bm0 * 32;
    float4* Xs4 = (float4*)Xs;
    float4* Ws4 = (float4*)Ws;
    const float4* W4 = (const float4*)W;
#pragma unroll
    for (int i = tid; i < 64 * L / 4; i += 256) Xs4[i] = X4[i];
#pragma unroll
    for (int i = tid; i < L * L / 4; i += 256) Ws4[i] = W4[i];
    __syncthreads();

    int tx = tid & 31;
    int ty = tid >> 5;
    int r0 = ty * 8;

    float acc[8][4];
#pragma unroll
    for (int i = 0; i < 8; i++)
#pragma unroll
        for (int j = 0; j < 4; j++) acc[i][j] = 0.f;

    for (int k4 = 0; k4 < 32; k4++) {
        float4 b0 = Ws4[(4 * k4 + 0) * 32 + tx];
        float4 b1 = Ws4[(4 * k4 + 1) * 32 + tx];
        float4 b2 = Ws4[(4 * k4 + 2) * 32 + tx];
        float4 b3 = Ws4[(4 * k4 + 3) * 32 + tx];
#pragma unroll
        for (int i = 0; i < 8; i++) {
            float4 a = Xs4[(r0 + i) * 32 + k4];
            acc[i][0] += a.x * b0.x + a.y * b1.x + a.z * b2.x + a.w * b3.x;
            acc[i][1] += a.x * b0.y + a.y * b1.y + a.z * b2.y + a.w * b3.y;
            acc[i][2] += a.x * b0.z + a.y * b1.z + a.z * b2.z + a.w * b3.z;
            acc[i][3] += a.x * b0.w + a.y * b1.w + a.z * b2.w + a.w * b3.w;
        }
    }

    float4 bb = ((const float4*)bias)[tx];
#pragma unroll
    for (int i = 0; i < 8; i++) {
        float4 v;
        v.x = fmaxf(acc[i][0] + bb.x, 0.f);
        v.y = fmaxf(acc[i][1] + bb.y, 0.f);
        v.z = fmaxf(acc[i][2] + bb.z, 0.f);
        v.w = fmaxf(acc[i][3] + bb.w, 0.f);
        size_t row = (size_t)(bm0 + r0 + i);
        if (mode == 0) {
            ((float4*)outf)[row * 32 + tx] = v;
        } else {
            __half2 h01 = __floats2half2_rn(v.x, v.y);
            __half2 h23 = __floats2half2_rn(v.z, v.w);
            uint2 pk; pk.x = *(uint32_t*)&h01; pk.y = *(uint32_t*)&h23;
            *(uint2*)(g_Ah + row * L + tx * 4) = pk;
        }
    }
}

// ================= persistent final GEMM: single-pass fp16 mma.sync + cp.async =================
#define SPE 136                         // padded row stride (272 B; 17*16B -> ldmatrix conflict-free)
#define TILE_BYTES (128 * SPE * 2)      // 34816 B
#define OFF_B   0
#define OFF_A0  TILE_BYTES
#define OFF_A1  (2 * TILE_BYTES)
#define FSM_BYTES (3 * TILE_BYTES)      // 104448 B -> 2 CTAs/SM

__device__ __forceinline__ uint32_t smem_u32(const void* p) {
    uint32_t a;
    asm("{ .reg .u64 t; cvta.to.shared.u64 t, %1; cvt.u32.u64 %0, t; }" : "=r"(a) : "l"(p));
    return a;
}
__device__ __forceinline__ void cpasync16(uint32_t dst, const void* src) {
    asm volatile("cp.async.cg.shared.global [%0], [%1], 16;" :: "r"(dst), "l"(src));
}
__device__ __forceinline__ void cp_commit() {
    asm volatile("cp.async.commit_group;" ::: "memory");
}
__device__ __forceinline__ void cp_wait1() {
    asm volatile("cp.async.wait_group 1;" ::: "memory");
}
__device__ __forceinline__ void cp_wait0() {
    asm volatile("cp.async.wait_group 0;" ::: "memory");
}
__device__ __forceinline__ void ldmx4(uint32_t* r, uint32_t addr) {
    asm volatile("ldmatrix.sync.aligned.m8n8.x4.shared.b16 {%0,%1,%2,%3}, [%4];"
                 : "=r"(r[0]), "=r"(r[1]), "=r"(r[2]), "=r"(r[3]) : "r"(addr));
}
__device__ __forceinline__ void ldmx2(uint32_t* r, uint32_t addr) {
    asm volatile("ldmatrix.sync.aligned.m8n8.x2.shared.b16 {%0,%1}, [%2];"
                 : "=r"(r[0]), "=r"(r[1]) : "r"(addr));
}
__device__ __forceinline__ void mma16816h(float* c, const uint32_t* a, const uint32_t* b) {
    asm volatile(
        "mma.sync.aligned.m16n8k16.row.col.f32.f16.f16.f32 "
        "{%0,%1,%2,%3}, {%4,%5,%6,%7}, {%8,%9}, {%0,%1,%2,%3};"
        : "+f"(c[0]), "+f"(c[1]), "+f"(c[2]), "+f"(c[3])
        : "r"(a[0]), "r"(a[1]), "r"(a[2]), "r"(a[3]), "r"(b[0]), "r"(b[1]));
}

__device__ __forceinline__ void issue_A(uint32_t sbase, int bm0, int tid) {
    const uint4* GA = (const uint4*)g_Ah;
#pragma unroll
    for (int t = tid; t < 2048; t += 256) {
        int r = t >> 4, q = t & 15;
        cpasync16(sbase + (uint32_t)(r * (SPE * 2) + q * 16),
                  GA + (size_t)(bm0 + r) * 16 + q);
    }
}

__global__ __launch_bounds__(256, 2)
void final_mma_kernel(const float* __restrict__ bias, float* __restrict__ out) {
    extern __shared__ __align__(16) char smf[];
    uint32_t sbase = smem_u32(smf);
    int tid  = threadIdx.x;
    int wid  = tid >> 5, lane = tid & 31;
    int bn0  = blockIdx.x * 128;

    // B tile (fp16 weights) via cp.async — group 0
    const uint4* GW = (const uint4*)g_Wh;
#pragma unroll
    for (int t = tid; t < 2048; t += 256) {
        int r = t >> 4, q = t & 15;
        cpasync16(sbase + OFF_B + (uint32_t)(r * (SPE * 2) + q * 16),
                  GW + (size_t)(bn0 + r) * 16 + q);
    }
    cp_commit();

    // A stage 0 — group 1
    issue_A(sbase + OFF_A0, blockIdx.y * 128, tid);
    cp_commit();

    int wm = wid >> 2, wn = wid & 3;

    uint32_t a_off[4], b_off[4];
#pragma unroll
    for (int mi = 0; mi < 4; mi++) {
        int row = wm * 64 + mi * 16 + (lane & 15);
        a_off[mi] = (uint32_t)(row * SPE * 2) + ((lane >> 4) << 4);
    }
#pragma unroll
    for (int ni = 0; ni < 4; ni++) {
        int row = wn * 32 + ni * 8 + (lane & 7);
        b_off[ni] = (uint32_t)(row * SPE * 2) + (((lane >> 3) & 1) << 4);
    }
    uint32_t sB = sbase + OFF_B;

    int g  = lane >> 2;
    int cc = (lane & 3) * 2;
    float2 br[4];
#pragma unroll
    for (int ni = 0; ni < 4; ni++) {
        int col = bn0 + wn * 32 + ni * 8 + cc;
        br[ni] = make_float2(bias[col], bias[col + 1]);
    }

    const int NT = 16;   // m-tiles per CTA (grid.y = 8)
    for (int it = 0; it < NT; it++) {
        int bm0 = (blockIdx.y + 8 * it) * 128;
        if (it + 1 < NT) {
            issue_A(sbase + ((it + 1) & 1 ? OFF_A1 : OFF_A0),
                    (blockIdx.y + 8 * (it + 1)) * 128, tid);
            cp_commit();
            cp_wait1();
        } else {
            cp_wait0();
        }
        __syncthreads();

        uint32_t sA = sbase + ((it & 1) ? OFF_A1 : OFF_A0);
        float c[4][4][4];
#pragma unroll
        for (int mi = 0; mi < 4; mi++)
#pragma unroll
            for (int ni = 0; ni < 4; ni++)
#pragma unroll
                for (int j = 0; j < 4; j++) c[mi][ni][j] = 0.f;

#pragma unroll
        for (int k0 = 0; k0 < 8; k0++) {
            uint32_t koff = (uint32_t)(k0 * 32);
            uint32_t a[4][4], b[4][2];
#pragma unroll
            for (int mi = 0; mi < 4; mi++) ldmx4(a[mi], sA + a_off[mi] + koff);
#pragma unroll
            for (int ni = 0; ni < 4; ni++) ldmx2(b[ni], sB + b_off[ni] + koff);
#pragma unroll
            for (int mi = 0; mi < 4; mi++)
#pragma unroll
                for (int ni = 0; ni < 4; ni++)
                    mma16816h(c[mi][ni], a[mi], b[ni]);
        }

#pragma unroll
        for (int ni = 0; ni < 4; ni++) {
            int col = bn0 + wn * 32 + ni * 8 + cc;
#pragma unroll
            for (int mi = 0; mi < 4; mi++) {
                size_t row = (size_t)(bm0 + wm * 64 + mi * 16 + g);
                float2 v0 = make_float2(c[mi][ni][0] + br[ni].x, c[mi][ni][1] + br[ni].y);
                float2 v1 = make_float2(c[mi][ni][2] + br[ni].x, c[mi][ni][3] + br[ni].y);
                *(float2*)(out + row * DD + col)       = v0;
                *(float2*)(out + (row + 8) * DD + col) = v1;
            }
        }
        __syncthreads();
    }
}

// ---------------- launch ----------------
extern "C" void kernel_launch(void* const* d_in, const int* in_sizes, int n_in,
                              void* d_out, int out_size) {
    const float* x0  = (const float*)d_in[0];
    const int*   idx = (const int*)  d_in[1];
    const float* K   = (const float*)d_in[2];
    const float* We0 = (const float*)d_in[3];
    const float* be0 = (const float*)d_in[4];
    const float* We1 = (const float*)d_in[5];
    const float* be1 = (const float*)d_in[6];
    const float* We2 = (const float*)d_in[7];
    const float* be2 = (const float*)d_in[8];
    const float* We3 = (const float*)d_in[9];
    const float* be3 = (const float*)d_in[10];
    const float* Wd0 = (const float*)d_in[11];
    const float* bd0 = (const float*)d_in[12];
    const float* Wd1 = (const float*)d_in[13];
    const float* bd1 = (const float*)d_in[14];
    const float* Wd2 = (const float*)d_in[15];
    const float* bd2 = (const float*)d_in[16];
    const float* Wd3 = (const float*)d_in[17];
    const float* bd3 = (const float*)d_in[18];
    float* out = (float*)d_out;

    const int smem_koop  = (L * L + 2 * L * BZ) * 4;       // 96 KB (phi/apply)
    const int smem_klo   = (L * L + 2 * 16 * L) * 4;       // 80 KB
    const int smem_dense = (64 * L + L * L) * 4;           // 96 KB
    const int smem_final = FSM_BYTES;                      // ~102 KB
    cudaFuncSetAttribute(klo_kernel,       cudaFuncAttributeMaxDynamicSharedMemorySize, smem_klo);
    cudaFuncSetAttribute(phi_kernel,       cudaFuncAttributeMaxDynamicSharedMemorySize, smem_koop);
    cudaFuncSetAttribute(apply_kernel,     cudaFuncAttributeMaxDynamicSharedMemorySize, smem_koop);
    cudaFuncSetAttribute(dense64_kernel,   cudaFuncAttributeMaxDynamicSharedMemorySize, smem_dense);
    cudaFuncSetAttribute(final_mma_kernel, cudaFuncAttributeMaxDynamicSharedMemorySize, smem_final);

    float *pZ, *pT1, *pT2;
    cudaGetSymbolAddress((void**)&pZ,  g_Z);
    cudaGetSymbolAddress((void**)&pT1, g_T1);
    cudaGetSymbolAddress((void**)&pT2, g_T2);

    // Encoder (enc_tail also resets the kpow grid barrier)
    enc0_kernel<<<BZ, 128>>>(x0, We0, be0);
    enc_tail_kernel<<<1, 256>>>(We1, be1, We2, be2, We3, be3);

    // K^2..K^512
    kpow_fused_kernel<<<128, 128>>>(K);

    // K^lo table (lo = 2..15)
    klo_kernel<<<dim3(14, 8), 256, smem_klo>>>(K);

    // Phi[hi] = (K^16)^hi @ z0^T
    phi_kernel<<<64, 256, smem_koop>>>();

    // Z_t = K^lo(t) @ Phi[hi(t)]
    apply_kernel<<<TT, 256, smem_koop>>>(K, idx);

    // Wd3 transpose + fp16 convert
    cvtW_kernel<<<DD / 32, 256>>>(Wd3);

    // Decoder hidden layers (last emits fp16 activations)
    dense64_kernel<<<MT / 64, 256, smem_dense>>>(pZ,  Wd0, bd0, pT1, 0);
    dense64_kernel<<<MT / 64, 256, smem_dense>>>(pT1, Wd1, bd1, pT2, 0);
    dense64_kernel<<<MT / 64, 256, smem_dense>>>(pT2, Wd2, bd2, nullptr, 2);

    // Final projection: single-pass fp16 tensor-core GEMM, 2 CTAs/SM
    dim3 fgrid(DD / 128, 8);
    final_mma_kernel<<<fgrid, 256, smem_final>>>(bd3, out);
}

// round 7
// speedup vs baseline: 2.3380x; 1.3912x over previous
#include <cuda_runtime.h>
#include <cuda_fp16.h>
#include <stdint.h>

#define L   128
#define BZ  32
#define TT  512
#define DD  4096
#define MT  (TT*BZ)   // 16384 decoder rows

// ---------------- scratch (device globals; no allocation) ----------------
__device__ float g_h1p[8 * BZ * L];          // enc0 split-K partials [chunk][row][n]
__device__ float g_z0[BZ * L];
__device__ float g_Kpow[9 * L * L];          // K^2, K^4, ..., K^512
__device__ float g_Klo[16 * L * L];          // K^lo, lo in [0,16)
__device__ float g_Phi[64 * L * BZ];         // Phi[hi] = (K^16)^hi @ z0^T, [hi][l][b]
__device__ float g_Z [MT * L];
__device__ __half g_Ah[MT * L];              // last hidden activations, fp16
__device__ __half g_Wh[DD * L];              // Wd3 transposed [n][k], fp16
__device__ int g_bar[16];                    // monotonic ticket barriers (never reset)

// ticket grid barrier: works across graph replays without zeroing
__device__ __forceinline__ void gridbar(int* ctr, int n) {
    __threadfence();
    __syncthreads();
    if (threadIdx.x == 0) {
        int t = atomicAdd(ctr, 1);
        int target = (t / n + 1) * n;
        while (*(volatile int*)ctr < target) {}
        __threadfence();
    }
    __syncthreads();
}

// ---------------- encoder fused: split-K layer0 (256 CTAs) + tail (CTA 0) ----------------
__device__ __forceinline__ void tail_layer128(const float* X, const float* __restrict__ W,
                                              const float* __restrict__ b,
                                              float* Xout, float* gout, int relu, int n) {
    float acc[32];
#pragma unroll
    for (int r = 0; r < 32; r++) acc[r] = 0.f;
#pragma unroll 4
    for (int k = 0; k < L; k++) {
        float w = W[k * L + n];
#pragma unroll
        for (int r = 0; r < 32; r++) acc[r] += X[r * L + k] * w;
    }
    float bn = b[n];
#pragma unroll
    for (int r = 0; r < 32; r++) {
        float v = acc[r] + bn;
        if (relu) v = fmaxf(v, 0.f);
        if (Xout) Xout[r * L + n] = v;
        else      gout[r * L + n] = v;
    }
}

__global__ void encA_kernel(const float* __restrict__ x0,
                            const float* __restrict__ W0, const float* __restrict__ b0,
                            const float* __restrict__ W1, const float* __restrict__ b1,
                            const float* __restrict__ W2, const float* __restrict__ b2,
                            const float* __restrict__ W3, const float* __restrict__ b3) {
    __shared__ float xs[512];
    __shared__ float Xa[BZ * L];
    __shared__ float Xb[BZ * L];
    int cb  = blockIdx.x;          // 0..255
    int row = cb >> 3, c = cb & 7;
    int n   = threadIdx.x;         // 0..127

    // phase 1: partial dot over K-chunk c
    ((float4*)xs)[n] = ((const float4*)(x0 + (size_t)row * DD + c * 512))[n];
    __syncthreads();
    float a0 = 0.f, a1 = 0.f, a2 = 0.f, a3 = 0.f;
    const float* Wc = W0 + (size_t)(c * 512) * L;
#pragma unroll 8
    for (int k = 0; k < 512; k += 4) {
        a0 += xs[k + 0] * Wc[(size_t)(k + 0) * L + n];
        a1 += xs[k + 1] * Wc[(size_t)(k + 1) * L + n];
        a2 += xs[k + 2] * Wc[(size_t)(k + 2) * L + n];
        a3 += xs[k + 3] * Wc[(size_t)(k + 3) * L + n];
    }
    g_h1p[(c * BZ + row) * L + n] = (a0 + a1) + (a2 + a3);

    gridbar(&g_bar[0], 256);
    if (blockIdx.x != 0) return;

    // tail on CTA 0: reduce partials, then 3 dense layers
#pragma unroll
    for (int r = 0; r < 32; r++) {
        float s = 0.f;
#pragma unroll
        for (int c2 = 0; c2 < 8; c2++) s += g_h1p[(c2 * BZ + r) * L + n];
        Xa[r * L + n] = fmaxf(s + b0[n], 0.f);
    }
    __syncthreads();
    tail_layer128(Xa, W1, b1, Xb, nullptr, 1, n); __syncthreads();
    tail_layer128(Xb, W2, b2, Xa, nullptr, 1, n); __syncthreads();
    tail_layer128(Xa, W3, b3, nullptr, g_z0, 0, n);
}

// ---------------- all 9 K squarings, ticket barriers, volatile poll ----------------
__global__ void kpow_fused_kernel(const float* __restrict__ K1) {
    __shared__ float rowA[L];
    int i = blockIdx.x;
    int n = threadIdx.x;
    const float* A = K1;
    for (int p = 0; p < 9; p++) {
        float* C = g_Kpow + (size_t)p * L * L;
        rowA[n] = A[i * L + n];
        __syncthreads();
        float a0 = 0.f, a1 = 0.f, a2 = 0.f, a3 = 0.f;
#pragma unroll 8
        for (int k = 0; k < L; k += 4) {
            a0 += rowA[k + 0] * A[(k + 0) * L + n];
            a1 += rowA[k + 1] * A[(k + 1) * L + n];
            a2 += rowA[k + 2] * A[(k + 2) * L + n];
            a3 += rowA[k + 3] * A[(k + 3) * L + n];
        }
        C[i * L + n] = (a0 + a1) + (a2 + a3);
        gridbar(&g_bar[1 + p], 128);
        A = C;
    }
}

// ---------------- fused klo (CTAs 64..175) || phi (CTAs 0..63) ----------------
__global__ __launch_bounds__(256)
void kloPhi_kernel(const float* __restrict__ K1) {
    extern __shared__ float sm[];
    int tid = threadIdx.x;

    if (blockIdx.x < 64) {
        // ---- phi: Phi[hi] = (K^16)^hi @ z0^T ----
        float* Ks    = sm;
        float* Zbuf0 = sm + L * L;
        float* Zbuf1 = Zbuf0 + L * BZ;
        int hi = blockIdx.x;

        for (int i = tid; i < L * BZ; i += 256) {
            int l = i >> 5, b = i & 31;
            Zbuf0[i] = g_z0[b * L + l];
        }
        __syncthreads();

        float* Zin = Zbuf0; float* Zout = Zbuf1;
        int b  = tid & 31;
        int ig = tid >> 5;

        for (int j = 0; j < 6; j++) {
            if ((hi >> j) & 1) {
                const float* Kp = g_Kpow + (size_t)(3 + j) * L * L;
#pragma unroll
                for (int i = tid; i < L * L / 4; i += 256)
                    ((float4*)Ks)[i] = ((const float4*)Kp)[i];
                __syncthreads();

                float acc[16];
#pragma unroll
                for (int i = 0; i < 16; i++) acc[i] = 0.f;
                for (int k4 = 0; k4 < 32; k4++) {
                    float z0v = Zin[(4 * k4 + 0) * 32 + b];
                    float z1v = Zin[(4 * k4 + 1) * 32 + b];
                    float z2v = Zin[(4 * k4 + 2) * 32 + b];
                    float z3v = Zin[(4 * k4 + 3) * 32 + b];
#pragma unroll
                    for (int i = 0; i < 16; i++) {
                        float4 kr = ((const float4*)Ks)[(ig * 16 + i) * 32 + k4];
                        acc[i] += kr.x * z0v + kr.y * z1v + kr.z * z2v + kr.w * z3v;
                    }
                }
#pragma unroll
                for (int i = 0; i < 16; i++)
                    Zout[(ig * 16 + i) * 32 + b] = acc[i];
                __syncthreads();
                float* tp = Zin; Zin = Zout; Zout = tp;
            }
        }
        float4* dst = (float4*)(g_Phi + (size_t)hi * L * BZ);
#pragma unroll
        for (int i = tid; i < L * BZ / 4; i += 256) dst[i] = ((float4*)Zin)[i];
    } else {
        // ---- klo: K^l, l in [2,16), 16-row band per CTA ----
        float* Fs = sm;              // 128*128
        float* S  = sm + L * L;      // 16*128
        float* T  = S + 16 * L;      // 16*128
        int u    = blockIdx.x - 64;  // 0..111
        int l    = (u >> 3) + 2;
        int band = u & 7;

        const float* fac[4]; int nf = 0;
        if (l & 1) fac[nf++] = K1;
        if (l & 2) fac[nf++] = g_Kpow + 0 * L * L;
        if (l & 4) fac[nf++] = g_Kpow + 1 * L * L;
        if (l & 8) fac[nf++] = g_Kpow + 2 * L * L;

        const float4* f0 = (const float4*)(fac[0] + (size_t)band * 16 * L);
#pragma unroll
        for (int i = tid; i < 16 * L / 4; i += 256) ((float4*)S)[i] = f0[i];
        __syncthreads();

        float* in = S; float* out = T;
        for (int f = 1; f < nf; f++) {
            const float4* F4 = (const float4*)fac[f];
#pragma unroll
            for (int i = tid; i < L * L / 4; i += 256) ((float4*)Fs)[i] = F4[i];
            __syncthreads();
            int n  = tid & 127;
            int r0 = (tid >> 7) * 8;
            float acc[8];
#pragma unroll
            for (int i = 0; i < 8; i++) acc[i] = 0.f;
#pragma unroll 4
            for (int k = 0; k < L; k++) {
                float w = Fs[k * L + n];
#pragma unroll
                for (int i = 0; i < 8; i++) acc[i] += in[(r0 + i) * L + k] * w;
            }
            __syncthreads();
#pragma unroll
            for (int i = 0; i < 8; i++) out[(r0 + i) * L + n] = acc[i];
            __syncthreads();
            float* tp = in; in = out; out = tp;
        }
        float* dst = g_Klo + (size_t)l * L * L + (size_t)band * 16 * L;
#pragma unroll
        for (int i = tid; i < 16 * L / 4; i += 256) ((float4*)dst)[i] = ((float4*)in)[i];
    }
}

// ---------------- apply: Z_t = K^lo(t) @ Phi[hi(t)] ----------------
__global__ __launch_bounds__(256)
void apply_kernel(const float* __restrict__ K1, const int* __restrict__ idxw) {
    extern __shared__ float sm[];
    float* Ks    = sm;
    float* Zbuf0 = sm + L * L;
    float* Zbuf1 = Zbuf0 + L * BZ;
    int t   = blockIdx.x;
    int tid = threadIdx.x;

    bool is64 = ((idxw[1] | idxw[3] | idxw[5] | idxw[7] | idxw[9] | idxw[11]) == 0);
    int e = is64 ? (idxw[2 * t] - idxw[0]) : (idxw[t] - idxw[0]);
    int lo = e & 15, hi = e >> 4;

    const float4* src = (const float4*)(g_Phi + (size_t)hi * L * BZ);
#pragma unroll
    for (int i = tid; i < L * BZ / 4; i += 256) ((float4*)Zbuf0)[i] = src[i];

    float* Zres = Zbuf0;
    if (lo != 0) {
        const float* Kp = (lo == 1) ? K1 : (g_Klo + (size_t)lo * L * L);
#pragma unroll
        for (int i = tid; i < L * L / 4; i += 256)
            ((float4*)Ks)[i] = ((const float4*)Kp)[i];
        __syncthreads();

        int b  = tid & 31;
        int ig = tid >> 5;
        float acc[16];
#pragma unroll
        for (int i = 0; i < 16; i++) acc[i] = 0.f;
        for (int k4 = 0; k4 < 32; k4++) {
            float z0v = Zbuf0[(4 * k4 + 0) * 32 + b];
            float z1v = Zbuf0[(4 * k4 + 1) * 32 + b];
            float z2v = Zbuf0[(4 * k4 + 2) * 32 + b];
            float z3v = Zbuf0[(4 * k4 + 3) * 32 + b];
#pragma unroll
            for (int i = 0; i < 16; i++) {
                float4 kr = ((const float4*)Ks)[(ig * 16 + i) * 32 + k4];
                acc[i] += kr.x * z0v + kr.y * z1v + kr.z * z2v + kr.w * z3v;
            }
        }
#pragma unroll
        for (int i = 0; i < 16; i++)
            Zbuf1[(ig * 16 + i) * 32 + b] = acc[i];
        Zres = Zbuf1;
    }
    __syncthreads();

    for (int i = tid; i < L * BZ; i += 256) {
        int bb = i >> 7, l = i & 127;
        g_Z[((size_t)t * BZ + bb) * L + l] = Zres[l * 32 + bb];
    }
}

// ---------------- W transpose + fp16 convert ----------------
__global__ void cvtW_kernel(const float* __restrict__ W) {
    __shared__ float tile[128][33];
    int n0 = blockIdx.x * 32;
    int tx = threadIdx.x & 31, ty = threadIdx.x >> 5;
    for (int k = ty; k < 128; k += 8)
        tile[k][tx] = W[(size_t)k * DD + n0 + tx];
    __syncthreads();
    int n  = n0 + (threadIdx.x >> 3);
    int k0 = (threadIdx.x & 7) * 16;
    int c  = n - n0;
    __half2 h[8];
#pragma unroll
    for (int j = 0; j < 8; j++)
        h[j] = __floats2half2_rn(tile[k0 + 2 * j][c], tile[k0 + 2 * j + 1][c]);
    uint4* dh = (uint4*)(g_Wh + (size_t)n * L + k0);
    dh[0] = ((uint4*)h)[0];
    dh[1] = ((uint4*)h)[1];
}

// ---------------- fused decoder hiddens: 3 layers, row-local, one kernel ----------------
__global__ __launch_bounds__(256)
void denseF_kernel(const float* __restrict__ W0, const float* __restrict__ b0,
                   const float* __restrict__ W1, const float* __restrict__ b1,
                   const float* __restrict__ W2, const float* __restrict__ b2) {
    extern __shared__ float sm[];
    float* Xs = sm;            // 64*128
    float* Ws = sm + 64 * L;   // 128*128
    int tid = threadIdx.x;
    int bm0 = blockIdx.x * 64;

    float4* Xs4 = (float4*)Xs;
    float4* Ws4 = (float4*)Ws;
    const float4* X4 = (const float4*)g_Z + (size_t)bm0 * 32;
#pragma unroll
    for (int i = tid; i < 64 * L / 4; i += 256) Xs4[i] = X4[i];

    int tx = tid & 31;
    int ty = tid >> 5;
    int r0 = ty * 8;

    const float* Wl[3] = {W0, W1, W2};
    const float* bl[3] = {b0, b1, b2};

#pragma unroll
    for (int layer = 0; layer < 3; layer++) {
        const float4* W4 = (const float4*)Wl[layer];
#pragma unroll
        for (int i = tid; i < L * L / 4; i += 256) Ws4[i] = W4[i];
        __syncthreads();   // Ws ready; also publishes previous Xs writes / initial load

        float acc[8][4];
#pragma unroll
        for (int i = 0; i < 8; i++)
#pragma unroll
            for (int j = 0; j < 4; j++) acc[i][j] = 0.f;

        for (int k4 = 0; k4 < 32; k4++) {
            float4 c0 = Ws4[(4 * k4 + 0) * 32 + tx];
            float4 c1 = Ws4[(4 * k4 + 1) * 32 + tx];
            float4 c2 = Ws4[(4 * k4 + 2) * 32 + tx];
            float4 c3 = Ws4[(4 * k4 + 3) * 32 + tx];
#pragma unroll
            for (int i = 0; i < 8; i++) {
                float4 a = Xs4[(r0 + i) * 32 + k4];
                acc[i][0] += a.x * c0.x + a.y * c1.x + a.z * c2.x + a.w * c3.x;
                acc[i][1] += a.x * c0.y + a.y * c1.y + a.z * c2.y + a.w * c3.y;
                acc[i][2] += a.x * c0.z + a.y * c1.z + a.z * c2.z + a.w * c3.z;
                acc[i][3] += a.x * c0.w + a.y * c1.w + a.z * c2.w + a.w * c3.w;
            }
        }
        __syncthreads();   // all Xs reads done before overwrite

        float4 bb = ((const float4*)bl[layer])[tx];
        if (layer < 2) {
#pragma unroll
            for (int i = 0; i < 8; i++) {
                float4 v;
                v.x = fmaxf(acc[i][0] + bb.x, 0.f);
                v.y = fmaxf(acc[i][1] + bb.y, 0.f);
                v.z = fmaxf(acc[i][2] + bb.z, 0.f);
                v.w = fmaxf(acc[i][3] + bb.w, 0.f);
                Xs4[(r0 + i) * 32 + tx] = v;
            }
        } else {
#pragma unroll
            for (int i = 0; i < 8; i++) {
                float vx = fmaxf(acc[i][0] + bb.x, 0.f);
                float vy = fmaxf(acc[i][1] + bb.y, 0.f);
                float vz = fmaxf(acc[i][2] + bb.z, 0.f);
                float vw = fmaxf(acc[i][3] + bb.w, 0.f);
                __half2 h01 = __floats2half2_rn(vx, vy);
                __half2 h23 = __floats2half2_rn(vz, vw);
                uint2 pk; pk.x = *(uint32_t*)&h01; pk.y = *(uint32_t*)&h23;
                *(uint2*)(g_Ah + (size_t)(bm0 + r0 + i) * L + tx * 4) = pk;
            }
        }
    }
}

// ================= persistent final GEMM: single-pass fp16 mma.sync + cp.async =================
#define SPE 136
#define TILE_BYTES (128 * SPE * 2)
#define OFF_B   0
#define OFF_A0  TILE_BYTES
#define OFF_A1  (2 * TILE_BYTES)
#define FSM_BYTES (3 * TILE_BYTES)      // 104448 B -> 2 CTAs/SM

__device__ __forceinline__ uint32_t smem_u32(const void* p) {
    uint32_t a;
    asm("{ .reg .u64 t; cvta.to.shared.u64 t, %1; cvt.u32.u64 %0, t; }" : "=r"(a) : "l"(p));
    return a;
}
__device__ __forceinline__ void cpasync16(uint32_t dst, const void* src) {
    asm volatile("cp.async.cg.shared.global [%0], [%1], 16;" :: "r"(dst), "l"(src));
}
__device__ __forceinline__ void cp_commit() {
    asm volatile("cp.async.commit_group;" ::: "memory");
}
__device__ __forceinline__ void cp_wait1() {
    asm volatile("cp.async.wait_group 1;" ::: "memory");
}
__device__ __forceinline__ void cp_wait0() {
    asm volatile("cp.async.wait_group 0;" ::: "memory");
}
__device__ __forceinline__ void ldmx4(uint32_t* r, uint32_t addr) {
    asm volatile("ldmatrix.sync.aligned.m8n8.x4.shared.b16 {%0,%1,%2,%3}, [%4];"
                 : "=r"(r[0]), "=r"(r[1]), "=r"(r[2]), "=r"(r[3]) : "r"(addr));
}
__device__ __forceinline__ void ldmx2(uint32_t* r, uint32_t addr) {
    asm volatile("ldmatrix.sync.aligned.m8n8.x2.shared.b16 {%0,%1}, [%2];"
                 : "=r"(r[0]), "=r"(r[1]) : "r"(addr));
}
__device__ __forceinline__ void mma16816h(float* c, const uint32_t* a, const uint32_t* b) {
    asm volatile(
        "mma.sync.aligned.m16n8k16.row.col.f32.f16.f16.f32 "
        "{%0,%1,%2,%3}, {%4,%5,%6,%7}, {%8,%9}, {%0,%1,%2,%3};"
        : "+f"(c[0]), "+f"(c[1]), "+f"(c[2]), "+f"(c[3])
        : "r"(a[0]), "r"(a[1]), "r"(a[2]), "r"(a[3]), "r"(b[0]), "r"(b[1]));
}

__device__ __forceinline__ void issue_A(uint32_t sbase, int bm0, int tid) {
    const uint4* GA = (const uint4*)g_Ah;
#pragma unroll
    for (int t = tid; t < 2048; t += 256) {
        int r = t >> 4, q = t & 15;
        cpasync16(sbase + (uint32_t)(r * (SPE * 2) + q * 16),
                  GA + (size_t)(bm0 + r) * 16 + q);
    }
}

__global__ __launch_bounds__(256, 2)
void final_mma_kernel(const float* __restrict__ bias, float* __restrict__ out) {
    extern __shared__ __align__(16) char smf[];
    uint32_t sbase = smem_u32(smf);
    int tid  = threadIdx.x;
    int wid  = tid >> 5, lane = tid & 31;
    int bn0  = blockIdx.x * 128;

    const uint4* GW = (const uint4*)g_Wh;
#pragma unroll
    for (int t = tid; t < 2048; t += 256) {
        int r = t >> 4, q = t & 15;
        cpasync16(sbase + OFF_B + (uint32_t)(r * (SPE * 2) + q * 16),
                  GW + (size_t)(bn0 + r) * 16 + q);
    }
    cp_commit();

    issue_A(sbase + OFF_A0, blockIdx.y * 128, tid);
    cp_commit();

    int wm = wid >> 2, wn = wid & 3;

    uint32_t a_off[4], b_off[4];
#pragma unroll
    for (int mi = 0; mi < 4; mi++) {
        int row = wm * 64 + mi * 16 + (lane & 15);
        a_off[mi] = (uint32_t)(row * SPE * 2) + ((lane >> 4) << 4);
    }
#pragma unroll
    for (int ni = 0; ni < 4; ni++) {
        int row = wn * 32 + ni * 8 + (lane & 7);
        b_off[ni] = (uint32_t)(row * SPE * 2) + (((lane >> 3) & 1) << 4);
    }
    uint32_t sB = sbase + OFF_B;

    int g  = lane >> 2;
    int cc = (lane & 3) * 2;
    float2 br[4];
#pragma unroll
    for (int ni = 0; ni < 4; ni++) {
        int col = bn0 + wn * 32 + ni * 8 + cc;
        br[ni] = make_float2(bias[col], bias[col + 1]);
    }

    const int NT = 16;
    for (int it = 0; it < NT; it++) {
        int bm0 = (blockIdx.y + 8 * it) * 128;
        if (it + 1 < NT) {
            issue_A(sbase + ((it + 1) & 1 ? OFF_A1 : OFF_A0),
                    (blockIdx.y + 8 * (it + 1)) * 128, tid);
            cp_commit();
            cp_wait1();
        } else {
            cp_wait0();
        }
        __syncthreads();

        uint32_t sA = sbase + ((it & 1) ? OFF_A1 : OFF_A0);
        float c[4][4][4];
#pragma unroll
        for (int mi = 0; mi < 4; mi++)
#pragma unroll
            for (int ni = 0; ni < 4; ni++)
#pragma unroll
                for (int j = 0; j < 4; j++) c[mi][ni][j] = 0.f;

#pragma unroll
        for (int k0 = 0; k0 < 8; k0++) {
            uint32_t koff = (uint32_t)(k0 * 32);
            uint32_t b[4][2];
#pragma unroll
            for (int ni = 0; ni < 4; ni++) ldmx2(b[ni], sB + b_off[ni] + koff);
#pragma unroll
            for (int mi = 0; mi < 4; mi++) {
                uint32_t a[4];
                ldmx4(a, sA + a_off[mi] + koff);
#pragma unroll
                for (int ni = 0; ni < 4; ni++)
                    mma16816h(c[mi][ni], a, b[ni]);
            }
        }

#pragma unroll
        for (int ni = 0; ni < 4; ni++) {
            int col = bn0 + wn * 32 + ni * 8 + cc;
#pragma unroll
            for (int mi = 0; mi < 4; mi++) {
                size_t row = (size_t)(bm0 + wm * 64 + mi * 16 + g);
                float2 v0 = make_float2(c[mi][ni][0] + br[ni].x, c[mi][ni][1] + br[ni].y);
                float2 v1 = make_float2(c[mi][ni][2] + br[ni].x, c[mi][ni][3] + br[ni].y);
                *(float2*)(out + row * DD + col)       = v0;
                *(float2*)(out + (row + 8) * DD + col) = v1;
            }
        }
        __syncthreads();
    }
}

// ---------------- launch ----------------
extern "C" void kernel_launch(void* const* d_in, const int* in_sizes, int n_in,
                              void* d_out, int out_size) {
    const float* x0  = (const float*)d_in[0];
    const int*   idx = (const int*)  d_in[1];
    const float* K   = (const float*)d_in[2];
    const float* We0 = (const float*)d_in[3];
    const float* be0 = (const float*)d_in[4];
    const float* We1 = (const float*)d_in[5];
    const float* be1 = (const float*)d_in[6];
    const float* We2 = (const float*)d_in[7];
    const float* be2 = (const float*)d_in[8];
    const float* We3 = (const float*)d_in[9];
    const float* be3 = (const float*)d_in[10];
    const float* Wd0 = (const float*)d_in[11];
    const float* bd0 = (const float*)d_in[12];
    const float* Wd1 = (const float*)d_in[13];
    const float* bd1 = (const float*)d_in[14];
    const float* Wd2 = (const float*)d_in[15];
    const float* bd2 = (const float*)d_in[16];
    const float* Wd3 = (const float*)d_in[17];
    const float* bd3 = (const float*)d_in[18];
    float* out = (float*)d_out;

    const int smem_koop  = (L * L + 2 * L * BZ) * 4;       // 96 KB (kloPhi/apply)
    const int smem_dense = (64 * L + L * L) * 4;           // 96 KB
    const int smem_final = FSM_BYTES;                      // ~102 KB
    cudaFuncSetAttribute(kloPhi_kernel,    cudaFuncAttributeMaxDynamicSharedMemorySize, smem_koop);
    cudaFuncSetAttribute(apply_kernel,     cudaFuncAttributeMaxDynamicSharedMemorySize, smem_koop);
    cudaFuncSetAttribute(denseF_kernel,    cudaFuncAttributeMaxDynamicSharedMemorySize, smem_dense);
    cudaFuncSetAttribute(final_mma_kernel, cudaFuncAttributeMaxDynamicSharedMemorySize, smem_final);

    // 1: encoder (split-K layer0 + fused tail)
    encA_kernel<<<256, 128>>>(x0, We0, be0, We1, be1, We2, be2, We3, be3);
    // 2: K^2..K^512
    kpow_fused_kernel<<<128, 128>>>(K);
    // 3: klo || phi
    kloPhi_kernel<<<176, 256, smem_koop>>>(K);
    // 4: apply (this is the launch ncu samples)
    apply_kernel<<<TT, 256, smem_koop>>>(K, idx);
    // 5: Wd3 transpose + fp16 convert
    cvtW_kernel<<<DD / 32, 256>>>(Wd3);
    // 6: fused decoder hiddens
    denseF_kernel<<<MT / 64, 256, smem_dense>>>(Wd0, bd0, Wd1, bd1, Wd2, bd2);
    // 7: final projection
    dim3 fgrid(DD / 128, 8);
    final_mma_kernel<<<fgrid, 256, smem_final>>>(bd3, out);
}

// round 8
// speedup vs baseline: 3.0807x; 1.3177x over previous
#include <cuda_runtime.h>
#include <cuda_fp16.h>
#include <stdint.h>

#define L   128
#define BZ  32
#define TT  512
#define DD  4096
#define MT  (TT*BZ)   // 16384 decoder rows

// ---------------- scratch (device globals; no allocation) ----------------
__device__ float g_h1p[8 * BZ * L];          // enc0 split-K partials
__device__ float g_z0[BZ * L];
__device__ float g_Kpow[9 * L * L];          // K^2 .. K^512
__device__ float g_Klo[16 * L * L];          // K^lo
__device__ float g_Phi[64 * L * BZ];         // (K^16)^hi @ z0^T, [hi][l][b]
__device__ float g_Z [MT * L];
__device__ __half g_Ah[MT * L];              // last hidden activations, fp16
__device__ __half g_Wh[DD * L];              // Wd3 transposed [n][k], fp16
__device__ int g_bar[16];                    // monotonic ticket barriers (never reset)

// ticket grid barrier: monotonic counter, safe across graph replays
__device__ __forceinline__ void gridbar(int* ctr, int n) {
    __threadfence();
    __syncthreads();
    if (threadIdx.x == 0) {
        int t = atomicAdd(ctr, 1);
        int target = (t / n + 1) * n;
        while (*(volatile int*)ctr < target) {}
        __threadfence();
    }
    __syncthreads();
}

// ================= launch 1: encoder (split-K + tail) PARALLEL WITH kpow chain =================
__device__ __forceinline__ void tail_layer128(const float* X, const float* __restrict__ W,
                                              const float* __restrict__ b,
                                              float* Xout, float* gout, int relu, int n) {
    float acc[32];
#pragma unroll
    for (int r = 0; r < 32; r++) acc[r] = 0.f;
#pragma unroll 4
    for (int k = 0; k < L; k++) {
        float w = W[k * L + n];
#pragma unroll
        for (int r = 0; r < 32; r++) acc[r] += X[r * L + k] * w;
    }
    float bn = b[n];
#pragma unroll
    for (int r = 0; r < 32; r++) {
        float v = acc[r] + bn;
        if (relu) v = fmaxf(v, 0.f);
        if (Xout) Xout[r * L + n] = v;
        else      gout[r * L + n] = v;
    }
}

// CTAs 0..127: kpow chain (9 squarings). CTAs 128..383: enc split-K + tail on CTA 128.
__global__ void encKpow_kernel(const float* __restrict__ x0, const float* __restrict__ K1,
                               const float* __restrict__ W0, const float* __restrict__ b0,
                               const float* __restrict__ W1, const float* __restrict__ b1,
                               const float* __restrict__ W2, const float* __restrict__ b2,
                               const float* __restrict__ W3, const float* __restrict__ b3) {
    __shared__ float shm[512 + 2 * BZ * L];   // 34.8 KB
    int n = threadIdx.x;                      // 0..127

    if (blockIdx.x < 128) {
        // ---- kpow: row i of each squaring ----
        float* rowA = shm;
        int i = blockIdx.x;
        const float* A = K1;
        for (int p = 0; p < 9; p++) {
            float* C = g_Kpow + (size_t)p * L * L;
            rowA[n] = A[i * L + n];
            __syncthreads();
            float a0 = 0.f, a1 = 0.f, a2 = 0.f, a3 = 0.f;
#pragma unroll 8
            for (int k = 0; k < L; k += 4) {
                a0 += rowA[k + 0] * A[(k + 0) * L + n];
                a1 += rowA[k + 1] * A[(k + 1) * L + n];
                a2 += rowA[k + 2] * A[(k + 2) * L + n];
                a3 += rowA[k + 3] * A[(k + 3) * L + n];
            }
            C[i * L + n] = (a0 + a1) + (a2 + a3);
            gridbar(&g_bar[1 + p], 128);
            A = C;
        }
    } else {
        // ---- encoder ----
        float* xs = shm;
        float* Xa = shm + 512;
        float* Xb = Xa + BZ * L;
        int cb  = blockIdx.x - 128;     // 0..255
        int row = cb >> 3, c = cb & 7;

        ((float4*)xs)[n] = ((const float4*)(x0 + (size_t)row * DD + c * 512))[n];
        __syncthreads();
        float a0 = 0.f, a1 = 0.f, a2 = 0.f, a3 = 0.f;
        const float* Wc = W0 + (size_t)(c * 512) * L;
#pragma unroll 8
        for (int k = 0; k < 512; k += 4) {
            a0 += xs[k + 0] * Wc[(size_t)(k + 0) * L + n];
            a1 += xs[k + 1] * Wc[(size_t)(k + 1) * L + n];
            a2 += xs[k + 2] * Wc[(size_t)(k + 2) * L + n];
            a3 += xs[k + 3] * Wc[(size_t)(k + 3) * L + n];
        }
        g_h1p[(c * BZ + row) * L + n] = (a0 + a1) + (a2 + a3);

        gridbar(&g_bar[0], 256);
        if (cb != 0) return;

        // tail on one CTA
#pragma unroll
        for (int r = 0; r < 32; r++) {
            float s = 0.f;
#pragma unroll
            for (int c2 = 0; c2 < 8; c2++) s += g_h1p[(c2 * BZ + r) * L + n];
            Xa[r * L + n] = fmaxf(s + b0[n], 0.f);
        }
        __syncthreads();
        tail_layer128(Xa, W1, b1, Xb, nullptr, 1, n); __syncthreads();
        tail_layer128(Xb, W2, b2, Xa, nullptr, 1, n); __syncthreads();
        tail_layer128(Xa, W3, b3, nullptr, g_z0, 0, n);
        __threadfence();
    }
}

// ================= launch 2: phi (0..63) || klo (64..175) || cvtW (176..303) =================
__global__ __launch_bounds__(256)
void kloPhiCvt_kernel(const float* __restrict__ K1, const float* __restrict__ Wd3) {
    extern __shared__ float sm[];
    int tid = threadIdx.x;

    if (blockIdx.x < 64) {
        // ---- phi: Phi[hi] = (K^16)^hi @ z0^T ----
        float* Ks    = sm;
        float* Zbuf0 = sm + L * L;
        float* Zbuf1 = Zbuf0 + L * BZ;
        int hi = blockIdx.x;

        for (int i = tid; i < L * BZ; i += 256) {
            int l = i >> 5, b = i & 31;
            Zbuf0[i] = g_z0[b * L + l];
        }
        __syncthreads();

        float* Zin = Zbuf0; float* Zout = Zbuf1;
        int b  = tid & 31;
        int ig = tid >> 5;

        for (int j = 0; j < 6; j++) {
            if ((hi >> j) & 1) {
                const float* Kp = g_Kpow + (size_t)(3 + j) * L * L;
#pragma unroll
                for (int i = tid; i < L * L / 4; i += 256)
                    ((float4*)Ks)[i] = ((const float4*)Kp)[i];
                __syncthreads();

                float acc[16];
#pragma unroll
                for (int i = 0; i < 16; i++) acc[i] = 0.f;
                for (int k4 = 0; k4 < 32; k4++) {
                    float z0v = Zin[(4 * k4 + 0) * 32 + b];
                    float z1v = Zin[(4 * k4 + 1) * 32 + b];
                    float z2v = Zin[(4 * k4 + 2) * 32 + b];
                    float z3v = Zin[(4 * k4 + 3) * 32 + b];
#pragma unroll
                    for (int i = 0; i < 16; i++) {
                        float4 kr = ((const float4*)Ks)[(ig * 16 + i) * 32 + k4];
                        acc[i] += kr.x * z0v + kr.y * z1v + kr.z * z2v + kr.w * z3v;
                    }
                }
#pragma unroll
                for (int i = 0; i < 16; i++)
                    Zout[(ig * 16 + i) * 32 + b] = acc[i];
                __syncthreads();
                float* tp = Zin; Zin = Zout; Zout = tp;
            }
        }
        float4* dst = (float4*)(g_Phi + (size_t)hi * L * BZ);
#pragma unroll
        for (int i = tid; i < L * BZ / 4; i += 256) dst[i] = ((float4*)Zin)[i];
    } else if (blockIdx.x < 176) {
        // ---- klo: K^l, l in [2,16), 16-row band per CTA ----
        float* Fs = sm;              // 128*128
        float* S  = sm + L * L;      // 16*128
        float* T  = S + 16 * L;      // 16*128
        int u    = blockIdx.x - 64;  // 0..111
        int l    = (u >> 3) + 2;
        int band = u & 7;

        const float* fac[4]; int nf = 0;
        if (l & 1) fac[nf++] = K1;
        if (l & 2) fac[nf++] = g_Kpow + 0 * L * L;
        if (l & 4) fac[nf++] = g_Kpow + 1 * L * L;
        if (l & 8) fac[nf++] = g_Kpow + 2 * L * L;

        const float4* f0 = (const float4*)(fac[0] + (size_t)band * 16 * L);
#pragma unroll
        for (int i = tid; i < 16 * L / 4; i += 256) ((float4*)S)[i] = f0[i];
        __syncthreads();

        float* in = S; float* out = T;
        for (int f = 1; f < nf; f++) {
            const float4* F4 = (const float4*)fac[f];
#pragma unroll
            for (int i = tid; i < L * L / 4; i += 256) ((float4*)Fs)[i] = F4[i];
            __syncthreads();
            int n  = tid & 127;
            int r0 = (tid >> 7) * 8;
            float acc[8];
#pragma unroll
            for (int i = 0; i < 8; i++) acc[i] = 0.f;
#pragma unroll 4
            for (int k = 0; k < L; k++) {
                float w = Fs[k * L + n];
#pragma unroll
                for (int i = 0; i < 8; i++) acc[i] += in[(r0 + i) * L + k] * w;
            }
            __syncthreads();
#pragma unroll
            for (int i = 0; i < 8; i++) out[(r0 + i) * L + n] = acc[i];
            __syncthreads();
            float* tp = in; in = out; out = tp;
        }
        float* dst = g_Klo + (size_t)l * L * L + (size_t)band * 16 * L;
#pragma unroll
        for (int i = tid; i < 16 * L / 4; i += 256) ((float4*)dst)[i] = ((float4*)in)[i];
    } else {
        // ---- cvtW: Wd3 [128,4096] -> g_Wh [4096,128] fp16 ----
        float (*tile)[33] = (float(*)[33])sm;   // 128x33
        int n0 = (blockIdx.x - 176) * 32;
        int tx = tid & 31, ty = tid >> 5;
        for (int k = ty; k < 128; k += 8)
            tile[k][tx] = Wd3[(size_t)k * DD + n0 + tx];
        __syncthreads();
        int nn = n0 + (tid >> 3);
        int k0 = (tid & 7) * 16;
        int c  = nn - n0;
        __half2 h[8];
#pragma unroll
        for (int j = 0; j < 8; j++)
            h[j] = __floats2half2_rn(tile[k0 + 2 * j][c], tile[k0 + 2 * j + 1][c]);
        uint4* dh = (uint4*)(g_Wh + (size_t)nn * L + k0);
        dh[0] = ((uint4*)h)[0];
        dh[1] = ((uint4*)h)[1];
    }
}

// ================= launch 3: apply: Z_t = K^lo(t) @ Phi[hi(t)] =================
__global__ __launch_bounds__(256)
void apply_kernel(const float* __restrict__ K1, const int* __restrict__ idxw) {
    extern __shared__ float sm[];
    float* Ks    = sm;
    float* Zbuf0 = sm + L * L;
    float* Zbuf1 = Zbuf0 + L * BZ;
    int t   = blockIdx.x;
    int tid = threadIdx.x;

    bool is64 = ((idxw[1] | idxw[3] | idxw[5] | idxw[7] | idxw[9] | idxw[11]) == 0);
    int e = is64 ? (idxw[2 * t] - idxw[0]) : (idxw[t] - idxw[0]);
    int lo = e & 15, hi = e >> 4;

    const float4* src = (const float4*)(g_Phi + (size_t)hi * L * BZ);
#pragma unroll
    for (int i = tid; i < L * BZ / 4; i += 256) ((float4*)Zbuf0)[i] = src[i];

    float* Zres = Zbuf0;
    if (lo != 0) {
        const float* Kp = (lo == 1) ? K1 : (g_Klo + (size_t)lo * L * L);
#pragma unroll
        for (int i = tid; i < L * L / 4; i += 256)
            ((float4*)Ks)[i] = ((const float4*)Kp)[i];
        __syncthreads();

        int b  = tid & 31;
        int ig = tid >> 5;
        float acc[16];
#pragma unroll
        for (int i = 0; i < 16; i++) acc[i] = 0.f;
        for (int k4 = 0; k4 < 32; k4++) {
            float z0v = Zbuf0[(4 * k4 + 0) * 32 + b];
            float z1v = Zbuf0[(4 * k4 + 1) * 32 + b];
            float z2v = Zbuf0[(4 * k4 + 2) * 32 + b];
            float z3v = Zbuf0[(4 * k4 + 3) * 32 + b];
#pragma unroll
            for (int i = 0; i < 16; i++) {
                float4 kr = ((const float4*)Ks)[(ig * 16 + i) * 32 + k4];
                acc[i] += kr.x * z0v + kr.y * z1v + kr.z * z2v + kr.w * z3v;
            }
        }
#pragma unroll
        for (int i = 0; i < 16; i++)
            Zbuf1[(ig * 16 + i) * 32 + b] = acc[i];
        Zres = Zbuf1;
    }
    __syncthreads();

    for (int i = tid; i < L * BZ; i += 256) {
        int bb = i >> 7, l = i & 127;
        g_Z[((size_t)t * BZ + bb) * L + l] = Zres[l * 32 + bb];
    }
}

// ================= launch 4: fused decoder hiddens + final fp16 GEMM (persistent) =================
#define SPE 136
#define TILE_BYTES (128 * SPE * 2)
#define OFF_B   0
#define OFF_A0  TILE_BYTES
#define OFF_A1  (2 * TILE_BYTES)
#define FSM_BYTES (3 * TILE_BYTES)      // 104448 B

__device__ __forceinline__ uint32_t smem_u32(const void* p) {
    uint32_t a;
    asm("{ .reg .u64 t; cvta.to.shared.u64 t, %1; cvt.u32.u64 %0, t; }" : "=r"(a) : "l"(p));
    return a;
}
__device__ __forceinline__ void cpasync16(uint32_t dst, const void* src) {
    asm volatile("cp.async.cg.shared.global [%0], [%1], 16;" :: "r"(dst), "l"(src));
}
__device__ __forceinline__ void cp_commit() {
    asm volatile("cp.async.commit_group;" ::: "memory");
}
__device__ __forceinline__ void cp_wait1() {
    asm volatile("cp.async.wait_group 1;" ::: "memory");
}
__device__ __forceinline__ void cp_wait0() {
    asm volatile("cp.async.wait_group 0;" ::: "memory");
}
__device__ __forceinline__ void ldmx4(uint32_t* r, uint32_t addr) {
    asm volatile("ldmatrix.sync.aligned.m8n8.x4.shared.b16 {%0,%1,%2,%3}, [%4];"
                 : "=r"(r[0]), "=r"(r[1]), "=r"(r[2]), "=r"(r[3]) : "r"(addr));
}
__device__ __forceinline__ void ldmx2(uint32_t* r, uint32_t addr) {
    asm volatile("ldmatrix.sync.aligned.m8n8.x2.shared.b16 {%0,%1}, [%2];"
                 : "=r"(r[0]), "=r"(r[1]) : "r"(addr));
}
__device__ __forceinline__ void mma16816h(float* c, const uint32_t* a, const uint32_t* b) {
    asm volatile(
        "mma.sync.aligned.m16n8k16.row.col.f32.f16.f16.f32 "
        "{%0,%1,%2,%3}, {%4,%5,%6,%7}, {%8,%9}, {%0,%1,%2,%3};"
        : "+f"(c[0]), "+f"(c[1]), "+f"(c[2]), "+f"(c[3])
        : "r"(a[0]), "r"(a[1]), "r"(a[2]), "r"(a[3]), "r"(b[0]), "r"(b[1]));
}

__device__ __forceinline__ void issue_A(uint32_t sbase, int bm0, int tid) {
    const uint4* GA = (const uint4*)g_Ah;
#pragma unroll
    for (int t = tid; t < 2048; t += 256) {
        int r = t >> 4, q = t & 15;
        cpasync16(sbase + (uint32_t)(r * (SPE * 2) + q * 16),
                  GA + (size_t)(bm0 + r) * 16 + q);
    }
}

__global__ __launch_bounds__(256, 2)
void denseFinal_kernel(const float* __restrict__ W0, const float* __restrict__ b0,
                       const float* __restrict__ W1, const float* __restrict__ b1,
                       const float* __restrict__ W2, const float* __restrict__ b2,
                       const float* __restrict__ bias, float* __restrict__ out) {
    extern __shared__ __align__(16) char smf[];
    int tid = threadIdx.x;

    // ---------- phase A: decoder hiddens (3 fused layers, 64 rows per CTA) ----------
    {
        float* Xs = (float*)smf;          // 64*128
        float* Ws = Xs + 64 * L;          // 128*128
        float4* Xs4 = (float4*)Xs;
        float4* Ws4 = (float4*)Ws;
        int id  = blockIdx.y * 32 + blockIdx.x;   // 0..255
        int bm0 = id * 64;

        const float4* X4 = (const float4*)g_Z + (size_t)bm0 * 32;
#pragma unroll
        for (int i = tid; i < 64 * L / 4; i += 256) Xs4[i] = X4[i];

        int tx = tid & 31;
        int ty = tid >> 5;
        int r0 = ty * 8;

        const float* Wl[3] = {W0, W1, W2};
        const float* bl[3] = {b0, b1, b2};

#pragma unroll
        for (int layer = 0; layer < 3; layer++) {
            const float4* W4 = (const float4*)Wl[layer];
#pragma unroll
            for (int i = tid; i < L * L / 4; i += 256) Ws4[i] = W4[i];
            __syncthreads();

            float acc[8][4];
#pragma unroll
            for (int i = 0; i < 8; i++)
#pragma unroll
                for (int j = 0; j < 4; j++) acc[i][j] = 0.f;

            for (int k4 = 0; k4 < 32; k4++) {
                float4 c0 = Ws4[(4 * k4 + 0) * 32 + tx];
                float4 c1 = Ws4[(4 * k4 + 1) * 32 + tx];
                float4 c2 = Ws4[(4 * k4 + 2) * 32 + tx];
                float4 c3 = Ws4[(4 * k4 + 3) * 32 + tx];
#pragma unroll
                for (int i = 0; i < 8; i++) {
                    float4 a = Xs4[(r0 + i) * 32 + k4];
                    acc[i][0] += a.x * c0.x + a.y * c1.x + a.z * c2.x + a.w * c3.x;
                    acc[i][1] += a.x * c0.y + a.y * c1.y + a.z * c2.y + a.w * c3.y;
                    acc[i][2] += a.x * c0.z + a.y * c1.z + a.z * c2.z + a.w * c3.z;
                    acc[i][3] += a.x * c0.w + a.y * c1.w + a.z * c2.w + a.w * c3.w;
                }
            }
            __syncthreads();

            float4 bb = ((const float4*)bl[layer])[tx];
            if (layer < 2) {
#pragma unroll
                for (int i = 0; i < 8; i++) {
                    float4 v;
                    v.x = fmaxf(acc[i][0] + bb.x, 0.f);
                    v.y = fmaxf(acc[i][1] + bb.y, 0.f);
                    v.z = fmaxf(acc[i][2] + bb.z, 0.f);
                    v.w = fmaxf(acc[i][3] + bb.w, 0.f);
                    Xs4[(r0 + i) * 32 + tx] = v;
                }
            } else {
#pragma unroll
                for (int i = 0; i < 8; i++) {
                    float vx = fmaxf(acc[i][0] + bb.x, 0.f);
                    float vy = fmaxf(acc[i][1] + bb.y, 0.f);
                    float vz = fmaxf(acc[i][2] + bb.z, 0.f);
                    float vw = fmaxf(acc[i][3] + bb.w, 0.f);
                    __half2 h01 = __floats2half2_rn(vx, vy);
                    __half2 h23 = __floats2half2_rn(vz, vw);
                    uint2 pk; pk.x = *(uint32_t*)&h01; pk.y = *(uint32_t*)&h23;
                    *(uint2*)(g_Ah + (size_t)(bm0 + r0 + i) * L + tx * 4) = pk;
                }
            }
        }
    }

    // all 256 CTAs resident (2/SM guaranteed by launch bounds + smem) -> safe
    gridbar(&g_bar[10], 256);

    // ---------- phase B: final fp16 tensor-core GEMM ----------
    uint32_t sbase = smem_u32(smf);
    int wid  = tid >> 5, lane = tid & 31;
    int bn0  = blockIdx.x * 128;

    const uint4* GW = (const uint4*)g_Wh;
#pragma unroll
    for (int t = tid; t < 2048; t += 256) {
        int r = t >> 4, q = t & 15;
        cpasync16(sbase + OFF_B + (uint32_t)(r * (SPE * 2) + q * 16),
                  GW + (size_t)(bn0 + r) * 16 + q);
    }
    cp_commit();

    issue_A(sbase + OFF_A0, blockIdx.y * 128, tid);
    cp_commit();

    int wm = wid >> 2, wn = wid & 3;

    uint32_t a_off[4], b_off[4];
#pragma unroll
    for (int mi = 0; mi < 4; mi++) {
        int row = wm * 64 + mi * 16 + (lane & 15);
        a_off[mi] = (uint32_t)(row * SPE * 2) + ((lane >> 4) << 4);
    }
#pragma unroll
    for (int ni = 0; ni < 4; ni++) {
        int row = wn * 32 + ni * 8 + (lane & 7);
        b_off[ni] = (uint32_t)(row * SPE * 2) + (((lane >> 3) & 1) << 4);
    }
    uint32_t sB = sbase + OFF_B;

    int g  = lane >> 2;
    int cc = (lane & 3) * 2;
    float2 br[4];
#pragma unroll
    for (int ni = 0; ni < 4; ni++) {
        int col = bn0 + wn * 32 + ni * 8 + cc;
        br[ni] = make_float2(bias[col], bias[col + 1]);
    }

    const int NT = 16;
    for (int it = 0; it < NT; it++) {
        int bm0 = (blockIdx.y + 8 * it) * 128;
        if (it + 1 < NT) {
            issue_A(sbase + ((it + 1) & 1 ? OFF_A1 : OFF_A0),
                    (blockIdx.y + 8 * (it + 1)) * 128, tid);
            cp_commit();
            cp_wait1();
        } else {
            cp_wait0();
        }
        __syncthreads();

        uint32_t sA = sbase + ((it & 1) ? OFF_A1 : OFF_A0);
        float c[4][4][4];
#pragma unroll
        for (int mi = 0; mi < 4; mi++)
#pragma unroll
            for (int ni = 0; ni < 4; ni++)
#pragma unroll
                for (int j = 0; j < 4; j++) c[mi][ni][j] = 0.f;

#pragma unroll
        for (int k0 = 0; k0 < 8; k0++) {
            uint32_t koff = (uint32_t)(k0 * 32);
            uint32_t b[4][2];
#pragma unroll
            for (int ni = 0; ni < 4; ni++) ldmx2(b[ni], sB + b_off[ni] + koff);
#pragma unroll
            for (int mi = 0; mi < 4; mi++) {
                uint32_t a[4];
                ldmx4(a, sA + a_off[mi] + koff);
#pragma unroll
                for (int ni = 0; ni < 4; ni++)
                    mma16816h(c[mi][ni], a, b[ni]);
            }
        }

#pragma unroll
        for (int ni = 0; ni < 4; ni++) {
            int col = bn0 + wn * 32 + ni * 8 + cc;
#pragma unroll
            for (int mi = 0; mi < 4; mi++) {
                size_t row = (size_t)(bm0 + wm * 64 + mi * 16 + g);
                float2 v0 = make_float2(c[mi][ni][0] + br[ni].x, c[mi][ni][1] + br[ni].y);
                float2 v1 = make_float2(c[mi][ni][2] + br[ni].x, c[mi][ni][3] + br[ni].y);
                *(float2*)(out + row * DD + col)       = v0;
                *(float2*)(out + (row + 8) * DD + col) = v1;
            }
        }
        __syncthreads();
    }
}

// ---------------- launch ----------------
extern "C" void kernel_launch(void* const* d_in, const int* in_sizes, int n_in,
                              void* d_out, int out_size) {
    const float* x0  = (const float*)d_in[0];
    const int*   idx = (const int*)  d_in[1];
    const float* K   = (const float*)d_in[2];
    const float* We0 = (const float*)d_in[3];
    const float* be0 = (const float*)d_in[4];
    const float* We1 = (const float*)d_in[5];
    const float* be1 = (const float*)d_in[6];
    const float* We2 = (const float*)d_in[7];
    const float* be2 = (const float*)d_in[8];
    const float* We3 = (const float*)d_in[9];
    const float* be3 = (const float*)d_in[10];
    const float* Wd0 = (const float*)d_in[11];
    const float* bd0 = (const float*)d_in[12];
    const float* Wd1 = (const float*)d_in[13];
    const float* bd1 = (const float*)d_in[14];
    const float* Wd2 = (const float*)d_in[15];
    const float* bd2 = (const float*)d_in[16];
    const float* Wd3 = (const float*)d_in[17];
    const float* bd3 = (const float*)d_in[18];
    float* out = (float*)d_out;

    const int smem_koop = (L * L + 2 * L * BZ) * 4;   // 96 KB
    const int smem_df   = FSM_BYTES;                  // ~102 KB
    cudaFuncSetAttribute(kloPhiCvt_kernel, cudaFuncAttributeMaxDynamicSharedMemorySize, smem_koop);
    cudaFuncSetAttribute(apply_kernel,     cudaFuncAttributeMaxDynamicSharedMemorySize, smem_koop);
    cudaFuncSetAttribute(denseFinal_kernel, cudaFuncAttributeMaxDynamicSharedMemorySize, smem_df);

    // 1: encoder || kpow chain
    encKpow_kernel<<<384, 128>>>(x0, K, We0, be0, We1, be1, We2, be2, We3, be3);
    // 2: phi || klo || cvtW
    kloPhiCvt_kernel<<<304, 256, smem_koop>>>(K, Wd3);
    // 3: apply
    apply_kernel<<<TT, 256, smem_koop>>>(K, idx);
    // 4: fused decoder hiddens + final tensor-core GEMM  (ncu samples this one)
    dim3 fgrid(DD / 128, 8);
    denseFinal_kernel<<<fgrid, 256, smem_df>>>(Wd0, bd0, Wd1, bd1, Wd2, bd2, bd3, out);
}

// round 9
// speedup vs baseline: 3.5584x; 1.1551x over previous
#include <cuda_runtime.h>
#include <cuda_fp16.h>
#include <stdint.h>

#define L   128
#define BZ  32
#define TT  512
#define DD  4096
#define MT  (TT*BZ)   // 16384 decoder rows

// ---------------- scratch (device globals; no allocation) ----------------
__device__ float g_h1p[8 * BZ * L];          // enc0 split-K partials
__device__ float g_z0[BZ * L];
__device__ float g_Kpow[9 * L * L];          // K^2 .. K^512
__device__ float g_Klo[16 * L * L];          // K^lo
__device__ float g_Phi[64 * L * BZ];         // (K^16)^hi @ z0^T, [hi][l][b]
__device__ __half g_Ah[MT * L];              // last hidden activations, fp16
__device__ __half g_Wh[DD * L];              // Wd3 transposed [n][k], fp16
__device__ __half g_Whid[3 * L * L];         // Wd0..2 transposed [n][k], fp16
__device__ int g_bar[16];                    // monotonic ticket barriers (never reset)

// ticket grid barrier: monotonic counter, safe across graph replays
__device__ __forceinline__ void gridbar(int* ctr, int n) {
    __threadfence();
    __syncthreads();
    if (threadIdx.x == 0) {
        int t = atomicAdd(ctr, 1);
        int target = (t / n + 1) * n;
        while (*(volatile int*)ctr < target) {}
        __threadfence();
    }
    __syncthreads();
}

// ================= launch 1: encoder (split-K + tail) PARALLEL WITH kpow chain =================
__device__ __forceinline__ void tail_layer128(const float* X, const float* __restrict__ W,
                                              const float* __restrict__ b,
                                              float* Xout, float* gout, int relu, int n) {
    float acc[32];
#pragma unroll
    for (int r = 0; r < 32; r++) acc[r] = 0.f;
#pragma unroll 4
    for (int k = 0; k < L; k++) {
        float w = W[k * L + n];
#pragma unroll
        for (int r = 0; r < 32; r++) acc[r] += X[r * L + k] * w;
    }
    float bn = b[n];
#pragma unroll
    for (int r = 0; r < 32; r++) {
        float v = acc[r] + bn;
        if (relu) v = fmaxf(v, 0.f);
        if (Xout) Xout[r * L + n] = v;
        else      gout[r * L + n] = v;
    }
}

__global__ void encKpow_kernel(const float* __restrict__ x0, const float* __restrict__ K1,
                               const float* __restrict__ W0, const float* __restrict__ b0,
                               const float* __restrict__ W1, const float* __restrict__ b1,
                               const float* __restrict__ W2, const float* __restrict__ b2,
                               const float* __restrict__ W3, const float* __restrict__ b3) {
    __shared__ float shm[512 + 2 * BZ * L];
    int n = threadIdx.x;

    if (blockIdx.x < 128) {
        // ---- kpow chain ----
        float* rowA = shm;
        int i = blockIdx.x;
        const float* A = K1;
        for (int p = 0; p < 9; p++) {
            float* C = g_Kpow + (size_t)p * L * L;
            rowA[n] = A[i * L + n];
            __syncthreads();
            float a0 = 0.f, a1 = 0.f, a2 = 0.f, a3 = 0.f;
#pragma unroll 8
            for (int k = 0; k < L; k += 4) {
                a0 += rowA[k + 0] * A[(k + 0) * L + n];
                a1 += rowA[k + 1] * A[(k + 1) * L + n];
                a2 += rowA[k + 2] * A[(k + 2) * L + n];
                a3 += rowA[k + 3] * A[(k + 3) * L + n];
            }
            C[i * L + n] = (a0 + a1) + (a2 + a3);
            gridbar(&g_bar[1 + p], 128);
            A = C;
        }
    } else {
        // ---- encoder split-K + tail ----
        float* xs = shm;
        float* Xa = shm + 512;
        float* Xb = Xa + BZ * L;
        int cb  = blockIdx.x - 128;
        int row = cb >> 3, c = cb & 7;

        ((float4*)xs)[n] = ((const float4*)(x0 + (size_t)row * DD + c * 512))[n];
        __syncthreads();
        float a0 = 0.f, a1 = 0.f, a2 = 0.f, a3 = 0.f;
        const float* Wc = W0 + (size_t)(c * 512) * L;
#pragma unroll 8
        for (int k = 0; k < 512; k += 4) {
            a0 += xs[k + 0] * Wc[(size_t)(k + 0) * L + n];
            a1 += xs[k + 1] * Wc[(size_t)(k + 1) * L + n];
            a2 += xs[k + 2] * Wc[(size_t)(k + 2) * L + n];
            a3 += xs[k + 3] * Wc[(size_t)(k + 3) * L + n];
        }
        g_h1p[(c * BZ + row) * L + n] = (a0 + a1) + (a2 + a3);

        gridbar(&g_bar[0], 256);
        if (cb != 0) return;

#pragma unroll
        for (int r = 0; r < 32; r++) {
            float s = 0.f;
#pragma unroll
            for (int c2 = 0; c2 < 8; c2++) s += g_h1p[(c2 * BZ + r) * L + n];
            Xa[r * L + n] = fmaxf(s + b0[n], 0.f);
        }
        __syncthreads();
        tail_layer128(Xa, W1, b1, Xb, nullptr, 1, n); __syncthreads();
        tail_layer128(Xb, W2, b2, Xa, nullptr, 1, n); __syncthreads();
        tail_layer128(Xa, W3, b3, nullptr, g_z0, 0, n);
        __threadfence();
    }
}

// ================= launch 2: phi(0..63) || klo(64..175) || cvtW3(176..303) || cvtHid(304..315) =================
__global__ __launch_bounds__(256)
void kloPhiCvt_kernel(const float* __restrict__ K1, const float* __restrict__ Wd3,
                      const float* __restrict__ Wd0, const float* __restrict__ Wd1,
                      const float* __restrict__ Wd2) {
    extern __shared__ float sm[];
    int tid = threadIdx.x;

    if (blockIdx.x < 64) {
        // ---- phi ----
        float* Ks    = sm;
        float* Zbuf0 = sm + L * L;
        float* Zbuf1 = Zbuf0 + L * BZ;
        int hi = blockIdx.x;

        for (int i = tid; i < L * BZ; i += 256) {
            int l = i >> 5, b = i & 31;
            Zbuf0[i] = g_z0[b * L + l];
        }
        __syncthreads();

        float* Zin = Zbuf0; float* Zout = Zbuf1;
        int b  = tid & 31;
        int ig = tid >> 5;

        for (int j = 0; j < 6; j++) {
            if ((hi >> j) & 1) {
                const float* Kp = g_Kpow + (size_t)(3 + j) * L * L;
#pragma unroll
                for (int i = tid; i < L * L / 4; i += 256)
                    ((float4*)Ks)[i] = ((const float4*)Kp)[i];
                __syncthreads();

                float acc[16];
#pragma unroll
                for (int i = 0; i < 16; i++) acc[i] = 0.f;
                for (int k4 = 0; k4 < 32; k4++) {
                    float z0v = Zin[(4 * k4 + 0) * 32 + b];
                    float z1v = Zin[(4 * k4 + 1) * 32 + b];
                    float z2v = Zin[(4 * k4 + 2) * 32 + b];
                    float z3v = Zin[(4 * k4 + 3) * 32 + b];
#pragma unroll
                    for (int i = 0; i < 16; i++) {
                        float4 kr = ((const float4*)Ks)[(ig * 16 + i) * 32 + k4];
                        acc[i] += kr.x * z0v + kr.y * z1v + kr.z * z2v + kr.w * z3v;
                    }
                }
#pragma unroll
                for (int i = 0; i < 16; i++)
                    Zout[(ig * 16 + i) * 32 + b] = acc[i];
                __syncthreads();
                float* tp = Zin; Zin = Zout; Zout = tp;
            }
        }
        float4* dst = (float4*)(g_Phi + (size_t)hi * L * BZ);
#pragma unroll
        for (int i = tid; i < L * BZ / 4; i += 256) dst[i] = ((float4*)Zin)[i];
    } else if (blockIdx.x < 176) {
        // ---- klo ----
        float* Fs = sm;
        float* S  = sm + L * L;
        float* T  = S + 16 * L;
        int u    = blockIdx.x - 64;
        int l    = (u >> 3) + 2;
        int band = u & 7;

        const float* fac[4]; int nf = 0;
        if (l & 1) fac[nf++] = K1;
        if (l & 2) fac[nf++] = g_Kpow + 0 * L * L;
        if (l & 4) fac[nf++] = g_Kpow + 1 * L * L;
        if (l & 8) fac[nf++] = g_Kpow + 2 * L * L;

        const float4* f0 = (const float4*)(fac[0] + (size_t)band * 16 * L);
#pragma unroll
        for (int i = tid; i < 16 * L / 4; i += 256) ((float4*)S)[i] = f0[i];
        __syncthreads();

        float* in = S; float* out = T;
        for (int f = 1; f < nf; f++) {
            const float4* F4 = (const float4*)fac[f];
#pragma unroll
            for (int i = tid; i < L * L / 4; i += 256) ((float4*)Fs)[i] = F4[i];
            __syncthreads();
            int n  = tid & 127;
            int r0 = (tid >> 7) * 8;
            float acc[8];
#pragma unroll
            for (int i = 0; i < 8; i++) acc[i] = 0.f;
#pragma unroll 4
            for (int k = 0; k < L; k++) {
                float w = Fs[k * L + n];
#pragma unroll
                for (int i = 0; i < 8; i++) acc[i] += in[(r0 + i) * L + k] * w;
            }
            __syncthreads();
#pragma unroll
            for (int i = 0; i < 8; i++) out[(r0 + i) * L + n] = acc[i];
            __syncthreads();
            float* tp = in; in = out; out = tp;
        }
        float* dst = g_Klo + (size_t)l * L * L + (size_t)band * 16 * L;
#pragma unroll
        for (int i = tid; i < 16 * L / 4; i += 256) ((float4*)dst)[i] = ((float4*)in)[i];
    } else {
        // ---- weight transpose + fp16 convert ----
        float (*tile)[33] = (float(*)[33])sm;
        const float* src;
        __half* dstg;
        int n0, stride;
        if (blockIdx.x < 304) {
            n0 = (blockIdx.x - 176) * 32; src = Wd3; stride = DD; dstg = g_Wh;
        } else {
            int u2 = blockIdx.x - 304;                 // 0..11
            int layer = u2 >> 2;
            n0 = (u2 & 3) * 32;
            src = (layer == 0) ? Wd0 : (layer == 1) ? Wd1 : Wd2;
            stride = L;
            dstg = g_Whid + (size_t)layer * L * L;
        }
        int tx = tid & 31, ty = tid >> 5;
        for (int k = ty; k < 128; k += 8)
            tile[k][tx] = src[(size_t)k * stride + n0 + tx];
        __syncthreads();
        int nn = n0 + (tid >> 3);
        int k0 = (tid & 7) * 16;
        int c  = nn - n0;
        __half2 h[8];
#pragma unroll
        for (int j = 0; j < 8; j++)
            h[j] = __floats2half2_rn(tile[k0 + 2 * j][c], tile[k0 + 2 * j + 1][c]);
        uint4* dh = (uint4*)(dstg + (size_t)nn * L + k0);
        dh[0] = ((uint4*)h)[0];
        dh[1] = ((uint4*)h)[1];
    }
}

// ================= launch 3: apply + fp16 hiddens + final fp16 GEMM (persistent) =================
#define SPE 136
#define TILE_BYTES (128 * SPE * 2)      // 34816
#define OFF_B   0
#define OFF_A0  TILE_BYTES
#define OFF_A1  (2 * TILE_BYTES)
#define FSM_BYTES (3 * TILE_BYTES)      // 104448

// phase-A smem offsets (all dead before phase B reuses the buffer)
#define KS_OFF   0                       // 64 KB fp32 K^lo
#define PHI_OFF  65536                   // 16 KB fp32 Phi
#define XA_OFF   81920                   // 64x136 fp16 act tile A (17408 B)
#define WH_OFF   0                       // 128x136 fp16 weight tile (34816 B)
#define XB_OFF   40960                   // 64x136 fp16 act tile B

__device__ __forceinline__ uint32_t smem_u32(const void* p) {
    uint32_t a;
    asm("{ .reg .u64 t; cvta.to.shared.u64 t, %1; cvt.u32.u64 %0, t; }" : "=r"(a) : "l"(p));
    return a;
}
__device__ __forceinline__ void cpasync16(uint32_t dst, const void* src) {
    asm volatile("cp.async.cg.shared.global [%0], [%1], 16;" :: "r"(dst), "l"(src));
}
__device__ __forceinline__ void cp_commit() {
    asm volatile("cp.async.commit_group;" ::: "memory");
}
__device__ __forceinline__ void cp_wait1() {
    asm volatile("cp.async.wait_group 1;" ::: "memory");
}
__device__ __forceinline__ void cp_wait0() {
    asm volatile("cp.async.wait_group 0;" ::: "memory");
}
__device__ __forceinline__ void ldmx4(uint32_t* r, uint32_t addr) {
    asm volatile("ldmatrix.sync.aligned.m8n8.x4.shared.b16 {%0,%1,%2,%3}, [%4];"
                 : "=r"(r[0]), "=r"(r[1]), "=r"(r[2]), "=r"(r[3]) : "r"(addr));
}
__device__ __forceinline__ void ldmx2(uint32_t* r, uint32_t addr) {
    asm volatile("ldmatrix.sync.aligned.m8n8.x2.shared.b16 {%0,%1}, [%2];"
                 : "=r"(r[0]), "=r"(r[1]) : "r"(addr));
}
__device__ __forceinline__ void mma16816h(float* c, const uint32_t* a, const uint32_t* b) {
    asm volatile(
        "mma.sync.aligned.m16n8k16.row.col.f32.f16.f16.f32 "
        "{%0,%1,%2,%3}, {%4,%5,%6,%7}, {%8,%9}, {%0,%1,%2,%3};"
        : "+f"(c[0]), "+f"(c[1]), "+f"(c[2]), "+f"(c[3])
        : "r"(a[0]), "r"(a[1]), "r"(a[2]), "r"(a[3]), "r"(b[0]), "r"(b[1]));
}

__device__ __forceinline__ void issue_A(uint32_t sbase, int bm0, int tid) {
    const uint4* GA = (const uint4*)g_Ah;
#pragma unroll
    for (int t = tid; t < 2048; t += 256) {
        int r = t >> 4, q = t & 15;
        cpasync16(sbase + (uint32_t)(r * (SPE * 2) + q * 16),
                  GA + (size_t)(bm0 + r) * 16 + q);
    }
}

__global__ __launch_bounds__(256, 2)
void denseFinal_kernel(const float* __restrict__ K1, const int* __restrict__ idxw,
                       const float* __restrict__ b0, const float* __restrict__ b1,
                       const float* __restrict__ b2,
                       const float* __restrict__ bias, float* __restrict__ out) {
    extern __shared__ __align__(16) char smf[];
    uint32_t sbase = smem_u32(smf);
    int tid  = threadIdx.x;
    int wid  = tid >> 5, lane = tid & 31;
    int id   = blockIdx.y * 32 + blockIdx.x;    // 0..255
    int bm0A = id * 64;                         // this CTA's 64 activation rows

    // ---------- phase A1: fused apply (fp32): Z rows -> fp16 tile at XA_OFF ----------
    {
        bool is64 = ((idxw[1] | idxw[3] | idxw[5] | idxw[7] | idxw[9] | idxw[11]) == 0);
        int b  = tid & 31;
        int ig = tid >> 5;
        float* Ks   = (float*)(smf + KS_OFF);
        float* sPhi = (float*)(smf + PHI_OFF);

        for (int tt = 0; tt < 2; tt++) {
            int t = id * 2 + tt;
            int e = is64 ? (idxw[2 * t] - idxw[0]) : (idxw[t] - idxw[0]);
            int lo = e & 15, hi = e >> 4;

            const float4* ps = (const float4*)(g_Phi + (size_t)hi * L * BZ);
#pragma unroll
            for (int i = tid; i < 1024; i += 256) ((float4*)sPhi)[i] = ps[i];

            float acc[16];
            if (lo != 0) {
                const float* Kp = (lo == 1) ? K1 : (g_Klo + (size_t)lo * L * L);
#pragma unroll
                for (int i = tid; i < 4096; i += 256) ((float4*)Ks)[i] = ((const float4*)Kp)[i];
                __syncthreads();
#pragma unroll
                for (int i = 0; i < 16; i++) acc[i] = 0.f;
                for (int k4 = 0; k4 < 32; k4++) {
                    float z0v = sPhi[(4 * k4 + 0) * 32 + b];
                    float z1v = sPhi[(4 * k4 + 1) * 32 + b];
                    float z2v = sPhi[(4 * k4 + 2) * 32 + b];
                    float z3v = sPhi[(4 * k4 + 3) * 32 + b];
#pragma unroll
                    for (int i = 0; i < 16; i++) {
                        float4 kr = ((const float4*)Ks)[(ig * 16 + i) * 32 + k4];
                        acc[i] += kr.x * z0v + kr.y * z1v + kr.z * z2v + kr.w * z3v;
                    }
                }
            } else {
                __syncthreads();
#pragma unroll
                for (int i = 0; i < 16; i++) acc[i] = sPhi[(ig * 16 + i) * 32 + b];
            }

            // transpose+convert: Xa[row = tt*32+b][k = ig*16 + i] fp16
            __half2 hh[8];
#pragma unroll
            for (int j = 0; j < 8; j++) hh[j] = __floats2half2_rn(acc[2 * j], acc[2 * j + 1]);
            uint4* dst = (uint4*)(smf + XA_OFF + (tt * 32 + b) * (SPE * 2) + ig * 32);
            dst[0] = ((uint4*)hh)[0];
            dst[1] = ((uint4*)hh)[1];
            __syncthreads();
        }
    }

    // ---------- phase A2: 3 hidden layers on fp16 tensor cores ----------
    {
        int rg = wid & 3;          // rows rg*16
        int cg = wid >> 2;         // cols cg*64
        uint32_t aoff = (uint32_t)((rg * 16 + (lane & 15)) * (SPE * 2)) + ((lane >> 4) << 4);
        uint32_t boff[4];
#pragma unroll
        for (int p = 0; p < 4; p++) {
            int row = cg * 64 + p * 16 + ((lane >> 4) << 3) + (lane & 7);
            boff[p] = (uint32_t)(row * (SPE * 2)) + (((lane >> 3) & 1) << 4);
        }
        int g  = lane >> 2;
        int cc = (lane & 3) * 2;
        const float* bl[3] = {b0, b1, b2};

        uint32_t inOff = XA_OFF, outOff = XB_OFF;
#pragma unroll
        for (int layer = 0; layer < 3; layer++) {
            // load W[n][k] fp16 into padded smem at WH_OFF
            const uint4* Wg = (const uint4*)(g_Whid + (size_t)layer * L * L);
#pragma unroll
            for (int i = tid; i < 2048; i += 256) {
                int r = i >> 4, q = i & 15;
                *(uint4*)(smf + WH_OFF + r * (SPE * 2) + q * 16) = Wg[r * 16 + q];
            }
            __syncthreads();

            float c[8][4];
#pragma unroll
            for (int p = 0; p < 8; p++)
#pragma unroll
                for (int j = 0; j < 4; j++) c[p][j] = 0.f;

#pragma unroll
            for (int k0 = 0; k0 < 8; k0++) {
                uint32_t koff = (uint32_t)(k0 * 32);
                uint32_t a[4];
                ldmx4(a, sbase + inOff + aoff + koff);
#pragma unroll
                for (int p = 0; p < 4; p++) {
                    uint32_t bf[4];
                    ldmx4(bf, sbase + WH_OFF + boff[p] + koff);
                    mma16816h(c[2 * p + 0], a, bf + 0);
                    mma16816h(c[2 * p + 1], a, bf + 2);
                }
            }

            // epilogue: bias + relu + cvt fp16
#pragma unroll
            for (int p = 0; p < 8; p++) {
                int col = cg * 64 + p * 8 + cc;
                float bx = bl[layer][col], by = bl[layer][col + 1];
                int row0 = rg * 16 + g;
                float v0x = fmaxf(c[p][0] + bx, 0.f), v0y = fmaxf(c[p][1] + by, 0.f);
                float v1x = fmaxf(c[p][2] + bx, 0.f), v1y = fmaxf(c[p][3] + by, 0.f);
                __half2 h0 = __floats2half2_rn(v0x, v0y);
                __half2 h1 = __floats2half2_rn(v1x, v1y);
                if (layer < 2) {
                    *(uint32_t*)(smf + outOff + row0 * (SPE * 2) + col * 2)       = *(uint32_t*)&h0;
                    *(uint32_t*)(smf + outOff + (row0 + 8) * (SPE * 2) + col * 2) = *(uint32_t*)&h1;
                } else {
                    *(uint32_t*)(g_Ah + (size_t)(bm0A + row0) * L + col)     = *(uint32_t*)&h0;
                    *(uint32_t*)(g_Ah + (size_t)(bm0A + row0 + 8) * L + col) = *(uint32_t*)&h1;
                }
            }
            __syncthreads();
            uint32_t tp = inOff; inOff = outOff; outOff = tp;
        }
    }

    // all 256 CTAs resident (2/SM via launch bounds + smem) -> safe
    gridbar(&g_bar[10], 256);

    // ---------- phase B: final fp16 tensor-core GEMM ----------
    int bn0 = blockIdx.x * 128;

    const uint4* GW = (const uint4*)g_Wh;
#pragma unroll
    for (int t = tid; t < 2048; t += 256) {
        int r = t >> 4, q = t & 15;
        cpasync16(sbase + OFF_B + (uint32_t)(r * (SPE * 2) + q * 16),
                  GW + (size_t)(bn0 + r) * 16 + q);
    }
    cp_commit();

    issue_A(sbase + OFF_A0, blockIdx.y * 128, tid);
    cp_commit();

    int wm = wid >> 2, wn = wid & 3;

    uint32_t a_off[4], b_off[4];
#pragma unroll
    for (int mi = 0; mi < 4; mi++) {
        int row = wm * 64 + mi * 16 + (lane & 15);
        a_off[mi] = (uint32_t)(row * SPE * 2) + ((lane >> 4) << 4);
    }
#pragma unroll
    for (int ni = 0; ni < 4; ni++) {
        int row = wn * 32 + ni * 8 + (lane & 7);
        b_off[ni] = (uint32_t)(row * SPE * 2) + (((lane >> 3) & 1) << 4);
    }
    uint32_t sB = sbase + OFF_B;

    int g  = lane >> 2;
    int cc = (lane & 3) * 2;
    float2 br[4];
#pragma unroll
    for (int ni = 0; ni < 4; ni++) {
        int col = bn0 + wn * 32 + ni * 8 + cc;
        br[ni] = make_float2(bias[col], bias[col + 1]);
    }

    const int NT = 16;
    for (int it = 0; it < NT; it++) {
        int bm0 = (blockIdx.y + 8 * it) * 128;
        if (it + 1 < NT) {
            issue_A(sbase + ((it + 1) & 1 ? OFF_A1 : OFF_A0),
                    (blockIdx.y + 8 * (it + 1)) * 128, tid);
            cp_commit();
            cp_wait1();
        } else {
            cp_wait0();
        }
        __syncthreads();

        uint32_t sA = sbase + ((it & 1) ? OFF_A1 : OFF_A0);
        float c[4][4][4];
#pragma unroll
        for (int mi = 0; mi < 4; mi++)
#pragma unroll
            for (int ni = 0; ni < 4; ni++)
#pragma unroll
                for (int j = 0; j < 4; j++) c[mi][ni][j] = 0.f;

#pragma unroll
        for (int k0 = 0; k0 < 8; k0++) {
            uint32_t koff = (uint32_t)(k0 * 32);
            uint32_t b[4][2];
#pragma unroll
            for (int ni = 0; ni < 4; ni++) ldmx2(b[ni], sB + b_off[ni] + koff);
#pragma unroll
            for (int mi = 0; mi < 4; mi++) {
                uint32_t a[4];
                ldmx4(a, sA + a_off[mi] + koff);
#pragma unroll
                for (int ni = 0; ni < 4; ni++)
                    mma16816h(c[mi][ni], a, b[ni]);
            }
        }

#pragma unroll
        for (int ni = 0; ni < 4; ni++) {
            int col = bn0 + wn * 32 + ni * 8 + cc;
#pragma unroll
            for (int mi = 0; mi < 4; mi++) {
                size_t row = (size_t)(bm0 + wm * 64 + mi * 16 + g);
                float2 v0 = make_float2(c[mi][ni][0] + br[ni].x, c[mi][ni][1] + br[ni].y);
                float2 v1 = make_float2(c[mi][ni][2] + br[ni].x, c[mi][ni][3] + br[ni].y);
                *(float2*)(out + row * DD + col)       = v0;
                *(float2*)(out + (row + 8) * DD + col) = v1;
            }
        }
        __syncthreads();
    }
}

// ---------------- launch ----------------
extern "C" void kernel_launch(void* const* d_in, const int* in_sizes, int n_in,
                              void* d_out, int out_size) {
    const float* x0  = (const float*)d_in[0];
    const int*   idx = (const int*)  d_in[1];
    const float* K   = (const float*)d_in[2];
    const float* We0 = (const float*)d_in[3];
    const float* be0 = (const float*)d_in[4];
    const float* We1 = (const float*)d_in[5];
    const float* be1 = (const float*)d_in[6];
    const float* We2 = (const float*)d_in[7];
    const float* be2 = (const float*)d_in[8];
    const float* We3 = (const float*)d_in[9];
    const float* be3 = (const float*)d_in[10];
    const float* Wd0 = (const float*)d_in[11];
    const float* bd0 = (const float*)d_in[12];
    const float* Wd1 = (const float*)d_in[13];
    const float* bd1 = (const float*)d_in[14];
    const float* Wd2 = (const float*)d_in[15];
    const float* bd2 = (const float*)d_in[16];
    const float* Wd3 = (const float*)d_in[17];
    const float* bd3 = (const float*)d_in[18];
    float* out = (float*)d_out;

    const int smem_koop = (L * L + 2 * L * BZ) * 4;   // 96 KB
    const int smem_df   = FSM_BYTES;                  // ~102 KB
    cudaFuncSetAttribute(kloPhiCvt_kernel,  cudaFuncAttributeMaxDynamicSharedMemorySize, smem_koop);
    cudaFuncSetAttribute(denseFinal_kernel, cudaFuncAttributeMaxDynamicSharedMemorySize, smem_df);

    // 1: encoder || kpow chain
    encKpow_kernel<<<384, 128>>>(x0, K, We0, be0, We1, be1, We2, be2, We3, be3);
    // 2: phi || klo || weight transposes/converts (Wd3 + Wd0..2)
    kloPhiCvt_kernel<<<316, 256, smem_koop>>>(K, Wd3, Wd0, Wd1, Wd2);
    // 3: fused apply + fp16 hiddens + final tensor-core GEMM
    dim3 fgrid(DD / 128, 8);
    denseFinal_kernel<<<fgrid, 256, smem_df>>>(K, idx, bd0, bd1, bd2, bd3, out);
}

// round 10
// speedup vs baseline: 3.8710x; 1.0879x over previous
#include <cuda_runtime.h>
#include <cuda_fp16.h>
#include <stdint.h>

#define L   128
#define BZ  32
#define TT  512
#define DD  4096
#define MT  (TT*BZ)   // 16384 decoder rows

// ---------------- scratch (device globals; no allocation) ----------------
__device__ float g_h1p[8 * BZ * L];          // enc0 split-K partials
__device__ float g_z0[BZ * L];
__device__ float g_Kpow[9 * L * L];          // K^2 .. K^512
__device__ float g_Klo[16 * L * L];          // K^lo
__device__ float g_Phi[64 * L * BZ];         // (K^16)^hi @ z0^T, [hi][l][b]
__device__ __half g_Ah[MT * L];              // last hidden activations, fp16
__device__ __half g_Wh[DD * L];              // Wd3 transposed [n][k], fp16
__device__ __half g_Whid[3 * L * L];         // Wd0..2 transposed [n][k], fp16
__device__ int g_bar[16];                    // monotonic ticket barriers (never reset)

// ticket grid barrier: monotonic counter, safe across graph replays
__device__ __forceinline__ void gridbar(int* ctr, int n) {
    __threadfence();
    __syncthreads();
    if (threadIdx.x == 0) {
        int t = atomicAdd(ctr, 1);
        int target = (t / n + 1) * n;
        while (*(volatile int*)ctr < target) {}
        __threadfence();
    }
    __syncthreads();
}

// ================= launch 1: encoder (split-K + tail) PARALLEL WITH kpow chain =================
// dynamic smem 96KB. CTAs 0..127: kpow (A cached in smem). CTAs 128..383: encoder.
__global__ void encKpow_kernel(const float* __restrict__ x0, const float* __restrict__ K1,
                               const float* __restrict__ W0, const float* __restrict__ b0,
                               const float* __restrict__ W1, const float* __restrict__ b1,
                               const float* __restrict__ W2, const float* __restrict__ b2,
                               const float* __restrict__ W3, const float* __restrict__ b3) {
    extern __shared__ float sm1[];
    int n = threadIdx.x;   // 0..127

    if (blockIdx.x < 128) {
        // ---- kpow chain, A fully smem-resident each step ----
        float* As = sm1;                       // 64 KB
        float4* As4 = (float4*)As;
        int i = blockIdx.x;
        const float* A = K1;
        for (int p = 0; p < 9; p++) {
            float* C = g_Kpow + (size_t)p * L * L;
            const float4* A4 = (const float4*)A;
#pragma unroll
            for (int q = n; q < 4096; q += 128) As4[q] = A4[q];
            __syncthreads();
            const float* rowA = As + i * L;
            float a0 = 0.f, a1 = 0.f, a2 = 0.f, a3 = 0.f;
#pragma unroll 8
            for (int k = 0; k < L; k += 4) {
                a0 += rowA[k + 0] * As[(k + 0) * L + n];
                a1 += rowA[k + 1] * As[(k + 1) * L + n];
                a2 += rowA[k + 2] * As[(k + 2) * L + n];
                a3 += rowA[k + 3] * As[(k + 3) * L + n];
            }
            C[i * L + n] = (a0 + a1) + (a2 + a3);
            __syncthreads();                   // As reads done before next fill
            gridbar(&g_bar[1 + p], 128);
            A = C;
        }
    } else {
        // ---- encoder split-K ----
        float* xs = sm1;                       // 2 KB (overlaps Ws; phases sequential)
        int cb  = blockIdx.x - 128;
        int row = cb >> 3, c = cb & 7;

        ((float4*)xs)[n] = ((const float4*)(x0 + (size_t)row * DD + c * 512))[n];
        __syncthreads();
        float a0 = 0.f, a1 = 0.f, a2 = 0.f, a3 = 0.f;
        const float* Wc = W0 + (size_t)(c * 512) * L;
#pragma unroll 8
        for (int k = 0; k < 512; k += 4) {
            a0 += xs[k + 0] * Wc[(size_t)(k + 0) * L + n];
            a1 += xs[k + 1] * Wc[(size_t)(k + 1) * L + n];
            a2 += xs[k + 2] * Wc[(size_t)(k + 2) * L + n];
            a3 += xs[k + 3] * Wc[(size_t)(k + 3) * L + n];
        }
        g_h1p[(c * BZ + row) * L + n] = (a0 + a1) + (a2 + a3);

        gridbar(&g_bar[0], 256);
        if (cb != 0) return;

        // ---- tail on one CTA, W layers staged through smem ----
        float* Ws = sm1;                       // 64 KB
        float* Xa = sm1 + 16384;               // 16 KB
        float* Xb = sm1 + 16384 + 4096;        // 16 KB
        float4* Ws4 = (float4*)Ws;

#pragma unroll
        for (int r = 0; r < 32; r++) {
            float s = 0.f;
#pragma unroll
            for (int c2 = 0; c2 < 8; c2++) s += g_h1p[(c2 * BZ + r) * L + n];
            Xa[r * L + n] = fmaxf(s + b0[n], 0.f);
        }
        __syncthreads();

        const float* Wl[3] = {W1, W2, W3};
        const float* bl[3] = {b1, b2, b3};
        float* Xi = Xa; float* Xo = Xb;
#pragma unroll
        for (int layer = 0; layer < 3; layer++) {
            const float4* W4 = (const float4*)Wl[layer];
#pragma unroll
            for (int q = n; q < 4096; q += 128) Ws4[q] = W4[q];
            __syncthreads();
            float acc[32];
#pragma unroll
            for (int r = 0; r < 32; r++) acc[r] = 0.f;
#pragma unroll 4
            for (int k = 0; k < L; k++) {
                float w = Ws[k * L + n];
#pragma unroll
                for (int r = 0; r < 32; r++) acc[r] += Xi[r * L + k] * w;
            }
            float bn = bl[layer][n];
            __syncthreads();                   // Ws/Xi reads done
            if (layer < 2) {
#pragma unroll
                for (int r = 0; r < 32; r++) Xo[r * L + n] = fmaxf(acc[r] + bn, 0.f);
                __syncthreads();
                float* tp = Xi; Xi = Xo; Xo = tp;
            } else {
#pragma unroll
                for (int r = 0; r < 32; r++) g_z0[r * L + n] = acc[r] + bn;
            }
        }
        __threadfence();
    }
}

// ================= launch 2: phi(0..127, b-split) || klo(128..239) || cvt(240..379) =================
__global__ __launch_bounds__(256)
void kloPhiCvt_kernel(const float* __restrict__ K1, const float* __restrict__ Wd3,
                      const float* __restrict__ Wd0, const float* __restrict__ Wd1,
                      const float* __restrict__ Wd2) {
    extern __shared__ float sm[];
    int tid = threadIdx.x;

    if (blockIdx.x < 128) {
        // ---- phi: Phi[hi] columns [half*16, half*16+16) ----
        int hi   = blockIdx.x & 63;
        int half = blockIdx.x >> 6;
        float* Ks = sm;                  // 64 KB
        float* Z0 = sm + 16384;          // 128x16 = 8 KB
        float* Z1 = Z0 + 2048;           // 8 KB
        float4* Ks4 = (float4*)Ks;

        for (int i = tid; i < 2048; i += 256) {
            int l = i >> 4, bb = i & 15;
            Z0[i] = g_z0[(half * 16 + bb) * L + l];
        }
        __syncthreads();

        float* Zin = Z0; float* Zout = Z1;
        int bb = tid & 15;
        int ig = tid >> 4;               // 0..15, rows ig*8..ig*8+7

        for (int j = 0; j < 6; j++) {
            if ((hi >> j) & 1) {
                const float4* Kp4 = (const float4*)(g_Kpow + (size_t)(3 + j) * L * L);
#pragma unroll
                for (int i = tid; i < 4096; i += 256) Ks4[i] = Kp4[i];
                __syncthreads();

                float acc[8];
#pragma unroll
                for (int i = 0; i < 8; i++) acc[i] = 0.f;
                for (int k4 = 0; k4 < 32; k4++) {
                    float z0v = Zin[(4 * k4 + 0) * 16 + bb];
                    float z1v = Zin[(4 * k4 + 1) * 16 + bb];
                    float z2v = Zin[(4 * k4 + 2) * 16 + bb];
                    float z3v = Zin[(4 * k4 + 3) * 16 + bb];
#pragma unroll
                    for (int i = 0; i < 8; i++) {
                        float4 kr = Ks4[(ig * 8 + i) * 32 + k4];
                        acc[i] += kr.x * z0v + kr.y * z1v + kr.z * z2v + kr.w * z3v;
                    }
                }
#pragma unroll
                for (int i = 0; i < 8; i++)
                    Zout[(ig * 8 + i) * 16 + bb] = acc[i];
                __syncthreads();
                float* tp = Zin; Zin = Zout; Zout = tp;
            }
        }
        for (int i = tid; i < 2048; i += 256) {
            int l = i >> 4, b2 = i & 15;
            g_Phi[(size_t)hi * L * BZ + l * 32 + half * 16 + b2] = Zin[i];
        }
    } else if (blockIdx.x < 240) {
        // ---- klo ----
        float* Fs = sm;
        float* S  = sm + L * L;
        float* T  = S + 16 * L;
        int u    = blockIdx.x - 128;
        int l    = (u >> 3) + 2;
        int band = u & 7;

        const float* fac[4]; int nf = 0;
        if (l & 1) fac[nf++] = K1;
        if (l & 2) fac[nf++] = g_Kpow + 0 * L * L;
        if (l & 4) fac[nf++] = g_Kpow + 1 * L * L;
        if (l & 8) fac[nf++] = g_Kpow + 2 * L * L;

        const float4* f0 = (const float4*)(fac[0] + (size_t)band * 16 * L);
#pragma unroll
        for (int i = tid; i < 16 * L / 4; i += 256) ((float4*)S)[i] = f0[i];
        __syncthreads();

        float* in = S; float* out = T;
        for (int f = 1; f < nf; f++) {
            const float4* F4 = (const float4*)fac[f];
#pragma unroll
            for (int i = tid; i < L * L / 4; i += 256) ((float4*)Fs)[i] = F4[i];
            __syncthreads();
            int n  = tid & 127;
            int r0 = (tid >> 7) * 8;
            float acc[8];
#pragma unroll
            for (int i = 0; i < 8; i++) acc[i] = 0.f;
#pragma unroll 4
            for (int k = 0; k < L; k++) {
                float w = Fs[k * L + n];
#pragma unroll
                for (int i = 0; i < 8; i++) acc[i] += in[(r0 + i) * L + k] * w;
            }
            __syncthreads();
#pragma unroll
            for (int i = 0; i < 8; i++) out[(r0 + i) * L + n] = acc[i];
            __syncthreads();
            float* tp = in; in = out; out = tp;
        }
        float* dst = g_Klo + (size_t)l * L * L + (size_t)band * 16 * L;
#pragma unroll
        for (int i = tid; i < 16 * L / 4; i += 256) ((float4*)dst)[i] = ((float4*)in)[i];
    } else {
        // ---- weight transpose + fp16 convert ----
        float (*tile)[33] = (float(*)[33])sm;
        const float* src;
        __half* dstg;
        int n0, stride;
        int u2 = blockIdx.x - 240;
        if (u2 < 128) {
            n0 = u2 * 32; src = Wd3; stride = DD; dstg = g_Wh;
        } else {
            int u3 = u2 - 128;                 // 0..11
            int layer = u3 >> 2;
            n0 = (u3 & 3) * 32;
            src = (layer == 0) ? Wd0 : (layer == 1) ? Wd1 : Wd2;
            stride = L;
            dstg = g_Whid + (size_t)layer * L * L;
        }
        int tx = tid & 31, ty = tid >> 5;
        for (int k = ty; k < 128; k += 8)
            tile[k][tx] = src[(size_t)k * stride + n0 + tx];
        __syncthreads();
        int nn = n0 + (tid >> 3);
        int k0 = (tid & 7) * 16;
        int c  = nn - n0;
        __half2 h[8];
#pragma unroll
        for (int j = 0; j < 8; j++)
            h[j] = __floats2half2_rn(tile[k0 + 2 * j][c], tile[k0 + 2 * j + 1][c]);
        uint4* dh = (uint4*)(dstg + (size_t)nn * L + k0);
        dh[0] = ((uint4*)h)[0];
        dh[1] = ((uint4*)h)[1];
    }
}

// ================= launch 3: apply + fp16 hiddens + final fp16 GEMM (persistent) =================
#define SPE 136
#define TILE_BYTES (128 * SPE * 2)      // 34816
#define OFF_B   0
#define OFF_A0  TILE_BYTES
#define OFF_A1  (2 * TILE_BYTES)
#define FSM_BYTES (3 * TILE_BYTES)      // 104448

#define KS_OFF   0                       // 64 KB fp32 K^lo
#define PHI_OFF  65536                   // 16 KB fp32 Phi
#define XA_OFF   81920                   // 64x136 fp16 act tile A
#define WH_OFF   0                       // 128x136 fp16 weight tile
#define XB_OFF   40960                   // 64x136 fp16 act tile B

__device__ __forceinline__ uint32_t smem_u32(const void* p) {
    uint32_t a;
    asm("{ .reg .u64 t; cvta.to.shared.u64 t, %1; cvt.u32.u64 %0, t; }" : "=r"(a) : "l"(p));
    return a;
}
__device__ __forceinline__ void cpasync16(uint32_t dst, const void* src) {
    asm volatile("cp.async.cg.shared.global [%0], [%1], 16;" :: "r"(dst), "l"(src));
}
__device__ __forceinline__ void cp_commit() {
    asm volatile("cp.async.commit_group;" ::: "memory");
}
__device__ __forceinline__ void cp_wait1() {
    asm volatile("cp.async.wait_group 1;" ::: "memory");
}
__device__ __forceinline__ void cp_wait0() {
    asm volatile("cp.async.wait_group 0;" ::: "memory");
}
__device__ __forceinline__ void ldmx4(uint32_t* r, uint32_t addr) {
    asm volatile("ldmatrix.sync.aligned.m8n8.x4.shared.b16 {%0,%1,%2,%3}, [%4];"
                 : "=r"(r[0]), "=r"(r[1]), "=r"(r[2]), "=r"(r[3]) : "r"(addr));
}
__device__ __forceinline__ void ldmx2(uint32_t* r, uint32_t addr) {
    asm volatile("ldmatrix.sync.aligned.m8n8.x2.shared.b16 {%0,%1}, [%2];"
                 : "=r"(r[0]), "=r"(r[1]) : "r"(addr));
}
__device__ __forceinline__ void mma16816h(float* c, const uint32_t* a, const uint32_t* b) {
    asm volatile(
        "mma.sync.aligned.m16n8k16.row.col.f32.f16.f16.f32 "
        "{%0,%1,%2,%3}, {%4,%5,%6,%7}, {%8,%9}, {%0,%1,%2,%3};"
        : "+f"(c[0]), "+f"(c[1]), "+f"(c[2]), "+f"(c[3])
        : "r"(a[0]), "r"(a[1]), "r"(a[2]), "r"(a[3]), "r"(b[0]), "r"(b[1]));
}

__device__ __forceinline__ void issue_A(uint32_t sbase, int bm0, int tid) {
    const uint4* GA = (const uint4*)g_Ah;
#pragma unroll
    for (int t = tid; t < 2048; t += 256) {
        int r = t >> 4, q = t & 15;
        cpasync16(sbase + (uint32_t)(r * (SPE * 2) + q * 16),
                  GA + (size_t)(bm0 + r) * 16 + q);
    }
}

__global__ __launch_bounds__(256, 2)
void denseFinal_kernel(const float* __restrict__ K1, const int* __restrict__ idxw,
                       const float* __restrict__ b0, const float* __restrict__ b1,
                       const float* __restrict__ b2,
                       const float* __restrict__ bias, float* __restrict__ out) {
    extern __shared__ __align__(16) char smf[];
    uint32_t sbase = smem_u32(smf);
    int tid  = threadIdx.x;
    int wid  = tid >> 5, lane = tid & 31;
    int id   = blockIdx.y * 32 + blockIdx.x;
    int bm0A = id * 64;

    // ---------- phase A1: fused apply (fp32): Z rows -> fp16 tile at XA_OFF ----------
    {
        bool is64 = ((idxw[1] | idxw[3] | idxw[5] | idxw[7] | idxw[9] | idxw[11]) == 0);
        int b  = tid & 31;
        int ig = tid >> 5;
        float* Ks   = (float*)(smf + KS_OFF);
        float* sPhi = (float*)(smf + PHI_OFF);

        for (int tt = 0; tt < 2; tt++) {
            int t = id * 2 + tt;
            int e = is64 ? (idxw[2 * t] - idxw[0]) : (idxw[t] - idxw[0]);
            int lo = e & 15, hi = e >> 4;

            const float4* ps = (const float4*)(g_Phi + (size_t)hi * L * BZ);
#pragma unroll
            for (int i = tid; i < 1024; i += 256) ((float4*)sPhi)[i] = ps[i];

            float acc[16];
            if (lo != 0) {
                const float* Kp = (lo == 1) ? K1 : (g_Klo + (size_t)lo * L * L);
#pragma unroll
                for (int i = tid; i < 4096; i += 256) ((float4*)Ks)[i] = ((const float4*)Kp)[i];
                __syncthreads();
#pragma unroll
                for (int i = 0; i < 16; i++) acc[i] = 0.f;
                for (int k4 = 0; k4 < 32; k4++) {
                    float z0v = sPhi[(4 * k4 + 0) * 32 + b];
                    float z1v = sPhi[(4 * k4 + 1) * 32 + b];
                    float z2v = sPhi[(4 * k4 + 2) * 32 + b];
                    float z3v = sPhi[(4 * k4 + 3) * 32 + b];
#pragma unroll
                    for (int i = 0; i < 16; i++) {
                        float4 kr = ((const float4*)Ks)[(ig * 16 + i) * 32 + k4];
                        acc[i] += kr.x * z0v + kr.y * z1v + kr.z * z2v + kr.w * z3v;
                    }
                }
            } else {
                __syncthreads();
#pragma unroll
                for (int i = 0; i < 16; i++) acc[i] = sPhi[(ig * 16 + i) * 32 + b];
            }

            __half2 hh[8];
#pragma unroll
            for (int j = 0; j < 8; j++) hh[j] = __floats2half2_rn(acc[2 * j], acc[2 * j + 1]);
            uint4* dst = (uint4*)(smf + XA_OFF + (tt * 32 + b) * (SPE * 2) + ig * 32);
            dst[0] = ((uint4*)hh)[0];
            dst[1] = ((uint4*)hh)[1];
            __syncthreads();
        }
    }

    // ---------- phase A2: 3 hidden layers on fp16 tensor cores ----------
    {
        int rg = wid & 3;
        int cg = wid >> 2;
        uint32_t aoff = (uint32_t)((rg * 16 + (lane & 15)) * (SPE * 2)) + ((lane >> 4) << 4);
        uint32_t boff[4];
#pragma unroll
        for (int p = 0; p < 4; p++) {
            int row = cg * 64 + p * 16 + ((lane >> 4) << 3) + (lane & 7);
            boff[p] = (uint32_t)(row * (SPE * 2)) + (((lane >> 3) & 1) << 4);
        }
        int g  = lane >> 2;
        int cc = (lane & 3) * 2;
        const float* bl[3] = {b0, b1, b2};

        uint32_t inOff = XA_OFF, outOff = XB_OFF;
#pragma unroll
        for (int layer = 0; layer < 3; layer++) {
            const uint4* Wg = (const uint4*)(g_Whid + (size_t)layer * L * L);
#pragma unroll
            for (int i = tid; i < 2048; i += 256) {
                int r = i >> 4, q = i & 15;
                *(uint4*)(smf + WH_OFF + r * (SPE * 2) + q * 16) = Wg[r * 16 + q];
            }
            __syncthreads();

            float c[8][4];
#pragma unroll
            for (int p = 0; p < 8; p++)
#pragma unroll
                for (int j = 0; j < 4; j++) c[p][j] = 0.f;

#pragma unroll
            for (int k0 = 0; k0 < 8; k0++) {
                uint32_t koff = (uint32_t)(k0 * 32);
                uint32_t a[4];
                ldmx4(a, sbase + inOff + aoff + koff);
#pragma unroll
                for (int p = 0; p < 4; p++) {
                    uint32_t bf[4];
                    ldmx4(bf, sbase + WH_OFF + boff[p] + koff);
                    mma16816h(c[2 * p + 0], a, bf + 0);
                    mma16816h(c[2 * p + 1], a, bf + 2);
                }
            }

#pragma unroll
            for (int p = 0; p < 8; p++) {
                int col = cg * 64 + p * 8 + cc;
                float bx = bl[layer][col], by = bl[layer][col + 1];
                int row0 = rg * 16 + g;
                float v0x = fmaxf(c[p][0] + bx, 0.f), v0y = fmaxf(c[p][1] + by, 0.f);
                float v1x = fmaxf(c[p][2] + bx, 0.f), v1y = fmaxf(c[p][3] + by, 0.f);
                __half2 h0 = __floats2half2_rn(v0x, v0y);
                __half2 h1 = __floats2half2_rn(v1x, v1y);
                if (layer < 2) {
                    *(uint32_t*)(smf + outOff + row0 * (SPE * 2) + col * 2)       = *(uint32_t*)&h0;
                    *(uint32_t*)(smf + outOff + (row0 + 8) * (SPE * 2) + col * 2) = *(uint32_t*)&h1;
                } else {
                    *(uint32_t*)(g_Ah + (size_t)(bm0A + row0) * L + col)     = *(uint32_t*)&h0;
                    *(uint32_t*)(g_Ah + (size_t)(bm0A + row0 + 8) * L + col) = *(uint32_t*)&h1;
                }
            }
            __syncthreads();
            uint32_t tp = inOff; inOff = outOff; outOff = tp;
        }
    }

    gridbar(&g_bar[10], 256);

    // ---------- phase B: final fp16 tensor-core GEMM ----------
    int bn0 = blockIdx.x * 128;

    const uint4* GW = (const uint4*)g_Wh;
#pragma unroll
    for (int t = tid; t < 2048; t += 256) {
        int r = t >> 4, q = t & 15;
        cpasync16(sbase + OFF_B + (uint32_t)(r * (SPE * 2) + q * 16),
                  GW + (size_t)(bn0 + r) * 16 + q);
    }
    cp_commit();

    issue_A(sbase + OFF_A0, blockIdx.y * 128, tid);
    cp_commit();

    int wm = wid >> 2, wn = wid & 3;

    uint32_t a_off[4], b_off[4];
#pragma unroll
    for (int mi = 0; mi < 4; mi++) {
        int row = wm * 64 + mi * 16 + (lane & 15);
        a_off[mi] = (uint32_t)(row * SPE * 2) + ((lane >> 4) << 4);
    }
#pragma unroll
    for (int ni = 0; ni < 4; ni++) {
        int row = wn * 32 + ni * 8 + (lane & 7);
        b_off[ni] = (uint32_t)(row * SPE * 2) + (((lane >> 3) & 1) << 4);
    }
    uint32_t sB = sbase + OFF_B;

    int g  = lane >> 2;
    int cc = (lane & 3) * 2;
    float2 br[4];
#pragma unroll
    for (int ni = 0; ni < 4; ni++) {
        int col = bn0 + wn * 32 + ni * 8 + cc;
        br[ni] = make_float2(bias[col], bias[col + 1]);
    }

    const int NT = 16;
    for (int it = 0; it < NT; it++) {
        int bm0 = (blockIdx.y + 8 * it) * 128;
        if (it + 1 < NT) {
            issue_A(sbase + ((it + 1) & 1 ? OFF_A1 : OFF_A0),
                    (blockIdx.y + 8 * (it + 1)) * 128, tid);
            cp_commit();
            cp_wait1();
        } else {
            cp_wait0();
        }
        __syncthreads();

        uint32_t sA = sbase + ((it & 1) ? OFF_A1 : OFF_A0);
        float c[4][4][4];
#pragma unroll
        for (int mi = 0; mi < 4; mi++)
#pragma unroll
            for (int ni = 0; ni < 4; ni++)
#pragma unroll
                for (int j = 0; j < 4; j++) c[mi][ni][j] = 0.f;

#pragma unroll
        for (int k0 = 0; k0 < 8; k0++) {
            uint32_t koff = (uint32_t)(k0 * 32);
            uint32_t b[4][2];
#pragma unroll
            for (int ni = 0; ni < 4; ni++) ldmx2(b[ni], sB + b_off[ni] + koff);
#pragma unroll
            for (int mi = 0; mi < 4; mi++) {
                uint32_t a[4];
                ldmx4(a, sA + a_off[mi] + koff);
#pragma unroll
                for (int ni = 0; ni < 4; ni++)
                    mma16816h(c[mi][ni], a, b[ni]);
            }
        }

#pragma unroll
        for (int ni = 0; ni < 4; ni++) {
            int col = bn0 + wn * 32 + ni * 8 + cc;
#pragma unroll
            for (int mi = 0; mi < 4; mi++) {
                size_t row = (size_t)(bm0 + wm * 64 + mi * 16 + g);
                float2 v0 = make_float2(c[mi][ni][0] + br[ni].x, c[mi][ni][1] + br[ni].y);
                float2 v1 = make_float2(c[mi][ni][2] + br[ni].x, c[mi][ni][3] + br[ni].y);
                *(float2*)(out + row * DD + col)       = v0;
                *(float2*)(out + (row + 8) * DD + col) = v1;
            }
        }
        __syncthreads();
    }
}

// ---------------- launch ----------------
extern "C" void kernel_launch(void* const* d_in, const int* in_sizes, int n_in,
                              void* d_out, int out_size) {
    const float* x0  = (const float*)d_in[0];
    const int*   idx = (const int*)  d_in[1];
    const float* K   = (const float*)d_in[2];
    const float* We0 = (const float*)d_in[3];
    const float* be0 = (const float*)d_in[4];
    const float* We1 = (const float*)d_in[5];
    const float* be1 = (const float*)d_in[6];
    const float* We2 = (const float*)d_in[7];
    const float* be2 = (const float*)d_in[8];
    const float* We3 = (const float*)d_in[9];
    const float* be3 = (const float*)d_in[10];
    const float* Wd0 = (const float*)d_in[11];
    const float* bd0 = (const float*)d_in[12];
    const float* Wd1 = (const float*)d_in[13];
    const float* bd1 = (const float*)d_in[14];
    const float* Wd2 = (const float*)d_in[15];
    const float* bd2 = (const float*)d_in[16];
    const float* Wd3 = (const float*)d_in[17];
    const float* bd3 = (const float*)d_in[18];
    float* out = (float*)d_out;

    const int smem_ek   = 96 * 1024;                  // encKpow: A/W cache + act tiles
    const int smem_koop = (L * L + 2 * L * BZ) * 4;   // 96 KB
    const int smem_df   = FSM_BYTES;                  // ~102 KB
    cudaFuncSetAttribute(encKpow_kernel,    cudaFuncAttributeMaxDynamicSharedMemorySize, smem_ek);
    cudaFuncSetAttribute(kloPhiCvt_kernel,  cudaFuncAttributeMaxDynamicSharedMemorySize, smem_koop);
    cudaFuncSetAttribute(denseFinal_kernel, cudaFuncAttributeMaxDynamicSharedMemorySize, smem_df);

    // 1: encoder || kpow chain
    encKpow_kernel<<<384, 128, smem_ek>>>(x0, K, We0, be0, We1, be1, We2, be2, We3, be3);
    // 2: phi (b-split, 128 CTAs) || klo || weight converts
    kloPhiCvt_kernel<<<380, 256, smem_koop>>>(K, Wd3, Wd0, Wd1, Wd2);
    // 3: fused apply + fp16 hiddens + final tensor-core GEMM
    dim3 fgrid(DD / 128, 8);
    denseFinal_kernel<<<fgrid, 256, smem_df>>>(K, idx, bd0, bd1, bd2, bd3, out);
}

// round 11
// speedup vs baseline: 4.4404x; 1.1471x over previous
#include <cuda_runtime.h>
#include <cuda_fp16.h>
#include <stdint.h>

#define L   128
#define BZ  32
#define TT  512
#define DD  4096
#define MT  (TT*BZ)   // 16384 decoder rows

// ---------------- scratch (device globals; no allocation) ----------------
__device__ float g_h1p[8 * BZ * L];          // enc0 split-K partials
__device__ float g_z0[BZ * L];
__device__ float g_Kpow[9 * L * L];          // K^2 .. K^512
__device__ float g_Klo[16 * L * L];          // K^lo
__device__ float g_Phi[64 * L * BZ];         // (K^16)^hi @ z0^T, [hi][l][b]
__device__ __half g_Ah[MT * L];              // last hidden activations, fp16
__device__ __half g_Wh[DD * L];              // Wd3 transposed [n][k], fp16
__device__ __half g_Whid[3 * L * L];         // Wd0..2 transposed [n][k], fp16
__device__ int g_bar[16];                    // monotonic ticket barriers (never reset)

// ticket grid barrier: monotonic counter, safe across graph replays
__device__ __forceinline__ void gridbar(int* ctr, int n) {
    __threadfence();
    __syncthreads();
    if (threadIdx.x == 0) {
        int t = atomicAdd(ctr, 1);
        int target = (t / n + 1) * n;
        while (*(volatile int*)ctr < target) {}
        __threadfence();
    }
    __syncthreads();
}

// ================= launch 1: encoder (split-K + tail) PARALLEL WITH kpow chain =================
// dynamic smem 64KB -> 3 CTAs/SM -> all 384 CTAs resident in one wave (true overlap).
__global__ void encKpow_kernel(const float* __restrict__ x0, const float* __restrict__ K1,
                               const float* __restrict__ W0, const float* __restrict__ b0,
                               const float* __restrict__ W1, const float* __restrict__ b1,
                               const float* __restrict__ W2, const float* __restrict__ b2,
                               const float* __restrict__ W3, const float* __restrict__ b3) {
    extern __shared__ float sm1[];
    int n = threadIdx.x;   // 0..127

    if (blockIdx.x < 128) {
        // ---- kpow chain, A fully smem-resident each step (64 KB) ----
        float* As = sm1;
        float4* As4 = (float4*)As;
        int i = blockIdx.x;
        const float* A = K1;
        for (int p = 0; p < 9; p++) {
            float* C = g_Kpow + (size_t)p * L * L;
            const float4* A4 = (const float4*)A;
#pragma unroll
            for (int q = n; q < 4096; q += 128) As4[q] = A4[q];
            __syncthreads();
            const float* rowA = As + i * L;
            float a0 = 0.f, a1 = 0.f, a2 = 0.f, a3 = 0.f;
#pragma unroll 8
            for (int k = 0; k < L; k += 4) {
                a0 += rowA[k + 0] * As[(k + 0) * L + n];
                a1 += rowA[k + 1] * As[(k + 1) * L + n];
                a2 += rowA[k + 2] * As[(k + 2) * L + n];
                a3 += rowA[k + 3] * As[(k + 3) * L + n];
            }
            C[i * L + n] = (a0 + a1) + (a2 + a3);
            __syncthreads();
            gridbar(&g_bar[1 + p], 128);
            A = C;
        }
    } else {
        // ---- encoder split-K ----
        float* xs = sm1;   // 2 KB
        int cb  = blockIdx.x - 128;
        int row = cb >> 3, c = cb & 7;

        ((float4*)xs)[n] = ((const float4*)(x0 + (size_t)row * DD + c * 512))[n];
        __syncthreads();
        float a0 = 0.f, a1 = 0.f, a2 = 0.f, a3 = 0.f;
        const float* Wc = W0 + (size_t)(c * 512) * L;
#pragma unroll 8
        for (int k = 0; k < 512; k += 4) {
            a0 += xs[k + 0] * Wc[(size_t)(k + 0) * L + n];
            a1 += xs[k + 1] * Wc[(size_t)(k + 1) * L + n];
            a2 += xs[k + 2] * Wc[(size_t)(k + 2) * L + n];
            a3 += xs[k + 3] * Wc[(size_t)(k + 3) * L + n];
        }
        g_h1p[(c * BZ + row) * L + n] = (a0 + a1) + (a2 + a3);

        gridbar(&g_bar[0], 256);
        if (cb != 0) return;

        // ---- tail on one CTA: W staged in two 32KB halves; Xa/Xb 16KB each ----
        float* Ws = sm1;                 // 8192 floats = 32 KB (half of W)
        float* Xa = sm1 + 8192;          // 4096 floats
        float* Xb = sm1 + 12288;         // 4096 floats
        float4* Ws4 = (float4*)Ws;

#pragma unroll
        for (int r = 0; r < 32; r++) {
            float s = 0.f;
#pragma unroll
            for (int c2 = 0; c2 < 8; c2++) s += g_h1p[(c2 * BZ + r) * L + n];
            Xa[r * L + n] = fmaxf(s + b0[n], 0.f);
        }
        __syncthreads();

        const float* Wl[3] = {W1, W2, W3};
        const float* bl[3] = {b1, b2, b3};
        float* Xi = Xa; float* Xo = Xb;
#pragma unroll
        for (int layer = 0; layer < 3; layer++) {
            float acc[32];
#pragma unroll
            for (int r = 0; r < 32; r++) acc[r] = 0.f;
#pragma unroll
            for (int half = 0; half < 2; half++) {
                const float4* W4 = (const float4*)(Wl[layer] + half * 64 * L);
#pragma unroll
                for (int q = n; q < 2048; q += 128) Ws4[q] = W4[q];
                __syncthreads();
#pragma unroll 4
                for (int k = 0; k < 64; k++) {
                    float w = Ws[k * L + n];
#pragma unroll
                    for (int r = 0; r < 32; r++) acc[r] += Xi[r * L + half * 64 + k] * w;
                }
                __syncthreads();     // Ws reads done before next half overwrite
            }
            float bn = bl[layer][n];
            if (layer < 2) {
#pragma unroll
                for (int r = 0; r < 32; r++) Xo[r * L + n] = fmaxf(acc[r] + bn, 0.f);
                __syncthreads();
                float* tp = Xi; Xi = Xo; Xo = tp;
            } else {
#pragma unroll
                for (int r = 0; r < 32; r++) g_z0[r * L + n] = acc[r] + bn;
            }
        }
        __threadfence();
    }
}

// ================= launch 2: phi(0..127, b-split) || klo(128..239) || cvt(240..379) =================
// dynamic smem 48KB -> 4 CTAs/SM -> all 380 CTAs in one wave.
__global__ __launch_bounds__(256)
void kloPhiCvt_kernel(const float* __restrict__ K1, const float* __restrict__ Wd3,
                      const float* __restrict__ Wd0, const float* __restrict__ Wd1,
                      const float* __restrict__ Wd2) {
    extern __shared__ float sm[];
    int tid = threadIdx.x;

    if (blockIdx.x < 128) {
        // ---- phi: Phi[hi] columns [half16*16, +16), K staged in 32KB k-halves ----
        int hi   = blockIdx.x & 63;
        int bhalf = blockIdx.x >> 6;
        float* Ksh = sm;                 // 8192 floats = 32 KB (k-half of K)
        float* Z0  = sm + 8192;          // 2048 floats
        float* Z1  = Z0 + 2048;          // 2048 floats
        float4* Ksh4 = (float4*)Ksh;

        for (int i = tid; i < 2048; i += 256) {
            int l = i >> 4, bb = i & 15;
            Z0[i] = g_z0[(bhalf * 16 + bb) * L + l];
        }
        __syncthreads();

        float* Zin = Z0; float* Zout = Z1;
        int bb = tid & 15;
        int ig = tid >> 4;               // 0..15, rows ig*8..ig*8+7

        for (int j = 0; j < 6; j++) {
            if ((hi >> j) & 1) {
                const float4* Kp4 = (const float4*)(g_Kpow + (size_t)(3 + j) * L * L);
                float acc[8];
#pragma unroll
                for (int i = 0; i < 8; i++) acc[i] = 0.f;
#pragma unroll
                for (int kh = 0; kh < 2; kh++) {
                    // rows 0..127, local k4 0..15 -> global f4 idx row*32 + kh*16 + q
#pragma unroll
                    for (int i = tid; i < 2048; i += 256) {
                        int row = i >> 4, q = i & 15;
                        Ksh4[i] = Kp4[row * 32 + kh * 16 + q];
                    }
                    __syncthreads();
                    for (int k4 = 0; k4 < 16; k4++) {
                        float z0v = Zin[(kh * 64 + 4 * k4 + 0) * 16 + bb];
                        float z1v = Zin[(kh * 64 + 4 * k4 + 1) * 16 + bb];
                        float z2v = Zin[(kh * 64 + 4 * k4 + 2) * 16 + bb];
                        float z3v = Zin[(kh * 64 + 4 * k4 + 3) * 16 + bb];
#pragma unroll
                        for (int i = 0; i < 8; i++) {
                            float4 kr = Ksh4[(ig * 8 + i) * 16 + k4];
                            acc[i] += kr.x * z0v + kr.y * z1v + kr.z * z2v + kr.w * z3v;
                        }
                    }
                    __syncthreads();
                }
#pragma unroll
                for (int i = 0; i < 8; i++)
                    Zout[(ig * 8 + i) * 16 + bb] = acc[i];
                __syncthreads();
                float* tp = Zin; Zin = Zout; Zout = tp;
            }
        }
        for (int i = tid; i < 2048; i += 256) {
            int l = i >> 4, b2 = i & 15;
            g_Phi[(size_t)hi * L * BZ + l * 32 + bhalf * 16 + b2] = Zin[i];
        }
    } else if (blockIdx.x < 240) {
        // ---- klo: factor staged in contiguous 32KB k-halves ----
        float* Fsh = sm;                 // 8192 floats
        float* S   = sm + 8192;          // 2048 floats (16 rows x 128)
        float* T   = S + 2048;
        float4* Fsh4 = (float4*)Fsh;
        int u    = blockIdx.x - 128;
        int l    = (u >> 3) + 2;
        int band = u & 7;

        const float* fac[4]; int nf = 0;
        if (l & 1) fac[nf++] = K1;
        if (l & 2) fac[nf++] = g_Kpow + 0 * L * L;
        if (l & 4) fac[nf++] = g_Kpow + 1 * L * L;
        if (l & 8) fac[nf++] = g_Kpow + 2 * L * L;

        const float4* f0 = (const float4*)(fac[0] + (size_t)band * 16 * L);
#pragma unroll
        for (int i = tid; i < 512; i += 256) ((float4*)S)[i] = f0[i];
        __syncthreads();

        float* in = S; float* out = T;
        for (int f = 1; f < nf; f++) {
            int n  = tid & 127;
            int r0 = (tid >> 7) * 8;
            float acc[8];
#pragma unroll
            for (int i = 0; i < 8; i++) acc[i] = 0.f;
#pragma unroll
            for (int kh = 0; kh < 2; kh++) {
                const float4* F4 = (const float4*)(fac[f] + kh * 64 * L);
#pragma unroll
                for (int i = tid; i < 2048; i += 256) Fsh4[i] = F4[i];
                __syncthreads();
#pragma unroll 4
                for (int k = 0; k < 64; k++) {
                    float w = Fsh[k * L + n];
#pragma unroll
                    for (int i = 0; i < 8; i++) acc[i] += in[(r0 + i) * L + kh * 64 + k] * w;
                }
                __syncthreads();
            }
#pragma unroll
            for (int i = 0; i < 8; i++) out[(r0 + i) * L + n] = acc[i];
            __syncthreads();
            float* tp = in; in = out; out = tp;
        }
        float* dst = g_Klo + (size_t)l * L * L + (size_t)band * 16 * L;
#pragma unroll
        for (int i = tid; i < 512; i += 256) ((float4*)dst)[i] = ((float4*)in)[i];
    } else {
        // ---- weight transpose + fp16 convert (17KB smem) ----
        float (*tile)[33] = (float(*)[33])sm;
        const float* src;
        __half* dstg;
        int n0, stride;
        int u2 = blockIdx.x - 240;
        if (u2 < 128) {
            n0 = u2 * 32; src = Wd3; stride = DD; dstg = g_Wh;
        } else {
            int u3 = u2 - 128;                 // 0..11
            int layer = u3 >> 2;
            n0 = (u3 & 3) * 32;
            src = (layer == 0) ? Wd0 : (layer == 1) ? Wd1 : Wd2;
            stride = L;
            dstg = g_Whid + (size_t)layer * L * L;
        }
        int tx = tid & 31, ty = tid >> 5;
        for (int k = ty; k < 128; k += 8)
            tile[k][tx] = src[(size_t)k * stride + n0 + tx];
        __syncthreads();
        int nn = n0 + (tid >> 3);
        int k0 = (tid & 7) * 16;
        int c  = nn - n0;
        __half2 h[8];
#pragma unroll
        for (int j = 0; j < 8; j++)
            h[j] = __floats2half2_rn(tile[k0 + 2 * j][c], tile[k0 + 2 * j + 1][c]);
        uint4* dh = (uint4*)(dstg + (size_t)nn * L + k0);
        dh[0] = ((uint4*)h)[0];
        dh[1] = ((uint4*)h)[1];
    }
}

// ================= launch 3: apply + fp16 hiddens + final fp16 GEMM (persistent) =================
#define SPE 136
#define TILE_BYTES (128 * SPE * 2)      // 34816
#define OFF_B   0
#define OFF_A0  TILE_BYTES
#define OFF_A1  (2 * TILE_BYTES)
#define FSM_BYTES (3 * TILE_BYTES)      // 104448

#define KS_OFF   0                       // 64 KB fp32 K^lo
#define PHI_OFF  65536                   // 16 KB fp32 Phi
#define XA_OFF   81920                   // 64x136 fp16 act tile A
#define WH_OFF   0                       // 128x136 fp16 weight tile
#define XB_OFF   40960                   // 64x136 fp16 act tile B

__device__ __forceinline__ uint32_t smem_u32(const void* p) {
    uint32_t a;
    asm("{ .reg .u64 t; cvta.to.shared.u64 t, %1; cvt.u32.u64 %0, t; }" : "=r"(a) : "l"(p));
    return a;
}
__device__ __forceinline__ void cpasync16(uint32_t dst, const void* src) {
    asm volatile("cp.async.cg.shared.global [%0], [%1], 16;" :: "r"(dst), "l"(src));
}
__device__ __forceinline__ void cp_commit() {
    asm volatile("cp.async.commit_group;" ::: "memory");
}
__device__ __forceinline__ void cp_wait1() {
    asm volatile("cp.async.wait_group 1;" ::: "memory");
}
__device__ __forceinline__ void cp_wait0() {
    asm volatile("cp.async.wait_group 0;" ::: "memory");
}
__device__ __forceinline__ void ldmx4(uint32_t* r, uint32_t addr) {
    asm volatile("ldmatrix.sync.aligned.m8n8.x4.shared.b16 {%0,%1,%2,%3}, [%4];"
                 : "=r"(r[0]), "=r"(r[1]), "=r"(r[2]), "=r"(r[3]) : "r"(addr));
}
__device__ __forceinline__ void ldmx2(uint32_t* r, uint32_t addr) {
    asm volatile("ldmatrix.sync.aligned.m8n8.x2.shared.b16 {%0,%1}, [%2];"
                 : "=r"(r[0]), "=r"(r[1]) : "r"(addr));
}
__device__ __forceinline__ void mma16816h(float* c, const uint32_t* a, const uint32_t* b) {
    asm volatile(
        "mma.sync.aligned.m16n8k16.row.col.f32.f16.f16.f32 "
        "{%0,%1,%2,%3}, {%4,%5,%6,%7}, {%8,%9}, {%0,%1,%2,%3};"
        : "+f"(c[0]), "+f"(c[1]), "+f"(c[2]), "+f"(c[3])
        : "r"(a[0]), "r"(a[1]), "r"(a[2]), "r"(a[3]), "r"(b[0]), "r"(b[1]));
}

__device__ __forceinline__ void issue_A(uint32_t sbase, int bm0, int tid) {
    const uint4* GA = (const uint4*)g_Ah;
#pragma unroll
    for (int t = tid; t < 2048; t += 256) {
        int r = t >> 4, q = t & 15;
        cpasync16(sbase + (uint32_t)(r * (SPE * 2) + q * 16),
                  GA + (size_t)(bm0 + r) * 16 + q);
    }
}

__global__ __launch_bounds__(256, 2)
void denseFinal_kernel(const float* __restrict__ K1, const int* __restrict__ idxw,
                       const float* __restrict__ b0, const float* __restrict__ b1,
                       const float* __restrict__ b2,
                       const float* __restrict__ bias, float* __restrict__ out) {
    extern __shared__ __align__(16) char smf[];
    uint32_t sbase = smem_u32(smf);
    int tid  = threadIdx.x;
    int wid  = tid >> 5, lane = tid & 31;
    int id   = blockIdx.y * 32 + blockIdx.x;
    int bm0A = id * 64;

    // ---------- phase A1: fused apply (fp32): Z rows -> fp16 tile at XA_OFF ----------
    {
        bool is64 = ((idxw[1] | idxw[3] | idxw[5] | idxw[7] | idxw[9] | idxw[11]) == 0);
        int b  = tid & 31;
        int ig = tid >> 5;
        float* Ks   = (float*)(smf + KS_OFF);
        float* sPhi = (float*)(smf + PHI_OFF);

        for (int tt = 0; tt < 2; tt++) {
            int t = id * 2 + tt;
            int e = is64 ? (idxw[2 * t] - idxw[0]) : (idxw[t] - idxw[0]);
            int lo = e & 15, hi = e >> 4;

            const float4* ps = (const float4*)(g_Phi + (size_t)hi * L * BZ);
#pragma unroll
            for (int i = tid; i < 1024; i += 256) ((float4*)sPhi)[i] = ps[i];

            float acc[16];
            if (lo != 0) {
                const float* Kp = (lo == 1) ? K1 : (g_Klo + (size_t)lo * L * L);
#pragma unroll
                for (int i = tid; i < 4096; i += 256) ((float4*)Ks)[i] = ((const float4*)Kp)[i];
                __syncthreads();
#pragma unroll
                for (int i = 0; i < 16; i++) acc[i] = 0.f;
                for (int k4 = 0; k4 < 32; k4++) {
                    float z0v = sPhi[(4 * k4 + 0) * 32 + b];
                    float z1v = sPhi[(4 * k4 + 1) * 32 + b];
                    float z2v = sPhi[(4 * k4 + 2) * 32 + b];
                    float z3v = sPhi[(4 * k4 + 3) * 32 + b];
#pragma unroll
                    for (int i = 0; i < 16; i++) {
                        float4 kr = ((const float4*)Ks)[(ig * 16 + i) * 32 + k4];
                        acc[i] += kr.x * z0v + kr.y * z1v + kr.z * z2v + kr.w * z3v;
                    }
                }
            } else {
                __syncthreads();
#pragma unroll
                for (int i = 0; i < 16; i++) acc[i] = sPhi[(ig * 16 + i) * 32 + b];
            }

            __half2 hh[8];
#pragma unroll
            for (int j = 0; j < 8; j++) hh[j] = __floats2half2_rn(acc[2 * j], acc[2 * j + 1]);
            uint4* dst = (uint4*)(smf + XA_OFF + (tt * 32 + b) * (SPE * 2) + ig * 32);
            dst[0] = ((uint4*)hh)[0];
            dst[1] = ((uint4*)hh)[1];
            __syncthreads();
        }
    }

    // ---------- phase A2: 3 hidden layers on fp16 tensor cores ----------
    {
        int rg = wid & 3;
        int cg = wid >> 2;
        uint32_t aoff = (uint32_t)((rg * 16 + (lane & 15)) * (SPE * 2)) + ((lane >> 4) << 4);
        uint32_t boff[4];
#pragma unroll
        for (int p = 0; p < 4; p++) {
            int row = cg * 64 + p * 16 + ((lane >> 4) << 3) + (lane & 7);
            boff[p] = (uint32_t)(row * (SPE * 2)) + (((lane >> 3) & 1) << 4);
        }
        int g  = lane >> 2;
        int cc = (lane & 3) * 2;
        const float* bl[3] = {b0, b1, b2};

        uint32_t inOff = XA_OFF, outOff = XB_OFF;
#pragma unroll
        for (int layer = 0; layer < 3; layer++) {
            const uint4* Wg = (const uint4*)(g_Whid + (size_t)layer * L * L);
#pragma unroll
            for (int i = tid; i < 2048; i += 256) {
                int r = i >> 4, q = i & 15;
                *(uint4*)(smf + WH_OFF + r * (SPE * 2) + q * 16) = Wg[r * 16 + q];
            }
            __syncthreads();

            float c[8][4];
#pragma unroll
            for (int p = 0; p < 8; p++)
#pragma unroll
                for (int j = 0; j < 4; j++) c[p][j] = 0.f;

#pragma unroll
            for (int k0 = 0; k0 < 8; k0++) {
                uint32_t koff = (uint32_t)(k0 * 32);
                uint32_t a[4];
                ldmx4(a, sbase + inOff + aoff + koff);
#pragma unroll
                for (int p = 0; p < 4; p++) {
                    uint32_t bf[4];
                    ldmx4(bf, sbase + WH_OFF + boff[p] + koff);
                    mma16816h(c[2 * p + 0], a, bf + 0);
                    mma16816h(c[2 * p + 1], a, bf + 2);
                }
            }

#pragma unroll
            for (int p = 0; p < 8; p++) {
                int col = cg * 64 + p * 8 + cc;
                float bx = bl[layer][col], by = bl[layer][col + 1];
                int row0 = rg * 16 + g;
                float v0x = fmaxf(c[p][0] + bx, 0.f), v0y = fmaxf(c[p][1] + by, 0.f);
                float v1x = fmaxf(c[p][2] + bx, 0.f), v1y = fmaxf(c[p][3] + by, 0.f);
                __half2 h0 = __floats2half2_rn(v0x, v0y);
                __half2 h1 = __floats2half2_rn(v1x, v1y);
                if (layer < 2) {
                    *(uint32_t*)(smf + outOff + row0 * (SPE * 2) + col * 2)       = *(uint32_t*)&h0;
                    *(uint32_t*)(smf + outOff + (row0 + 8) * (SPE * 2) + col * 2) = *(uint32_t*)&h1;
                } else {
                    *(uint32_t*)(g_Ah + (size_t)(bm0A + row0) * L + col)     = *(uint32_t*)&h0;
                    *(uint32_t*)(g_Ah + (size_t)(bm0A + row0 + 8) * L + col) = *(uint32_t*)&h1;
                }
            }
            __syncthreads();
            uint32_t tp = inOff; inOff = outOff; outOff = tp;
        }
    }

    gridbar(&g_bar[10], 256);

    // ---------- phase B: final fp16 tensor-core GEMM ----------
    int bn0 = blockIdx.x * 128;

    const uint4* GW = (const uint4*)g_Wh;
#pragma unroll
    for (int t = tid; t < 2048; t += 256) {
        int r = t >> 4, q = t & 15;
        cpasync16(sbase + OFF_B + (uint32_t)(r * (SPE * 2) + q * 16),
                  GW + (size_t)(bn0 + r) * 16 + q);
    }
    cp_commit();

    issue_A(sbase + OFF_A0, blockIdx.y * 128, tid);
    cp_commit();

    int wm = wid >> 2, wn = wid & 3;

    uint32_t a_off[4], b_off[4];
#pragma unroll
    for (int mi = 0; mi < 4; mi++) {
        int row = wm * 64 + mi * 16 + (lane & 15);
        a_off[mi] = (uint32_t)(row * SPE * 2) + ((lane >> 4) << 4);
    }
#pragma unroll
    for (int ni = 0; ni < 4; ni++) {
        int row = wn * 32 + ni * 8 + (lane & 7);
        b_off[ni] = (uint32_t)(row * SPE * 2) + (((lane >> 3) & 1) << 4);
    }
    uint32_t sB = sbase + OFF_B;

    int g  = lane >> 2;
    int cc = (lane & 3) * 2;
    float2 br[4];
#pragma unroll
    for (int ni = 0; ni < 4; ni++) {
        int col = bn0 + wn * 32 + ni * 8 + cc;
        br[ni] = make_float2(bias[col], bias[col + 1]);
    }

    const int NT = 16;
    for (int it = 0; it < NT; it++) {
        int bm0 = (blockIdx.y + 8 * it) * 128;
        if (it + 1 < NT) {
            issue_A(sbase + ((it + 1) & 1 ? OFF_A1 : OFF_A0),
                    (blockIdx.y + 8 * (it + 1)) * 128, tid);
            cp_commit();
            cp_wait1();
        } else {
            cp_wait0();
        }
        __syncthreads();

        uint32_t sA = sbase + ((it & 1) ? OFF_A1 : OFF_A0);
        float c[4][4][4];
#pragma unroll
        for (int mi = 0; mi < 4; mi++)
#pragma unroll
            for (int ni = 0; ni < 4; ni++)
#pragma unroll
                for (int j = 0; j < 4; j++) c[mi][ni][j] = 0.f;

#pragma unroll
        for (int k0 = 0; k0 < 8; k0++) {
            uint32_t koff = (uint32_t)(k0 * 32);
            uint32_t b[4][2];
#pragma unroll
            for (int ni = 0; ni < 4; ni++) ldmx2(b[ni], sB + b_off[ni] + koff);
#pragma unroll
            for (int mi = 0; mi < 4; mi++) {
                uint32_t a[4];
                ldmx4(a, sA + a_off[mi] + koff);
#pragma unroll
                for (int ni = 0; ni < 4; ni++)
                    mma16816h(c[mi][ni], a, b[ni]);
            }
        }

#pragma unroll
        for (int ni = 0; ni < 4; ni++) {
            int col = bn0 + wn * 32 + ni * 8 + cc;
#pragma unroll
            for (int mi = 0; mi < 4; mi++) {
                size_t row = (size_t)(bm0 + wm * 64 + mi * 16 + g);
                float2 v0 = make_float2(c[mi][ni][0] + br[ni].x, c[mi][ni][1] + br[ni].y);
                float2 v1 = make_float2(c[mi][ni][2] + br[ni].x, c[mi][ni][3] + br[ni].y);
                *(float2*)(out + row * DD + col)       = v0;
                *(float2*)(out + (row + 8) * DD + col) = v1;
            }
        }
        __syncthreads();
    }
}

// ---------------- launch ----------------
extern "C" void kernel_launch(void* const* d_in, const int* in_sizes, int n_in,
                              void* d_out, int out_size) {
    const float* x0  = (const float*)d_in[0];
    const int*   idx = (const int*)  d_in[1];
    const float* K   = (const float*)d_in[2];
    const float* We0 = (const float*)d_in[3];
    const float* be0 = (const float*)d_in[4];
    const float* We1 = (const float*)d_in[5];
    const float* be1 = (const float*)d_in[6];
    const float* We2 = (const float*)d_in[7];
    const float* be2 = (const float*)d_in[8];
    const float* We3 = (const float*)d_in[9];
    const float* be3 = (const float*)d_in[10];
    const float* Wd0 = (const float*)d_in[11];
    const float* bd0 = (const float*)d_in[12];
    const float* Wd1 = (const float*)d_in[13];
    const float* bd1 = (const float*)d_in[14];
    const float* Wd2 = (const float*)d_in[15];
    const float* bd2 = (const float*)d_in[16];
    const float* Wd3 = (const float*)d_in[17];
    const float* bd3 = (const float*)d_in[18];
    float* out = (float*)d_out;

    const int smem_ek   = 64 * 1024;   // 3 CTAs/SM -> 384 CTAs single wave
    const int smem_koop = 48 * 1024;   // 4 CTAs/SM -> 380 CTAs single wave
    const int smem_df   = FSM_BYTES;   // ~102 KB, 2 CTAs/SM -> 256 CTAs single wave
    cudaFuncSetAttribute(encKpow_kernel,    cudaFuncAttributeMaxDynamicSharedMemorySize, smem_ek);
    cudaFuncSetAttribute(kloPhiCvt_kernel,  cudaFuncAttributeMaxDynamicSharedMemorySize, smem_koop);
    cudaFuncSetAttribute(denseFinal_kernel, cudaFuncAttributeMaxDynamicSharedMemorySize, smem_df);

    // 1: encoder || kpow chain (all CTAs resident -> true overlap)
    encKpow_kernel<<<384, 128, smem_ek>>>(x0, K, We0, be0, We1, be1, We2, be2, We3, be3);
    // 2: phi (b-split) || klo || weight converts
    kloPhiCvt_kernel<<<380, 256, smem_koop>>>(K, Wd3, Wd0, Wd1, Wd2);
    // 3: fused apply + fp16 hiddens + final tensor-core GEMM
    dim3 fgrid(DD / 128, 8);
    denseFinal_kernel<<<fgrid, 256, smem_df>>>(K, idx, bd0, bd1, bd2, bd3, out);
}